// round 10
// baseline (speedup 1.0000x reference)
#include <cuda_runtime.h>
#include <cuda_bf16.h>
#include <math.h>

// Problem constants (fixed by setup_inputs)
#define NN      65536
#define BB      512
#define NPG     128
#define EE      262144
#define EPG     512
#define HH      256
#define FIN     128
#define BN_EPS  1e-5f

// ---------------- scratch (device globals; no cudaMalloc allowed) ----------
__device__ float d_z[NN * HH];
__device__ float d_t[NN * HH];
__device__ float d_a[NN * 2];
__device__ float d_stats[3 * 2 * HH];
__device__ float d_bnsb[3 * 2 * HH];
__device__ float d_pen[BB];
__device__ int   d_csr[EE];
__device__ int   d_rowstart[NN];
__device__ int   d_deg[NN];
// activation planes (bf16 hi/lo)
__device__ __nv_bfloat16 d_ah[NN * HH];
__device__ __nv_bfloat16 d_al[NN * HH];
__device__ __nv_bfloat16 d_th[NN * HH];
__device__ __nv_bfloat16 d_tl[NN * HH];
// weight planes
#define WSPLIT_TOTAL (256 * (128 + 6 * 256))
__device__ __nv_bfloat16 d_wth[WSPLIT_TOTAL];
__device__ __nv_bfloat16 d_wtl[WSPLIT_TOTAL];

// ---------------- helpers ----------------------------------------------------
__device__ __forceinline__ unsigned smem_u32(const void* p) {
    return (unsigned)__cvta_generic_to_shared(p);
}
__device__ __forceinline__ void ldsm_x4(unsigned addr, unsigned& r0, unsigned& r1,
                                        unsigned& r2, unsigned& r3) {
    asm volatile("ldmatrix.sync.aligned.m8n8.x4.shared.b16 {%0,%1,%2,%3}, [%4];"
                 : "=r"(r0), "=r"(r1), "=r"(r2), "=r"(r3) : "r"(addr));
}
__device__ __forceinline__ void ldsm_x4t(unsigned addr, unsigned& r0, unsigned& r1,
                                         unsigned& r2, unsigned& r3) {
    asm volatile("ldmatrix.sync.aligned.m8n8.x4.trans.shared.b16 {%0,%1,%2,%3}, [%4];"
                 : "=r"(r0), "=r"(r1), "=r"(r2), "=r"(r3) : "r"(addr));
}
__device__ __forceinline__ void mma_bf16(float* d, const unsigned* a,
                                         unsigned b0, unsigned b1) {
    asm volatile("mma.sync.aligned.m16n8k16.row.col.f32.bf16.bf16.f32 "
                 "{%0,%1,%2,%3}, {%4,%5,%6,%7}, {%8,%9}, {%0,%1,%2,%3};"
                 : "+f"(d[0]), "+f"(d[1]), "+f"(d[2]), "+f"(d[3])
                 : "r"(a[0]), "r"(a[1]), "r"(a[2]), "r"(a[3]), "r"(b0), "r"(b1));
}
__device__ __forceinline__ void split_bf16(float v, __nv_bfloat16& h, __nv_bfloat16& l) {
    h = __float2bfloat16(v);
    l = __float2bfloat16(v - __bfloat162float(h));
}
__device__ __forceinline__ unsigned pack2h(float a, float b) {
    __nv_bfloat16 ha, hb;
    ha = __float2bfloat16(a); hb = __float2bfloat16(b);
    return ((unsigned)*(unsigned short*)&hb << 16) | *(unsigned short*)&ha;
}
#define CP_ASYNC16(dst, src) \
    asm volatile("cp.async.cg.shared.global [%0], [%1], 16;" \
                 :: "r"(dst), "l"(src))
#define CP_COMMIT() asm volatile("cp.async.commit_group;")
#define CP_WAIT1()  asm volatile("cp.async.wait_group 1;")
#define CP_WAIT0()  asm volatile("cp.async.wait_group 0;")

// ---------------- BN stats zero ----------------------------------------------
__global__ void bn_zero_all_kernel() {
    int i = blockIdx.x * 512 + threadIdx.x;
    if (i < 3 * 2 * HH) d_stats[i] = 0.f;
}

// ---------------- BN finalize: stats -> (s, b) --------------------------------
__global__ void bn_finalize_kernel(const float* __restrict__ gamma,
                                   const float* __restrict__ beta, int layer) {
    const int f = threadIdx.x;
    const float* st = d_stats + layer * 2 * HH;
    const float mu  = st[f] * (1.f / NN);
    const float var = st[HH + f] * (1.f / NN) - mu * mu;
    const float s = rsqrtf(var + BN_EPS) * gamma[f];
    d_bnsb[layer * 2 * HH + f] = s;
    d_bnsb[layer * 2 * HH + HH + f] = beta[f] - mu * s;
}

// ---------------- weight prep ----------------------------------------------
__global__ void wsplit_all_kernel(const float* __restrict__ w01,
                                  const float* __restrict__ w02,
                                  const float* __restrict__ wl1,
                                  const float* __restrict__ wl2,
                                  const float* __restrict__ c1w,
                                  __nv_bfloat16* __restrict__ oh,
                                  __nv_bfloat16* __restrict__ ol) {
    int id = blockIdx.x * 256 + threadIdx.x;
    if (id >= WSPLIT_TOTAL) return;
    const float* src;
    if (id < 32768) {
        src = w01 + id;
    } else {
        int r = id - 32768;
        int m = r >> 16, off = r & 65535;
        const float* bases[6] = {w02, wl1, wl2, wl1 + 65536, wl2 + 65536, c1w};
        src = bases[m] + off;
    }
    __nv_bfloat16 h, l;
    split_bf16(*src, h, l);
    oh[id] = h; ol[id] = l;
}

// ---------------- CSR build --------------------------------------------------
__global__ void csr_kernel(const int* __restrict__ src,
                           const int* __restrict__ dst) {
    __shared__ int   ssrc[EPG];
    __shared__ short sdst[EPG];
    __shared__ int   sscan[NPG];
    const int g = blockIdx.x, t = threadIdx.x;
    const int ebase = g * EPG;
    for (int i = t; i < EPG; i += NPG) {
        ssrc[i] = src[ebase + i];
        sdst[i] = (short)(dst[ebase + i] - g * NPG);
    }
    __syncthreads();
    int cnt = 0;
    #pragma unroll 8
    for (int e = 0; e < EPG; ++e) cnt += (sdst[e] == t);
    sscan[t] = cnt;
    __syncthreads();
    for (int off = 1; off < NPG; off <<= 1) {
        int v = (t >= off) ? sscan[t - off] : 0;
        __syncthreads();
        sscan[t] += v;
        __syncthreads();
    }
    int o = ebase + sscan[t] - cnt;
    d_rowstart[g * NPG + t] = o;
    d_deg[g * NPG + t] = cnt;
    for (int e = 0; e < EPG; ++e)
        if (sdst[e] == t) d_csr[o++] = ssrc[e];
}

// ------ gather aggregation -> pre-split bf16 hi/lo planes (BN optional) ----
template <int F, bool BN>
__global__ void agg_gather_bf(const float* __restrict__ h,
                              __nv_bfloat16* __restrict__ zh,
                              __nv_bfloat16* __restrict__ zl, int layer) {
    const int node = blockIdx.x * 8 + (threadIdx.x >> 5);
    const int lane = threadIdx.x & 31;
    const int s = d_rowstart[node];
    const int dg = d_deg[node];
    const int c0 = lane * 4;
    const size_t rb = (size_t)node * F;
    float4 a0 = *reinterpret_cast<const float4*>(&h[rb + c0]);
    float4 a1;
    if (F == 256) a1 = *reinterpret_cast<const float4*>(&h[rb + c0 + 128]);
    for (int e = 0; e < dg; ++e) {
        const size_t sb = (size_t)__ldg(&d_csr[s + e]) * F;
        float4 b0 = *reinterpret_cast<const float4*>(&h[sb + c0]);
        a0.x += b0.x; a0.y += b0.y; a0.z += b0.z; a0.w += b0.w;
        if (F == 256) {
            float4 b1 = *reinterpret_cast<const float4*>(&h[sb + c0 + 128]);
            a1.x += b1.x; a1.y += b1.y; a1.z += b1.z; a1.w += b1.w;
        }
    }
    if (BN) {
        const float* sb = d_bnsb + layer * 2 * HH;
        const float dp1 = (float)(dg + 1);
        float4 sv = *reinterpret_cast<const float4*>(&sb[c0]);
        float4 bv = *reinterpret_cast<const float4*>(&sb[HH + c0]);
        a0.x = sv.x * a0.x + dp1 * bv.x;
        a0.y = sv.y * a0.y + dp1 * bv.y;
        a0.z = sv.z * a0.z + dp1 * bv.z;
        a0.w = sv.w * a0.w + dp1 * bv.w;
        if (F == 256) {
            float4 sv1 = *reinterpret_cast<const float4*>(&sb[c0 + 128]);
            float4 bv1 = *reinterpret_cast<const float4*>(&sb[HH + c0 + 128]);
            a1.x = sv1.x * a1.x + dp1 * bv1.x;
            a1.y = sv1.y * a1.y + dp1 * bv1.y;
            a1.z = sv1.z * a1.z + dp1 * bv1.z;
            a1.w = sv1.w * a1.w + dp1 * bv1.w;
        }
    }
    // split + store planes
    {
        float vv[4] = {a0.x, a0.y, a0.z, a0.w};
        unsigned hp[2], lp[2];
        #pragma unroll
        for (int q = 0; q < 2; ++q) {
            __nv_bfloat16 h0, l0, h1, l1;
            split_bf16(vv[2 * q], h0, l0);
            split_bf16(vv[2 * q + 1], h1, l1);
            hp[q] = ((unsigned)*(unsigned short*)&h1 << 16) | *(unsigned short*)&h0;
            lp[q] = ((unsigned)*(unsigned short*)&l1 << 16) | *(unsigned short*)&l0;
        }
        *reinterpret_cast<uint2*>(&zh[rb + c0]) = make_uint2(hp[0], hp[1]);
        *reinterpret_cast<uint2*>(&zl[rb + c0]) = make_uint2(lp[0], lp[1]);
    }
    if (F == 256) {
        float vv[4] = {a1.x, a1.y, a1.z, a1.w};
        unsigned hp[2], lp[2];
        #pragma unroll
        for (int q = 0; q < 2; ++q) {
            __nv_bfloat16 h0, l0, h1, l1;
            split_bf16(vv[2 * q], h0, l0);
            split_bf16(vv[2 * q + 1], h1, l1);
            hp[q] = ((unsigned)*(unsigned short*)&h1 << 16) | *(unsigned short*)&h0;
            lp[q] = ((unsigned)*(unsigned short*)&l1 << 16) | *(unsigned short*)&l0;
        }
        *reinterpret_cast<uint2*>(&zh[rb + c0 + 128]) = make_uint2(hp[0], hp[1]);
        *reinterpret_cast<uint2*>(&zl[rb + c0 + 128]) = make_uint2(lp[0], lp[1]);
    }
}

// -------- bf16x3 HMMA GEMM: pre-split bf16 planes in, ReLU ------------------
// STATS=false: output bf16 hi/lo planes.  STATS=true: output fp32 + BN stats.
// All tiles via cp.async, depth-2 prefetch. 128x128 tile, BK=32, 8 warps 4x2.
#define LDA 40
#define LDW 136
#define SM_AH  0
#define SM_AL  10240
#define SM_WH  20480
#define SM_WL  29184
#define GEMM_SMEM_BYTES (37888 * 2)

template <bool STATS>
__global__ void __launch_bounds__(256)
gemm_bb(const __nv_bfloat16* __restrict__ Ah_g,
        const __nv_bfloat16* __restrict__ Al_g,
        const __nv_bfloat16* __restrict__ Wh_g,
        const __nv_bfloat16* __restrict__ Wl_g,
        const float* __restrict__ bias,
        float* __restrict__ Cf,
        __nv_bfloat16* __restrict__ Ch, __nv_bfloat16* __restrict__ Cl,
        int K, float* __restrict__ stats) {
    extern __shared__ __nv_bfloat16 sm[];
    __shared__ float s_sum[128], s_sq[128];

    const int tid = threadIdx.x;
    const int lane = tid & 31;
    const int wid = tid >> 5;
    const int warp_m = wid & 3;
    const int warp_n = wid >> 2;
    const int rowBase = blockIdx.y * 128;
    const int colBase = blockIdx.x * 128;

    if (STATS && tid < 128) { s_sum[tid] = 0.f; s_sq[tid] = 0.f; }

    float acc[2][8][4] = {};

    const int lg = lane >> 3, lj = lane & 7;
    const int a_row_off = (lg & 1) * 8 + lj;
    const int a_col_off = (lg >> 1) * 8;
    const int b_k_off = (lg & 1) * 8 + lj;
    const int b_n_off = (lg >> 1) * 8;

    const int niter = K >> 5;

    #define CP_ALL(it, buf) do {                                              \
        const int k0 = (it) * 32;                                             \
        __nv_bfloat16* ah = sm + SM_AH + (buf) * 5120;                        \
        __nv_bfloat16* al = sm + SM_AL + (buf) * 5120;                        \
        __nv_bfloat16* wh = sm + SM_WH + (buf) * 4352;                        \
        __nv_bfloat16* wl = sm + SM_WL + (buf) * 4352;                        \
        _Pragma("unroll")                                                     \
        for (int i = 0; i < 2; ++i) {                                         \
            int idx = tid + i * 256;                                          \
            int row = idx >> 2;                                               \
            int c = (idx & 3) * 8;                                            \
            size_t go = (size_t)(rowBase + row) * K + k0 + c;                 \
            CP_ASYNC16(smem_u32(&ah[row * LDA + c]), &Ah_g[go]);              \
            CP_ASYNC16(smem_u32(&al[row * LDA + c]), &Al_g[go]);              \
        }                                                                     \
        _Pragma("unroll")                                                     \
        for (int i = 0; i < 2; ++i) {                                         \
            int idx = tid + i * 256;                                          \
            int row = idx >> 4;                                               \
            int c8 = (idx & 15) * 8;                                          \
            size_t go = (size_t)(k0 + row) * HH + colBase + c8;               \
            CP_ASYNC16(smem_u32(&wh[row * LDW + c8]), &Wh_g[go]);             \
            CP_ASYNC16(smem_u32(&wl[row * LDW + c8]), &Wl_g[go]);             \
        }                                                                     \
        CP_COMMIT();                                                          \
    } while (0)

    CP_ALL(0, 0);
    CP_ALL(1, 1);

    for (int it = 0; it < niter; ++it) {
        const int buf = it & 1;
        if (it + 1 < niter) CP_WAIT1(); else CP_WAIT0();
        __syncthreads();

        const __nv_bfloat16* ah = sm + SM_AH + buf * 5120;
        const __nv_bfloat16* al = sm + SM_AL + buf * 5120;
        const __nv_bfloat16* wh = sm + SM_WH + buf * 4352;
        const __nv_bfloat16* wl = sm + SM_WL + buf * 4352;

        #pragma unroll
        for (int ks = 0; ks < 2; ++ks) {
            const int kb = ks * 16;
            unsigned afr[2][2][4];
            #pragma unroll
            for (int mt = 0; mt < 2; ++mt) {
                int row = warp_m * 32 + mt * 16 + a_row_off;
                int col = kb + a_col_off;
                ldsm_x4(smem_u32(&ah[row * LDA + col]),
                        afr[0][mt][0], afr[0][mt][1], afr[0][mt][2], afr[0][mt][3]);
                ldsm_x4(smem_u32(&al[row * LDA + col]),
                        afr[1][mt][0], afr[1][mt][1], afr[1][mt][2], afr[1][mt][3]);
            }
            unsigned bfr[4][4];
            #pragma unroll
            for (int p = 0; p < 4; ++p) {
                int kk = kb + b_k_off;
                int nn = warp_n * 64 + p * 16 + b_n_off;
                ldsm_x4t(smem_u32(&wh[kk * LDW + nn]),
                         bfr[p][0], bfr[p][1], bfr[p][2], bfr[p][3]);
            }
            #pragma unroll
            for (int s = 0; s < 2; ++s)
                #pragma unroll
                for (int mt = 0; mt < 2; ++mt)
                    #pragma unroll
                    for (int p = 0; p < 4; ++p) {
                        mma_bf16(acc[mt][2 * p],     afr[s][mt], bfr[p][0], bfr[p][1]);
                        mma_bf16(acc[mt][2 * p + 1], afr[s][mt], bfr[p][2], bfr[p][3]);
                    }
            #pragma unroll
            for (int p = 0; p < 4; ++p) {
                int kk = kb + b_k_off;
                int nn = warp_n * 64 + p * 16 + b_n_off;
                ldsm_x4t(smem_u32(&wl[kk * LDW + nn]),
                         bfr[p][0], bfr[p][1], bfr[p][2], bfr[p][3]);
            }
            #pragma unroll
            for (int mt = 0; mt < 2; ++mt)
                #pragma unroll
                for (int p = 0; p < 4; ++p) {
                    mma_bf16(acc[mt][2 * p],     afr[0][mt], bfr[p][0], bfr[p][1]);
                    mma_bf16(acc[mt][2 * p + 1], afr[0][mt], bfr[p][2], bfr[p][3]);
                }
        }
        __syncthreads();
        if (it + 2 < niter) CP_ALL(it + 2, buf);
    }

    // ---- epilogue: bias + ReLU, then either bf16 planes or fp32+stats ----
    const int g = lane >> 2, tq = lane & 3;
    float cs[16], cq[16];
    if (STATS) {
        #pragma unroll
        for (int i = 0; i < 16; ++i) { cs[i] = 0.f; cq[i] = 0.f; }
    }
    #pragma unroll
    for (int mt = 0; mt < 2; ++mt) {
        #pragma unroll
        for (int nt = 0; nt < 8; ++nt) {
            int row0 = rowBase + warp_m * 32 + mt * 16 + g;
            int col = colBase + warp_n * 64 + nt * 8 + 2 * tq;
            float b0 = bias[col], b1 = bias[col + 1];
            float v[4] = {fmaxf(acc[mt][nt][0] + b0, 0.f),
                          fmaxf(acc[mt][nt][1] + b1, 0.f),
                          fmaxf(acc[mt][nt][2] + b0, 0.f),
                          fmaxf(acc[mt][nt][3] + b1, 0.f)};
            if (STATS) {
                cs[nt * 2 + 0] += v[0] + v[2];
                cs[nt * 2 + 1] += v[1] + v[3];
                cq[nt * 2 + 0] += v[0] * v[0] + v[2] * v[2];
                cq[nt * 2 + 1] += v[1] * v[1] + v[3] * v[3];
                *reinterpret_cast<float2*>(&Cf[(size_t)row0 * HH + col]) =
                    make_float2(v[0], v[1]);
                *reinterpret_cast<float2*>(&Cf[(size_t)(row0 + 8) * HH + col]) =
                    make_float2(v[2], v[3]);
            } else {
                __nv_bfloat16 h0, l0, h1, l1;
                split_bf16(v[0], h0, l0); split_bf16(v[1], h1, l1);
                unsigned hp = ((unsigned)*(unsigned short*)&h1 << 16) |
                              *(unsigned short*)&h0;
                unsigned lp = ((unsigned)*(unsigned short*)&l1 << 16) |
                              *(unsigned short*)&l0;
                *reinterpret_cast<unsigned*>(&Ch[(size_t)row0 * HH + col]) = hp;
                *reinterpret_cast<unsigned*>(&Cl[(size_t)row0 * HH + col]) = lp;
                split_bf16(v[2], h0, l0); split_bf16(v[3], h1, l1);
                hp = ((unsigned)*(unsigned short*)&h1 << 16) | *(unsigned short*)&h0;
                lp = ((unsigned)*(unsigned short*)&l1 << 16) | *(unsigned short*)&l0;
                *reinterpret_cast<unsigned*>(&Ch[(size_t)(row0 + 8) * HH + col]) = hp;
                *reinterpret_cast<unsigned*>(&Cl[(size_t)(row0 + 8) * HH + col]) = lp;
            }
        }
    }
    if (STATS) {
        #pragma unroll
        for (int i = 0; i < 16; ++i) {
            #pragma unroll
            for (int off = 16; off >= 4; off >>= 1) {
                cs[i] += __shfl_down_sync(0xffffffffu, cs[i], off);
                cq[i] += __shfl_down_sync(0xffffffffu, cq[i], off);
            }
        }
        if (lane < 4) {
            #pragma unroll
            for (int nt = 0; nt < 8; ++nt) {
                #pragma unroll
                for (int c = 0; c < 2; ++c) {
                    int lc = warp_n * 64 + nt * 8 + 2 * lane + c;
                    atomicAdd(&s_sum[lc], cs[nt * 2 + c]);
                    atomicAdd(&s_sq[lc], cq[nt * 2 + c]);
                }
            }
        }
        __syncthreads();
        int c = tid & 127;
        if (tid < 128) atomicAdd(&stats[colBase + c], s_sum[c]);
        else           atomicAdd(&stats[HH + colBase + c], s_sq[c]);
    }
    #undef CP_ALL
}

// -------- fp32-input GEMM (c1 layer: bn2 affine on A, tanh output) ---------
__global__ void __launch_bounds__(256)
gemm_f2f(const float* __restrict__ A,
         const __nv_bfloat16* __restrict__ Wth,
         const __nv_bfloat16* __restrict__ Wtl,
         const float* __restrict__ bias, float* __restrict__ C,
         int K, const float* __restrict__ asb) {
    extern __shared__ __nv_bfloat16 sm[];
    const int tid = threadIdx.x;
    const int lane = tid & 31;
    const int wid = tid >> 5;
    const int warp_m = wid & 3;
    const int warp_n = wid >> 2;
    const int rowBase = blockIdx.y * 128;
    const int colBase = blockIdx.x * 128;

    float acc[2][8][4] = {};
    float4 a_reg[4];

    const int lg = lane >> 3, lj = lane & 7;
    const int a_row_off = (lg & 1) * 8 + lj;
    const int a_col_off = (lg >> 1) * 8;
    const int b_k_off = (lg & 1) * 8 + lj;
    const int b_n_off = (lg >> 1) * 8;

    const int niter = K >> 5;

    #define LOAD_A(it) do {                                                   \
        const int k0 = (it) * 32;                                             \
        _Pragma("unroll")                                                     \
        for (int i = 0; i < 4; ++i) {                                         \
            int idx = tid + i * 256;                                          \
            int row = idx >> 3;                                               \
            int c = (idx & 7) * 4;                                            \
            a_reg[i] = *reinterpret_cast<const float4*>(                      \
                &A[(size_t)(rowBase + row) * K + k0 + c]);                    \
            float4 sv = *reinterpret_cast<const float4*>(&asb[k0 + c]);       \
            float4 bv = *reinterpret_cast<const float4*>(&asb[HH + k0 + c]);  \
            a_reg[i].x = sv.x * a_reg[i].x + bv.x;                            \
            a_reg[i].y = sv.y * a_reg[i].y + bv.y;                            \
            a_reg[i].z = sv.z * a_reg[i].z + bv.z;                            \
            a_reg[i].w = sv.w * a_reg[i].w + bv.w;                            \
        }                                                                     \
    } while (0)

    #define STORE_A(buf) do {                                                 \
        __nv_bfloat16* ah = sm + SM_AH + (buf) * 5120;                        \
        __nv_bfloat16* al = sm + SM_AL + (buf) * 5120;                        \
        _Pragma("unroll")                                                     \
        for (int i = 0; i < 4; ++i) {                                         \
            int idx = tid + i * 256;                                          \
            int row = idx >> 3;                                               \
            int c = (idx & 7) * 4;                                            \
            float vv[4] = {a_reg[i].x, a_reg[i].y, a_reg[i].z, a_reg[i].w};   \
            unsigned hp[2], lp[2];                                            \
            _Pragma("unroll")                                                 \
            for (int q = 0; q < 2; ++q) {                                     \
                __nv_bfloat16 h0, l0, h1, l1;                                 \
                split_bf16(vv[2 * q], h0, l0);                                \
                split_bf16(vv[2 * q + 1], h1, l1);                            \
                hp[q] = ((unsigned)*(unsigned short*)&h1 << 16) |             \
                        *(unsigned short*)&h0;                                \
                lp[q] = ((unsigned)*(unsigned short*)&l1 << 16) |             \
                        *(unsigned short*)&l0;                                \
            }                                                                 \
            *reinterpret_cast<uint2*>(&ah[row * LDA + c]) =                   \
                make_uint2(hp[0], hp[1]);                                     \
            *reinterpret_cast<uint2*>(&al[row * LDA + c]) =                   \
                make_uint2(lp[0], lp[1]);                                     \
        }                                                                     \
    } while (0)

    #define CP_W(it, buf) do {                                                \
        const int k0 = (it) * 32;                                             \
        __nv_bfloat16* wh = sm + SM_WH + (buf) * 4352;                        \
        __nv_bfloat16* wl = sm + SM_WL + (buf) * 4352;                        \
        _Pragma("unroll")                                                     \
        for (int i = 0; i < 2; ++i) {                                         \
            int idx = tid + i * 256;                                          \
            int row = idx >> 4;                                               \
            int c8 = (idx & 15) * 8;                                          \
            size_t go = (size_t)(k0 + row) * HH + colBase + c8;               \
            CP_ASYNC16(smem_u32(&wh[row * LDW + c8]), &Wth[go]);              \
            CP_ASYNC16(smem_u32(&wl[row * LDW + c8]), &Wtl[go]);              \
        }                                                                     \
        CP_COMMIT();                                                          \
    } while (0)

    LOAD_A(0);
    CP_W(0, 0);

    for (int it = 0; it < niter; ++it) {
        const int buf = it & 1;
        CP_WAIT0();
        STORE_A(buf);
        __syncthreads();
        if (it + 1 < niter) {
            LOAD_A(it + 1);
            CP_W(it + 1, buf ^ 1);
        }
        const __nv_bfloat16* ah = sm + SM_AH + buf * 5120;
        const __nv_bfloat16* al = sm + SM_AL + buf * 5120;
        const __nv_bfloat16* wh = sm + SM_WH + buf * 4352;
        const __nv_bfloat16* wl = sm + SM_WL + buf * 4352;

        #pragma unroll
        for (int ks = 0; ks < 2; ++ks) {
            const int kb = ks * 16;
            unsigned afr[2][2][4];
            #pragma unroll
            for (int mt = 0; mt < 2; ++mt) {
                int row = warp_m * 32 + mt * 16 + a_row_off;
                int col = kb + a_col_off;
                ldsm_x4(smem_u32(&ah[row * LDA + col]),
                        afr[0][mt][0], afr[0][mt][1], afr[0][mt][2], afr[0][mt][3]);
                ldsm_x4(smem_u32(&al[row * LDA + col]),
                        afr[1][mt][0], afr[1][mt][1], afr[1][mt][2], afr[1][mt][3]);
            }
            unsigned bfr[4][4];
            #pragma unroll
            for (int p = 0; p < 4; ++p) {
                int kk = kb + b_k_off;
                int nn = warp_n * 64 + p * 16 + b_n_off;
                ldsm_x4t(smem_u32(&wh[kk * LDW + nn]),
                         bfr[p][0], bfr[p][1], bfr[p][2], bfr[p][3]);
            }
            #pragma unroll
            for (int s = 0; s < 2; ++s)
                #pragma unroll
                for (int mt = 0; mt < 2; ++mt)
                    #pragma unroll
                    for (int p = 0; p < 4; ++p) {
                        mma_bf16(acc[mt][2 * p],     afr[s][mt], bfr[p][0], bfr[p][1]);
                        mma_bf16(acc[mt][2 * p + 1], afr[s][mt], bfr[p][2], bfr[p][3]);
                    }
            #pragma unroll
            for (int p = 0; p < 4; ++p) {
                int kk = kb + b_k_off;
                int nn = warp_n * 64 + p * 16 + b_n_off;
                ldsm_x4t(smem_u32(&wl[kk * LDW + nn]),
                         bfr[p][0], bfr[p][1], bfr[p][2], bfr[p][3]);
            }
            #pragma unroll
            for (int mt = 0; mt < 2; ++mt)
                #pragma unroll
                for (int p = 0; p < 4; ++p) {
                    mma_bf16(acc[mt][2 * p],     afr[0][mt], bfr[p][0], bfr[p][1]);
                    mma_bf16(acc[mt][2 * p + 1], afr[0][mt], bfr[p][2], bfr[p][3]);
                }
        }
        __syncthreads();
    }

    const int g = lane >> 2, tq = lane & 3;
    #pragma unroll
    for (int mt = 0; mt < 2; ++mt) {
        #pragma unroll
        for (int nt = 0; nt < 8; ++nt) {
            int row0 = rowBase + warp_m * 32 + mt * 16 + g;
            int col = colBase + warp_n * 64 + nt * 8 + 2 * tq;
            float b0 = bias[col], b1 = bias[col + 1];
            float v[4] = {tanhf(acc[mt][nt][0] + b0), tanhf(acc[mt][nt][1] + b1),
                          tanhf(acc[mt][nt][2] + b0), tanhf(acc[mt][nt][3] + b1)};
            *reinterpret_cast<float2*>(&C[(size_t)row0 * HH + col]) =
                make_float2(v[0], v[1]);
            *reinterpret_cast<float2*>(&C[(size_t)(row0 + 8) * HH + col]) =
                make_float2(v[2], v[3]);
        }
    }
    #undef LOAD_A
    #undef STORE_A
    #undef CP_W
}

// ---------------- assignment softmax ---------------------------------------
__global__ void assign_kernel(const float* __restrict__ T,
                              const float* __restrict__ c2w,
                              const float* __restrict__ c2b,
                              float* __restrict__ Aout) {
    const int lane = threadIdx.x & 31;
    const int row = blockIdx.x * 8 + (threadIdx.x >> 5);
    float s0 = 0.f, s1 = 0.f;
    #pragma unroll
    for (int k = lane; k < HH; k += 32) {
        float tv = T[(size_t)row * HH + k];
        s0 += tv * c2w[k * 2 + 0];
        s1 += tv * c2w[k * 2 + 1];
    }
    #pragma unroll
    for (int o = 16; o > 0; o >>= 1) {
        s0 += __shfl_xor_sync(0xffffffffu, s0, o);
        s1 += __shfl_xor_sync(0xffffffffu, s1, o);
    }
    if (lane == 0) {
        s0 += c2b[0]; s1 += c2b[1];
        float m = fmaxf(s0, s1);
        float e0 = expf(s0 - m), e1 = expf(s1 - m);
        float inv = 1.f / (e0 + e1);
        Aout[row * 2 + 0] = e0 * inv;
        Aout[row * 2 + 1] = e1 * inv;
    }
}

// ---------------- pooling (applies layer-2 BN affine on the fly) -----------
__global__ void pool_kernel(const float* __restrict__ Z,
                            const float* __restrict__ Aa,
                            float* __restrict__ sub_out,
                            float* __restrict__ graph_out) {
    __shared__ float sa0[NPG];
    const int g = blockIdx.x, t = threadIdx.x;
    if (t < NPG) sa0[t] = Aa[(g * NPG + t) * 2];
    __syncthreads();
    const float sf = d_bnsb[2 * 2 * HH + t];
    const float bf = d_bnsb[2 * 2 * HH + HH + t];
    float sh = 0.f, ss = 0.f;
    const size_t base = (size_t)g * NPG * HH;
    for (int r = 0; r < NPG; ++r) {
        float hv = sf * Z[base + r * HH + t] + bf;
        sh += hv;
        ss += sa0[r] * hv;
    }
    sub_out[g * HH + t] = ss;
    graph_out[g * HH + t] = sh * (1.f / NPG);
}

// ---------------- pooled adjacency diag penalty -----------------------------
__global__ void adj_kernel(const float* __restrict__ Aa,
                           const int* __restrict__ src,
                           const int* __restrict__ dst) {
    const int g = blockIdx.x, t = threadIdx.x;
    float m00 = 0.f, m01 = 0.f, m10 = 0.f, m11 = 0.f;
    for (int e = t; e < EPG; e += 128) {
        int se = src[g * EPG + e], de = dst[g * EPG + e];
        float a0 = Aa[se * 2], a1 = Aa[se * 2 + 1];
        float b0 = Aa[de * 2], b1 = Aa[de * 2 + 1];
        m00 += a0 * b0; m01 += a0 * b1;
        m10 += a1 * b0; m11 += a1 * b1;
    }
    __shared__ float red[4][128];
    red[0][t] = m00; red[1][t] = m01; red[2][t] = m10; red[3][t] = m11;
    __syncthreads();
    for (int s = 64; s > 0; s >>= 1) {
        if (t < s) {
            red[0][t] += red[0][t + s]; red[1][t] += red[1][t + s];
            red[2][t] += red[2][t + s]; red[3][t] += red[3][t + s];
        }
        __syncthreads();
    }
    if (t == 0) {
        float r0 = fmaxf(fabsf(red[0][0]) + fabsf(red[1][0]), 1e-12f);
        float r1 = fmaxf(fabsf(red[2][0]) + fabsf(red[3][0]), 1e-12f);
        float e0 = red[0][0] / r0 - 1.f;
        float e1 = red[3][0] / r1 - 1.f;
        d_pen[g] = 0.5f * (e0 * e0 + e1 * e1);
    }
}

__global__ void pen_reduce_kernel(float* __restrict__ outp) {
    __shared__ float s[BB];
    s[threadIdx.x] = d_pen[threadIdx.x];
    __syncthreads();
    for (int st = BB / 2; st > 0; st >>= 1) {
        if (threadIdx.x < st) s[threadIdx.x] += s[threadIdx.x + st];
        __syncthreads();
    }
    if (threadIdx.x == 0) outp[0] = s[0] * (1.f / BB);
}

// ---------------- classifier head -------------------------------------------
__global__ void head_kernel(const float* __restrict__ sub,
                            const float* __restrict__ l1w,
                            const float* __restrict__ l1b,
                            const float* __restrict__ l2w,
                            const float* __restrict__ l2b,
                            float* __restrict__ outp) {
    __shared__ float ssub[HH];
    __shared__ float red0[HH], red1[HH];
    const int r = blockIdx.x, t = threadIdx.x;
    ssub[t] = sub[r * HH + t];
    __syncthreads();
    float acc = l1b[t];
    #pragma unroll 8
    for (int k = 0; k < HH; ++k) acc += ssub[k] * l1w[k * HH + t];
    float zc = fmaxf(acc, 0.f);
    red0[t] = zc * l2w[t * 2 + 0];
    red1[t] = zc * l2w[t * 2 + 1];
    __syncthreads();
    for (int s = 128; s > 0; s >>= 1) {
        if (t < s) { red0[t] += red0[t + s]; red1[t] += red1[t + s]; }
        __syncthreads();
    }
    if (t == 0) {
        float s0 = red0[0] + l2b[0], s1 = red1[0] + l2b[1];
        float m = fmaxf(s0, s1);
        float lse = m + logf(expf(s0 - m) + expf(s1 - m));
        outp[r * 2 + 0] = s0 - lse;
        outp[r * 2 + 1] = s1 - lse;
    }
}

// ---------------- launch ------------------------------------------------------
extern "C" void kernel_launch(void* const* d_in, const int* in_sizes, int n_in,
                              void* d_out, int out_size) {
    const float* x    = (const float*)d_in[0];
    const int*   ei   = (const int*)d_in[1];
    const int*   src  = ei;
    const int*   dst  = ei + EE;
    const float* w0_1 = (const float*)d_in[3];
    const float* b0_1 = (const float*)d_in[4];
    const float* w0_2 = (const float*)d_in[5];
    const float* b0_2 = (const float*)d_in[6];
    const float* g0   = (const float*)d_in[7];
    const float* be0  = (const float*)d_in[8];
    const float* wl1  = (const float*)d_in[9];
    const float* bl1  = (const float*)d_in[10];
    const float* wl2  = (const float*)d_in[11];
    const float* bl2  = (const float*)d_in[12];
    const float* gl   = (const float*)d_in[13];
    const float* bel  = (const float*)d_in[14];
    const float* c1w  = (const float*)d_in[15];
    const float* c1b  = (const float*)d_in[16];
    const float* c2w  = (const float*)d_in[17];
    const float* c2b  = (const float*)d_in[18];
    const float* l1w  = (const float*)d_in[19];
    const float* l1b  = (const float*)d_in[20];
    const float* l2w  = (const float*)d_in[21];
    const float* l2b  = (const float*)d_in[22];

    float* out        = (float*)d_out;
    float* out_logits = out;
    float* out_sub    = out + BB * 2;
    float* out_graph  = out + BB * 2 + BB * HH;
    float* out_pen    = out + BB * 2 + 2 * BB * HH;

    float *zb, *tb, *ab, *stats, *bnsb;
    cudaGetSymbolAddress((void**)&zb, d_z);
    cudaGetSymbolAddress((void**)&tb, d_t);
    cudaGetSymbolAddress((void**)&ab, d_a);
    cudaGetSymbolAddress((void**)&stats, d_stats);
    cudaGetSymbolAddress((void**)&bnsb, d_bnsb);
    __nv_bfloat16 *wth, *wtl, *ah, *al, *th, *tl;
    cudaGetSymbolAddress((void**)&wth, d_wth);
    cudaGetSymbolAddress((void**)&wtl, d_wtl);
    cudaGetSymbolAddress((void**)&ah, d_ah);
    cudaGetSymbolAddress((void**)&al, d_al);
    cudaGetSymbolAddress((void**)&th, d_th);
    cudaGetSymbolAddress((void**)&tl, d_tl);

    cudaFuncSetAttribute(gemm_bb<false>,
                         cudaFuncAttributeMaxDynamicSharedMemorySize, GEMM_SMEM_BYTES);
    cudaFuncSetAttribute(gemm_bb<true>,
                         cudaFuncAttributeMaxDynamicSharedMemorySize, GEMM_SMEM_BYTES);
    cudaFuncSetAttribute(gemm_f2f,
                         cudaFuncAttributeMaxDynamicSharedMemorySize, GEMM_SMEM_BYTES);

    const int O_W01 = 0;
    const int O_W02 = 32768;
    const int O_L1A = 98304;
    const int O_L2A = 163840;
    const int O_L1B = 229376;
    const int O_L2B = 294912;
    const int O_C1  = 360448;

    const dim3 gemm_grid(HH / 128, NN / 128);

    wsplit_all_kernel<<<(WSPLIT_TOTAL + 255) / 256, 256>>>(
        w0_1, w0_2, wl1, wl2, c1w, wth, wtl);                             // 0
    csr_kernel<<<BB, NPG>>>(src, dst);                                    // 1
    agg_gather_bf<FIN, false><<<NN / 8, 256>>>(x, ah, al, 0);             // 2
    gemm_bb<false><<<gemm_grid, 256, GEMM_SMEM_BYTES>>>(                  // 3 (profiled)
        ah, al, wth + O_W01, wtl + O_W01, b0_1, nullptr, th, tl, FIN, nullptr);
    bn_zero_all_kernel<<<3, 512>>>();                                     // 4
    gemm_bb<true><<<gemm_grid, 256, GEMM_SMEM_BYTES>>>(                   // 5
        th, tl, wth + O_W02, wtl + O_W02, b0_2, zb, nullptr, nullptr, HH, stats);
    bn_finalize_kernel<<<1, 256>>>(g0, be0, 0);

    const int offs1[2] = {O_L1A, O_L1B};
    const int offs2[2] = {O_L2A, O_L2B};
    for (int i = 0; i < 2; ++i) {
        agg_gather_bf<HH, true><<<NN / 8, 256>>>(zb, ah, al, i);
        gemm_bb<false><<<gemm_grid, 256, GEMM_SMEM_BYTES>>>(
            ah, al, wth + offs1[i], wtl + offs1[i], bl1 + i * HH,
            nullptr, th, tl, HH, nullptr);
        gemm_bb<true><<<gemm_grid, 256, GEMM_SMEM_BYTES>>>(
            th, tl, wth + offs2[i], wtl + offs2[i], bl2 + i * HH,
            zb, nullptr, nullptr, HH, stats + (1 + i) * 2 * HH);
        bn_finalize_kernel<<<1, 256>>>(gl + i * HH, bel + i * HH, 1 + i);
    }

    // ---- assignment (A = bn2(z) applied in-GEMM, tanh) ----
    gemm_f2f<<<gemm_grid, 256, GEMM_SMEM_BYTES>>>(
        zb, wth + O_C1, wtl + O_C1, c1b, tb, HH, bnsb + 2 * 2 * HH);
    assign_kernel<<<NN / 8, 256>>>(tb, c2w, c2b, ab);

    // ---- pooling / penalty / head ----
    pool_kernel<<<BB, 256>>>(zb, ab, out_sub, out_graph);
    adj_kernel<<<BB, 128>>>(ab, src, dst);
    pen_reduce_kernel<<<1, BB>>>(out_pen);
    head_kernel<<<BB, 256>>>(out_sub, l1w, l1b, l2w, l2b, out_logits);
}

// round 11
// speedup vs baseline: 1.0538x; 1.0538x over previous
#include <cuda_runtime.h>
#include <cuda_bf16.h>
#include <math.h>

// Problem constants (fixed by setup_inputs)
#define NN      65536
#define BB      512
#define NPG     128
#define EE      262144
#define EPG     512
#define HH      256
#define FIN     128
#define BN_EPS  1e-5f

// ---------------- scratch (device globals; no cudaMalloc allowed) ----------
__device__ float d_z[NN * HH];
__device__ float d_t[NN * HH];
__device__ float d_a[NN * 2];
__device__ float d_stats[3 * 2 * HH];
__device__ float d_bnsb[3 * 2 * HH];
__device__ float d_pen[BB];
__device__ int   d_csr[EE];
__device__ int   d_rowstart[NN];
__device__ int   d_deg[NN];
// activation planes (bf16 hi/lo)
__device__ __nv_bfloat16 d_ah[NN * HH];
__device__ __nv_bfloat16 d_al[NN * HH];
__device__ __nv_bfloat16 d_th[NN * HH];
__device__ __nv_bfloat16 d_tl[NN * HH];
// weight planes
#define WSPLIT_TOTAL (256 * (128 + 6 * 256))
__device__ __nv_bfloat16 d_wth[WSPLIT_TOTAL];
__device__ __nv_bfloat16 d_wtl[WSPLIT_TOTAL];

// ---------------- helpers ----------------------------------------------------
__device__ __forceinline__ unsigned smem_u32(const void* p) {
    return (unsigned)__cvta_generic_to_shared(p);
}
__device__ __forceinline__ void ldsm_x4(unsigned addr, unsigned& r0, unsigned& r1,
                                        unsigned& r2, unsigned& r3) {
    asm volatile("ldmatrix.sync.aligned.m8n8.x4.shared.b16 {%0,%1,%2,%3}, [%4];"
                 : "=r"(r0), "=r"(r1), "=r"(r2), "=r"(r3) : "r"(addr));
}
__device__ __forceinline__ void ldsm_x4t(unsigned addr, unsigned& r0, unsigned& r1,
                                         unsigned& r2, unsigned& r3) {
    asm volatile("ldmatrix.sync.aligned.m8n8.x4.trans.shared.b16 {%0,%1,%2,%3}, [%4];"
                 : "=r"(r0), "=r"(r1), "=r"(r2), "=r"(r3) : "r"(addr));
}
__device__ __forceinline__ void mma_bf16(float* d, const unsigned* a,
                                         unsigned b0, unsigned b1) {
    asm volatile("mma.sync.aligned.m16n8k16.row.col.f32.bf16.bf16.f32 "
                 "{%0,%1,%2,%3}, {%4,%5,%6,%7}, {%8,%9}, {%0,%1,%2,%3};"
                 : "+f"(d[0]), "+f"(d[1]), "+f"(d[2]), "+f"(d[3])
                 : "r"(a[0]), "r"(a[1]), "r"(a[2]), "r"(a[3]), "r"(b0), "r"(b1));
}
__device__ __forceinline__ void split_bf16(float v, __nv_bfloat16& h, __nv_bfloat16& l) {
    h = __float2bfloat16(v);
    l = __float2bfloat16(v - __bfloat162float(h));
}
#define CP_ASYNC16(dst, src) \
    asm volatile("cp.async.cg.shared.global [%0], [%1], 16;" \
                 :: "r"(dst), "l"(src))
#define CP_COMMIT() asm volatile("cp.async.commit_group;")
#define CP_WAIT0()  asm volatile("cp.async.wait_group 0;")

// ---------------- BN stats zero ----------------------------------------------
__global__ void bn_zero_all_kernel() {
    int i = blockIdx.x * 512 + threadIdx.x;
    if (i < 3 * 2 * HH) d_stats[i] = 0.f;
}

// ---------------- BN finalize: stats -> (s, b) --------------------------------
__global__ void bn_finalize_kernel(const float* __restrict__ gamma,
                                   const float* __restrict__ beta, int layer) {
    const int f = threadIdx.x;
    const float* st = d_stats + layer * 2 * HH;
    const float mu  = st[f] * (1.f / NN);
    const float var = st[HH + f] * (1.f / NN) - mu * mu;
    const float s = rsqrtf(var + BN_EPS) * gamma[f];
    d_bnsb[layer * 2 * HH + f] = s;
    d_bnsb[layer * 2 * HH + HH + f] = beta[f] - mu * s;
}

// ---------------- weight prep ----------------------------------------------
__global__ void wsplit_all_kernel(const float* __restrict__ w01,
                                  const float* __restrict__ w02,
                                  const float* __restrict__ wl1,
                                  const float* __restrict__ wl2,
                                  const float* __restrict__ c1w,
                                  __nv_bfloat16* __restrict__ oh,
                                  __nv_bfloat16* __restrict__ ol) {
    int id = blockIdx.x * 256 + threadIdx.x;
    if (id >= WSPLIT_TOTAL) return;
    const float* src;
    if (id < 32768) {
        src = w01 + id;
    } else {
        int r = id - 32768;
        int m = r >> 16, off = r & 65535;
        const float* bases[6] = {w02, wl1, wl2, wl1 + 65536, wl2 + 65536, c1w};
        src = bases[m] + off;
    }
    __nv_bfloat16 h, l;
    split_bf16(*src, h, l);
    oh[id] = h; ol[id] = l;
}

// ---------------- CSR build --------------------------------------------------
__global__ void csr_kernel(const int* __restrict__ src,
                           const int* __restrict__ dst) {
    __shared__ int   ssrc[EPG];
    __shared__ short sdst[EPG];
    __shared__ int   sscan[NPG];
    const int g = blockIdx.x, t = threadIdx.x;
    const int ebase = g * EPG;
    for (int i = t; i < EPG; i += NPG) {
        ssrc[i] = src[ebase + i];
        sdst[i] = (short)(dst[ebase + i] - g * NPG);
    }
    __syncthreads();
    int cnt = 0;
    #pragma unroll 8
    for (int e = 0; e < EPG; ++e) cnt += (sdst[e] == t);
    sscan[t] = cnt;
    __syncthreads();
    for (int off = 1; off < NPG; off <<= 1) {
        int v = (t >= off) ? sscan[t - off] : 0;
        __syncthreads();
        sscan[t] += v;
        __syncthreads();
    }
    int o = ebase + sscan[t] - cnt;
    d_rowstart[g * NPG + t] = o;
    d_deg[g * NPG + t] = cnt;
    for (int e = 0; e < EPG; ++e)
        if (sdst[e] == t) d_csr[o++] = ssrc[e];
}

// ------ gather aggregation -> pre-split bf16 hi/lo planes (BN optional) ----
template <int F, bool BN>
__global__ void agg_gather_bf(const float* __restrict__ h,
                              __nv_bfloat16* __restrict__ zh,
                              __nv_bfloat16* __restrict__ zl, int layer) {
    const int node = blockIdx.x * 8 + (threadIdx.x >> 5);
    const int lane = threadIdx.x & 31;
    const int s = d_rowstart[node];
    const int dg = d_deg[node];
    const int c0 = lane * 4;
    const size_t rb = (size_t)node * F;
    float4 a0 = *reinterpret_cast<const float4*>(&h[rb + c0]);
    float4 a1;
    if (F == 256) a1 = *reinterpret_cast<const float4*>(&h[rb + c0 + 128]);
    for (int e = 0; e < dg; ++e) {
        const size_t sb = (size_t)__ldg(&d_csr[s + e]) * F;
        float4 b0 = *reinterpret_cast<const float4*>(&h[sb + c0]);
        a0.x += b0.x; a0.y += b0.y; a0.z += b0.z; a0.w += b0.w;
        if (F == 256) {
            float4 b1 = *reinterpret_cast<const float4*>(&h[sb + c0 + 128]);
            a1.x += b1.x; a1.y += b1.y; a1.z += b1.z; a1.w += b1.w;
        }
    }
    if (BN) {
        const float* sb = d_bnsb + layer * 2 * HH;
        const float dp1 = (float)(dg + 1);
        float4 sv = *reinterpret_cast<const float4*>(&sb[c0]);
        float4 bv = *reinterpret_cast<const float4*>(&sb[HH + c0]);
        a0.x = sv.x * a0.x + dp1 * bv.x;
        a0.y = sv.y * a0.y + dp1 * bv.y;
        a0.z = sv.z * a0.z + dp1 * bv.z;
        a0.w = sv.w * a0.w + dp1 * bv.w;
        if (F == 256) {
            float4 sv1 = *reinterpret_cast<const float4*>(&sb[c0 + 128]);
            float4 bv1 = *reinterpret_cast<const float4*>(&sb[HH + c0 + 128]);
            a1.x = sv1.x * a1.x + dp1 * bv1.x;
            a1.y = sv1.y * a1.y + dp1 * bv1.y;
            a1.z = sv1.z * a1.z + dp1 * bv1.z;
            a1.w = sv1.w * a1.w + dp1 * bv1.w;
        }
    }
    {
        float vv[4] = {a0.x, a0.y, a0.z, a0.w};
        unsigned hp[2], lp[2];
        #pragma unroll
        for (int q = 0; q < 2; ++q) {
            __nv_bfloat16 h0, l0, h1, l1;
            split_bf16(vv[2 * q], h0, l0);
            split_bf16(vv[2 * q + 1], h1, l1);
            hp[q] = ((unsigned)*(unsigned short*)&h1 << 16) | *(unsigned short*)&h0;
            lp[q] = ((unsigned)*(unsigned short*)&l1 << 16) | *(unsigned short*)&l0;
        }
        *reinterpret_cast<uint2*>(&zh[rb + c0]) = make_uint2(hp[0], hp[1]);
        *reinterpret_cast<uint2*>(&zl[rb + c0]) = make_uint2(lp[0], lp[1]);
    }
    if (F == 256) {
        float vv[4] = {a1.x, a1.y, a1.z, a1.w};
        unsigned hp[2], lp[2];
        #pragma unroll
        for (int q = 0; q < 2; ++q) {
            __nv_bfloat16 h0, l0, h1, l1;
            split_bf16(vv[2 * q], h0, l0);
            split_bf16(vv[2 * q + 1], h1, l1);
            hp[q] = ((unsigned)*(unsigned short*)&h1 << 16) | *(unsigned short*)&h0;
            lp[q] = ((unsigned)*(unsigned short*)&l1 << 16) | *(unsigned short*)&l0;
        }
        *reinterpret_cast<uint2*>(&zh[rb + c0 + 128]) = make_uint2(hp[0], hp[1]);
        *reinterpret_cast<uint2*>(&zl[rb + c0 + 128]) = make_uint2(lp[0], lp[1]);
    }
}

// -------- bf16x3 HMMA GEMM, R9 schedule, pre-split A planes ------------------
// STATS=false: output bf16 hi/lo planes.  STATS=true: output fp32 + BN stats.
// 128x128 tile, BK=32, 256 threads (8 warps 4x2), warp tile 32x64.
#define LDA 40
#define LDW 136
#define SM_AH  0
#define SM_AL  10240
#define SM_WH  20480
#define SM_WL  29184
#define GEMM_SMEM_BYTES (37888 * 2)

template <bool STATS>
__global__ void __launch_bounds__(256)
gemm_pp(const __nv_bfloat16* __restrict__ Ah_g,
        const __nv_bfloat16* __restrict__ Al_g,
        const __nv_bfloat16* __restrict__ Wh_g,
        const __nv_bfloat16* __restrict__ Wl_g,
        const float* __restrict__ bias,
        float* __restrict__ Cf,
        __nv_bfloat16* __restrict__ Ch, __nv_bfloat16* __restrict__ Cl,
        int K, float* __restrict__ stats) {
    extern __shared__ __nv_bfloat16 sm[];
    __shared__ float s_sum[128], s_sq[128];

    const int tid = threadIdx.x;
    const int lane = tid & 31;
    const int wid = tid >> 5;
    const int warp_m = wid & 3;
    const int warp_n = wid >> 2;
    const int rowBase = blockIdx.y * 128;
    const int colBase = blockIdx.x * 128;

    if (STATS && tid < 128) { s_sum[tid] = 0.f; s_sq[tid] = 0.f; }

    float acc[2][8][4] = {};
    uint4 a_regh[2], a_regl[2];

    const int lg = lane >> 3, lj = lane & 7;
    const int a_row_off = (lg & 1) * 8 + lj;
    const int a_col_off = (lg >> 1) * 8;
    const int b_k_off = (lg & 1) * 8 + lj;
    const int b_n_off = (lg >> 1) * 8;

    const int niter = K >> 5;

    #define LOAD_A(it) do {                                                   \
        const int k0 = (it) * 32;                                             \
        _Pragma("unroll")                                                     \
        for (int i = 0; i < 2; ++i) {                                         \
            int idx = tid + i * 256;                                          \
            int row = idx >> 2;                                               \
            int c8 = (idx & 3) * 8;                                           \
            size_t go = (size_t)(rowBase + row) * K + k0 + c8;                \
            a_regh[i] = *reinterpret_cast<const uint4*>(&Ah_g[go]);           \
            a_regl[i] = *reinterpret_cast<const uint4*>(&Al_g[go]);           \
        }                                                                     \
    } while (0)

    #define STORE_A(buf) do {                                                 \
        __nv_bfloat16* ah = sm + SM_AH + (buf) * 5120;                        \
        __nv_bfloat16* al = sm + SM_AL + (buf) * 5120;                        \
        _Pragma("unroll")                                                     \
        for (int i = 0; i < 2; ++i) {                                         \
            int idx = tid + i * 256;                                          \
            int row = idx >> 2;                                               \
            int c8 = (idx & 3) * 8;                                           \
            *reinterpret_cast<uint4*>(&ah[row * LDA + c8]) = a_regh[i];       \
            *reinterpret_cast<uint4*>(&al[row * LDA + c8]) = a_regl[i];       \
        }                                                                     \
    } while (0)

    #define CP_W(it, buf) do {                                                \
        const int k0 = (it) * 32;                                             \
        __nv_bfloat16* wh = sm + SM_WH + (buf) * 4352;                        \
        __nv_bfloat16* wl = sm + SM_WL + (buf) * 4352;                        \
        _Pragma("unroll")                                                     \
        for (int i = 0; i < 2; ++i) {                                         \
            int idx = tid + i * 256;                                          \
            int row = idx >> 4;                                               \
            int c8 = (idx & 15) * 8;                                          \
            size_t go = (size_t)(k0 + row) * HH + colBase + c8;               \
            CP_ASYNC16(smem_u32(&wh[row * LDW + c8]), &Wh_g[go]);             \
            CP_ASYNC16(smem_u32(&wl[row * LDW + c8]), &Wl_g[go]);             \
        }                                                                     \
        CP_COMMIT();                                                          \
    } while (0)

    LOAD_A(0);
    CP_W(0, 0);

    for (int it = 0; it < niter; ++it) {
        const int buf = it & 1;
        CP_WAIT0();
        STORE_A(buf);
        __syncthreads();
        if (it + 1 < niter) {
            LOAD_A(it + 1);
            CP_W(it + 1, buf ^ 1);
        }
        const __nv_bfloat16* ah = sm + SM_AH + buf * 5120;
        const __nv_bfloat16* al = sm + SM_AL + buf * 5120;
        const __nv_bfloat16* wh = sm + SM_WH + buf * 4352;
        const __nv_bfloat16* wl = sm + SM_WL + buf * 4352;

        #pragma unroll
        for (int ks = 0; ks < 2; ++ks) {
            const int kb = ks * 16;
            unsigned afr[2][2][4];
            #pragma unroll
            for (int mt = 0; mt < 2; ++mt) {
                int row = warp_m * 32 + mt * 16 + a_row_off;
                int col = kb + a_col_off;
                ldsm_x4(smem_u32(&ah[row * LDA + col]),
                        afr[0][mt][0], afr[0][mt][1], afr[0][mt][2], afr[0][mt][3]);
                ldsm_x4(smem_u32(&al[row * LDA + col]),
                        afr[1][mt][0], afr[1][mt][1], afr[1][mt][2], afr[1][mt][3]);
            }
            unsigned bfr[4][4];
            #pragma unroll
            for (int p = 0; p < 4; ++p) {
                int kk = kb + b_k_off;
                int nn = warp_n * 64 + p * 16 + b_n_off;
                ldsm_x4t(smem_u32(&wh[kk * LDW + nn]),
                         bfr[p][0], bfr[p][1], bfr[p][2], bfr[p][3]);
            }
            #pragma unroll
            for (int s = 0; s < 2; ++s)
                #pragma unroll
                for (int mt = 0; mt < 2; ++mt)
                    #pragma unroll
                    for (int p = 0; p < 4; ++p) {
                        mma_bf16(acc[mt][2 * p],     afr[s][mt], bfr[p][0], bfr[p][1]);
                        mma_bf16(acc[mt][2 * p + 1], afr[s][mt], bfr[p][2], bfr[p][3]);
                    }
            #pragma unroll
            for (int p = 0; p < 4; ++p) {
                int kk = kb + b_k_off;
                int nn = warp_n * 64 + p * 16 + b_n_off;
                ldsm_x4t(smem_u32(&wl[kk * LDW + nn]),
                         bfr[p][0], bfr[p][1], bfr[p][2], bfr[p][3]);
            }
            #pragma unroll
            for (int mt = 0; mt < 2; ++mt)
                #pragma unroll
                for (int p = 0; p < 4; ++p) {
                    mma_bf16(acc[mt][2 * p],     afr[0][mt], bfr[p][0], bfr[p][1]);
                    mma_bf16(acc[mt][2 * p + 1], afr[0][mt], bfr[p][2], bfr[p][3]);
                }
        }
        __syncthreads();
    }

    // ---- epilogue: bias + ReLU, then bf16 planes or fp32+stats ----
    const int g = lane >> 2, tq = lane & 3;
    float cs[16], cq[16];
    if (STATS) {
        #pragma unroll
        for (int i = 0; i < 16; ++i) { cs[i] = 0.f; cq[i] = 0.f; }
    }
    #pragma unroll
    for (int mt = 0; mt < 2; ++mt) {
        #pragma unroll
        for (int nt = 0; nt < 8; ++nt) {
            int row0 = rowBase + warp_m * 32 + mt * 16 + g;
            int col = colBase + warp_n * 64 + nt * 8 + 2 * tq;
            float b0 = bias[col], b1 = bias[col + 1];
            float v[4] = {fmaxf(acc[mt][nt][0] + b0, 0.f),
                          fmaxf(acc[mt][nt][1] + b1, 0.f),
                          fmaxf(acc[mt][nt][2] + b0, 0.f),
                          fmaxf(acc[mt][nt][3] + b1, 0.f)};
            if (STATS) {
                cs[nt * 2 + 0] += v[0] + v[2];
                cs[nt * 2 + 1] += v[1] + v[3];
                cq[nt * 2 + 0] += v[0] * v[0] + v[2] * v[2];
                cq[nt * 2 + 1] += v[1] * v[1] + v[3] * v[3];
                *reinterpret_cast<float2*>(&Cf[(size_t)row0 * HH + col]) =
                    make_float2(v[0], v[1]);
                *reinterpret_cast<float2*>(&Cf[(size_t)(row0 + 8) * HH + col]) =
                    make_float2(v[2], v[3]);
            } else {
                __nv_bfloat16 h0, l0, h1, l1;
                split_bf16(v[0], h0, l0); split_bf16(v[1], h1, l1);
                unsigned hp = ((unsigned)*(unsigned short*)&h1 << 16) |
                              *(unsigned short*)&h0;
                unsigned lp = ((unsigned)*(unsigned short*)&l1 << 16) |
                              *(unsigned short*)&l0;
                *reinterpret_cast<unsigned*>(&Ch[(size_t)row0 * HH + col]) = hp;
                *reinterpret_cast<unsigned*>(&Cl[(size_t)row0 * HH + col]) = lp;
                split_bf16(v[2], h0, l0); split_bf16(v[3], h1, l1);
                hp = ((unsigned)*(unsigned short*)&h1 << 16) | *(unsigned short*)&h0;
                lp = ((unsigned)*(unsigned short*)&l1 << 16) | *(unsigned short*)&l0;
                *reinterpret_cast<unsigned*>(&Ch[(size_t)(row0 + 8) * HH + col]) = hp;
                *reinterpret_cast<unsigned*>(&Cl[(size_t)(row0 + 8) * HH + col]) = lp;
            }
        }
    }
    if (STATS) {
        #pragma unroll
        for (int i = 0; i < 16; ++i) {
            #pragma unroll
            for (int off = 16; off >= 4; off >>= 1) {
                cs[i] += __shfl_down_sync(0xffffffffu, cs[i], off);
                cq[i] += __shfl_down_sync(0xffffffffu, cq[i], off);
            }
        }
        if (lane < 4) {
            #pragma unroll
            for (int nt = 0; nt < 8; ++nt) {
                #pragma unroll
                for (int c = 0; c < 2; ++c) {
                    int lc = warp_n * 64 + nt * 8 + 2 * lane + c;
                    atomicAdd(&s_sum[lc], cs[nt * 2 + c]);
                    atomicAdd(&s_sq[lc], cq[nt * 2 + c]);
                }
            }
        }
        __syncthreads();
        int c = tid & 127;
        if (tid < 128) atomicAdd(&stats[colBase + c], s_sum[c]);
        else           atomicAdd(&stats[HH + colBase + c], s_sq[c]);
    }
    #undef LOAD_A
    #undef STORE_A
    #undef CP_W
}

// -------- fp32-input GEMM (c1 layer: bn2 affine on A, tanh output) ---------
__global__ void __launch_bounds__(256)
gemm_f2f(const float* __restrict__ A,
         const __nv_bfloat16* __restrict__ Wth,
         const __nv_bfloat16* __restrict__ Wtl,
         const float* __restrict__ bias, float* __restrict__ C,
         int K, const float* __restrict__ asb) {
    extern __shared__ __nv_bfloat16 sm[];
    const int tid = threadIdx.x;
    const int lane = tid & 31;
    const int wid = tid >> 5;
    const int warp_m = wid & 3;
    const int warp_n = wid >> 2;
    const int rowBase = blockIdx.y * 128;
    const int colBase = blockIdx.x * 128;

    float acc[2][8][4] = {};
    float4 a_reg[4];

    const int lg = lane >> 3, lj = lane & 7;
    const int a_row_off = (lg & 1) * 8 + lj;
    const int a_col_off = (lg >> 1) * 8;
    const int b_k_off = (lg & 1) * 8 + lj;
    const int b_n_off = (lg >> 1) * 8;

    const int niter = K >> 5;

    #define LOAD_A(it) do {                                                   \
        const int k0 = (it) * 32;                                             \
        _Pragma("unroll")                                                     \
        for (int i = 0; i < 4; ++i) {                                         \
            int idx = tid + i * 256;                                          \
            int row = idx >> 3;                                               \
            int c = (idx & 7) * 4;                                            \
            a_reg[i] = *reinterpret_cast<const float4*>(                      \
                &A[(size_t)(rowBase + row) * K + k0 + c]);                    \
            float4 sv = *reinterpret_cast<const float4*>(&asb[k0 + c]);       \
            float4 bv = *reinterpret_cast<const float4*>(&asb[HH + k0 + c]);  \
            a_reg[i].x = sv.x * a_reg[i].x + bv.x;                            \
            a_reg[i].y = sv.y * a_reg[i].y + bv.y;                            \
            a_reg[i].z = sv.z * a_reg[i].z + bv.z;                            \
            a_reg[i].w = sv.w * a_reg[i].w + bv.w;                            \
        }                                                                     \
    } while (0)

    #define STORE_A(buf) do {                                                 \
        __nv_bfloat16* ah = sm + SM_AH + (buf) * 5120;                        \
        __nv_bfloat16* al = sm + SM_AL + (buf) * 5120;                        \
        _Pragma("unroll")                                                     \
        for (int i = 0; i < 4; ++i) {                                         \
            int idx = tid + i * 256;                                          \
            int row = idx >> 3;                                               \
            int c = (idx & 7) * 4;                                            \
            float vv[4] = {a_reg[i].x, a_reg[i].y, a_reg[i].z, a_reg[i].w};   \
            unsigned hp[2], lp[2];                                            \
            _Pragma("unroll")                                                 \
            for (int q = 0; q < 2; ++q) {                                     \
                __nv_bfloat16 h0, l0, h1, l1;                                 \
                split_bf16(vv[2 * q], h0, l0);                                \
                split_bf16(vv[2 * q + 1], h1, l1);                            \
                hp[q] = ((unsigned)*(unsigned short*)&h1 << 16) |             \
                        *(unsigned short*)&h0;                                \
                lp[q] = ((unsigned)*(unsigned short*)&l1 << 16) |             \
                        *(unsigned short*)&l0;                                \
            }                                                                 \
            *reinterpret_cast<uint2*>(&ah[row * LDA + c]) =                   \
                make_uint2(hp[0], hp[1]);                                     \
            *reinterpret_cast<uint2*>(&al[row * LDA + c]) =                   \
                make_uint2(lp[0], lp[1]);                                     \
        }                                                                     \
    } while (0)

    #define CP_W(it, buf) do {                                                \
        const int k0 = (it) * 32;                                             \
        __nv_bfloat16* wh = sm + SM_WH + (buf) * 4352;                        \
        __nv_bfloat16* wl = sm + SM_WL + (buf) * 4352;                        \
        _Pragma("unroll")                                                     \
        for (int i = 0; i < 2; ++i) {                                         \
            int idx = tid + i * 256;                                          \
            int row = idx >> 4;                                               \
            int c8 = (idx & 15) * 8;                                          \
            size_t go = (size_t)(k0 + row) * HH + colBase + c8;               \
            CP_ASYNC16(smem_u32(&wh[row * LDW + c8]), &Wth[go]);              \
            CP_ASYNC16(smem_u32(&wl[row * LDW + c8]), &Wtl[go]);              \
        }                                                                     \
        CP_COMMIT();                                                          \
    } while (0)

    LOAD_A(0);
    CP_W(0, 0);

    for (int it = 0; it < niter; ++it) {
        const int buf = it & 1;
        CP_WAIT0();
        STORE_A(buf);
        __syncthreads();
        if (it + 1 < niter) {
            LOAD_A(it + 1);
            CP_W(it + 1, buf ^ 1);
        }
        const __nv_bfloat16* ah = sm + SM_AH + buf * 5120;
        const __nv_bfloat16* al = sm + SM_AL + buf * 5120;
        const __nv_bfloat16* wh = sm + SM_WH + buf * 4352;
        const __nv_bfloat16* wl = sm + SM_WL + buf * 4352;

        #pragma unroll
        for (int ks = 0; ks < 2; ++ks) {
            const int kb = ks * 16;
            unsigned afr[2][2][4];
            #pragma unroll
            for (int mt = 0; mt < 2; ++mt) {
                int row = warp_m * 32 + mt * 16 + a_row_off;
                int col = kb + a_col_off;
                ldsm_x4(smem_u32(&ah[row * LDA + col]),
                        afr[0][mt][0], afr[0][mt][1], afr[0][mt][2], afr[0][mt][3]);
                ldsm_x4(smem_u32(&al[row * LDA + col]),
                        afr[1][mt][0], afr[1][mt][1], afr[1][mt][2], afr[1][mt][3]);
            }
            unsigned bfr[4][4];
            #pragma unroll
            for (int p = 0; p < 4; ++p) {
                int kk = kb + b_k_off;
                int nn = warp_n * 64 + p * 16 + b_n_off;
                ldsm_x4t(smem_u32(&wh[kk * LDW + nn]),
                         bfr[p][0], bfr[p][1], bfr[p][2], bfr[p][3]);
            }
            #pragma unroll
            for (int s = 0; s < 2; ++s)
                #pragma unroll
                for (int mt = 0; mt < 2; ++mt)
                    #pragma unroll
                    for (int p = 0; p < 4; ++p) {
                        mma_bf16(acc[mt][2 * p],     afr[s][mt], bfr[p][0], bfr[p][1]);
                        mma_bf16(acc[mt][2 * p + 1], afr[s][mt], bfr[p][2], bfr[p][3]);
                    }
            #pragma unroll
            for (int p = 0; p < 4; ++p) {
                int kk = kb + b_k_off;
                int nn = warp_n * 64 + p * 16 + b_n_off;
                ldsm_x4t(smem_u32(&wl[kk * LDW + nn]),
                         bfr[p][0], bfr[p][1], bfr[p][2], bfr[p][3]);
            }
            #pragma unroll
            for (int mt = 0; mt < 2; ++mt)
                #pragma unroll
                for (int p = 0; p < 4; ++p) {
                    mma_bf16(acc[mt][2 * p],     afr[0][mt], bfr[p][0], bfr[p][1]);
                    mma_bf16(acc[mt][2 * p + 1], afr[0][mt], bfr[p][2], bfr[p][3]);
                }
        }
        __syncthreads();
    }

    const int g = lane >> 2, tq = lane & 3;
    #pragma unroll
    for (int mt = 0; mt < 2; ++mt) {
        #pragma unroll
        for (int nt = 0; nt < 8; ++nt) {
            int row0 = rowBase + warp_m * 32 + mt * 16 + g;
            int col = colBase + warp_n * 64 + nt * 8 + 2 * tq;
            float b0 = bias[col], b1 = bias[col + 1];
            float v[4] = {tanhf(acc[mt][nt][0] + b0), tanhf(acc[mt][nt][1] + b1),
                          tanhf(acc[mt][nt][2] + b0), tanhf(acc[mt][nt][3] + b1)};
            *reinterpret_cast<float2*>(&C[(size_t)row0 * HH + col]) =
                make_float2(v[0], v[1]);
            *reinterpret_cast<float2*>(&C[(size_t)(row0 + 8) * HH + col]) =
                make_float2(v[2], v[3]);
        }
    }
    #undef LOAD_A
    #undef STORE_A
    #undef CP_W
}

// ---------------- assignment softmax ---------------------------------------
__global__ void assign_kernel(const float* __restrict__ T,
                              const float* __restrict__ c2w,
                              const float* __restrict__ c2b,
                              float* __restrict__ Aout) {
    const int lane = threadIdx.x & 31;
    const int row = blockIdx.x * 8 + (threadIdx.x >> 5);
    float s0 = 0.f, s1 = 0.f;
    #pragma unroll
    for (int k = lane; k < HH; k += 32) {
        float tv = T[(size_t)row * HH + k];
        s0 += tv * c2w[k * 2 + 0];
        s1 += tv * c2w[k * 2 + 1];
    }
    #pragma unroll
    for (int o = 16; o > 0; o >>= 1) {
        s0 += __shfl_xor_sync(0xffffffffu, s0, o);
        s1 += __shfl_xor_sync(0xffffffffu, s1, o);
    }
    if (lane == 0) {
        s0 += c2b[0]; s1 += c2b[1];
        float m = fmaxf(s0, s1);
        float e0 = expf(s0 - m), e1 = expf(s1 - m);
        float inv = 1.f / (e0 + e1);
        Aout[row * 2 + 0] = e0 * inv;
        Aout[row * 2 + 1] = e1 * inv;
    }
}

// ---------------- pooling (applies layer-2 BN affine on the fly) -----------
__global__ void pool_kernel(const float* __restrict__ Z,
                            const float* __restrict__ Aa,
                            float* __restrict__ sub_out,
                            float* __restrict__ graph_out) {
    __shared__ float sa0[NPG];
    const int g = blockIdx.x, t = threadIdx.x;
    if (t < NPG) sa0[t] = Aa[(g * NPG + t) * 2];
    __syncthreads();
    const float sf = d_bnsb[2 * 2 * HH + t];
    const float bf = d_bnsb[2 * 2 * HH + HH + t];
    float sh = 0.f, ss = 0.f;
    const size_t base = (size_t)g * NPG * HH;
    for (int r = 0; r < NPG; ++r) {
        float hv = sf * Z[base + r * HH + t] + bf;
        sh += hv;
        ss += sa0[r] * hv;
    }
    sub_out[g * HH + t] = ss;
    graph_out[g * HH + t] = sh * (1.f / NPG);
}

// ---------------- pooled adjacency diag penalty -----------------------------
__global__ void adj_kernel(const float* __restrict__ Aa,
                           const int* __restrict__ src,
                           const int* __restrict__ dst) {
    const int g = blockIdx.x, t = threadIdx.x;
    float m00 = 0.f, m01 = 0.f, m10 = 0.f, m11 = 0.f;
    for (int e = t; e < EPG; e += 128) {
        int se = src[g * EPG + e], de = dst[g * EPG + e];
        float a0 = Aa[se * 2], a1 = Aa[se * 2 + 1];
        float b0 = Aa[de * 2], b1 = Aa[de * 2 + 1];
        m00 += a0 * b0; m01 += a0 * b1;
        m10 += a1 * b0; m11 += a1 * b1;
    }
    __shared__ float red[4][128];
    red[0][t] = m00; red[1][t] = m01; red[2][t] = m10; red[3][t] = m11;
    __syncthreads();
    for (int s = 64; s > 0; s >>= 1) {
        if (t < s) {
            red[0][t] += red[0][t + s]; red[1][t] += red[1][t + s];
            red[2][t] += red[2][t + s]; red[3][t] += red[3][t + s];
        }
        __syncthreads();
    }
    if (t == 0) {
        float r0 = fmaxf(fabsf(red[0][0]) + fabsf(red[1][0]), 1e-12f);
        float r1 = fmaxf(fabsf(red[2][0]) + fabsf(red[3][0]), 1e-12f);
        float e0 = red[0][0] / r0 - 1.f;
        float e1 = red[3][0] / r1 - 1.f;
        d_pen[g] = 0.5f * (e0 * e0 + e1 * e1);
    }
}

__global__ void pen_reduce_kernel(float* __restrict__ outp) {
    __shared__ float s[BB];
    s[threadIdx.x] = d_pen[threadIdx.x];
    __syncthreads();
    for (int st = BB / 2; st > 0; st >>= 1) {
        if (threadIdx.x < st) s[threadIdx.x] += s[threadIdx.x + st];
        __syncthreads();
    }
    if (threadIdx.x == 0) outp[0] = s[0] * (1.f / BB);
}

// ---------------- classifier head -------------------------------------------
__global__ void head_kernel(const float* __restrict__ sub,
                            const float* __restrict__ l1w,
                            const float* __restrict__ l1b,
                            const float* __restrict__ l2w,
                            const float* __restrict__ l2b,
                            float* __restrict__ outp) {
    __shared__ float ssub[HH];
    __shared__ float red0[HH], red1[HH];
    const int r = blockIdx.x, t = threadIdx.x;
    ssub[t] = sub[r * HH + t];
    __syncthreads();
    float acc = l1b[t];
    #pragma unroll 8
    for (int k = 0; k < HH; ++k) acc += ssub[k] * l1w[k * HH + t];
    float zc = fmaxf(acc, 0.f);
    red0[t] = zc * l2w[t * 2 + 0];
    red1[t] = zc * l2w[t * 2 + 1];
    __syncthreads();
    for (int s = 128; s > 0; s >>= 1) {
        if (t < s) { red0[t] += red0[t + s]; red1[t] += red1[t + s]; }
        __syncthreads();
    }
    if (t == 0) {
        float s0 = red0[0] + l2b[0], s1 = red1[0] + l2b[1];
        float m = fmaxf(s0, s1);
        float lse = m + logf(expf(s0 - m) + expf(s1 - m));
        outp[r * 2 + 0] = s0 - lse;
        outp[r * 2 + 1] = s1 - lse;
    }
}

// ---------------- launch ------------------------------------------------------
extern "C" void kernel_launch(void* const* d_in, const int* in_sizes, int n_in,
                              void* d_out, int out_size) {
    const float* x    = (const float*)d_in[0];
    const int*   ei   = (const int*)d_in[1];
    const int*   src  = ei;
    const int*   dst  = ei + EE;
    const float* w0_1 = (const float*)d_in[3];
    const float* b0_1 = (const float*)d_in[4];
    const float* w0_2 = (const float*)d_in[5];
    const float* b0_2 = (const float*)d_in[6];
    const float* g0   = (const float*)d_in[7];
    const float* be0  = (const float*)d_in[8];
    const float* wl1  = (const float*)d_in[9];
    const float* bl1  = (const float*)d_in[10];
    const float* wl2  = (const float*)d_in[11];
    const float* bl2  = (const float*)d_in[12];
    const float* gl   = (const float*)d_in[13];
    const float* bel  = (const float*)d_in[14];
    const float* c1w  = (const float*)d_in[15];
    const float* c1b  = (const float*)d_in[16];
    const float* c2w  = (const float*)d_in[17];
    const float* c2b  = (const float*)d_in[18];
    const float* l1w  = (const float*)d_in[19];
    const float* l1b  = (const float*)d_in[20];
    const float* l2w  = (const float*)d_in[21];
    const float* l2b  = (const float*)d_in[22];

    float* out        = (float*)d_out;
    float* out_logits = out;
    float* out_sub    = out + BB * 2;
    float* out_graph  = out + BB * 2 + BB * HH;
    float* out_pen    = out + BB * 2 + 2 * BB * HH;

    float *zb, *tb, *ab, *stats, *bnsb;
    cudaGetSymbolAddress((void**)&zb, d_z);
    cudaGetSymbolAddress((void**)&tb, d_t);
    cudaGetSymbolAddress((void**)&ab, d_a);
    cudaGetSymbolAddress((void**)&stats, d_stats);
    cudaGetSymbolAddress((void**)&bnsb, d_bnsb);
    __nv_bfloat16 *wth, *wtl, *ah, *al, *th, *tl;
    cudaGetSymbolAddress((void**)&wth, d_wth);
    cudaGetSymbolAddress((void**)&wtl, d_wtl);
    cudaGetSymbolAddress((void**)&ah, d_ah);
    cudaGetSymbolAddress((void**)&al, d_al);
    cudaGetSymbolAddress((void**)&th, d_th);
    cudaGetSymbolAddress((void**)&tl, d_tl);

    cudaFuncSetAttribute(gemm_pp<false>,
                         cudaFuncAttributeMaxDynamicSharedMemorySize, GEMM_SMEM_BYTES);
    cudaFuncSetAttribute(gemm_pp<true>,
                         cudaFuncAttributeMaxDynamicSharedMemorySize, GEMM_SMEM_BYTES);
    cudaFuncSetAttribute(gemm_f2f,
                         cudaFuncAttributeMaxDynamicSharedMemorySize, GEMM_SMEM_BYTES);

    const int O_W01 = 0;
    const int O_W02 = 32768;
    const int O_L1A = 98304;
    const int O_L2A = 163840;
    const int O_L1B = 229376;
    const int O_L2B = 294912;
    const int O_C1  = 360448;

    const dim3 gemm_grid(HH / 128, NN / 128);

    wsplit_all_kernel<<<(WSPLIT_TOTAL + 255) / 256, 256>>>(
        w0_1, w0_2, wl1, wl2, c1w, wth, wtl);                             // 0
    csr_kernel<<<BB, NPG>>>(src, dst);                                    // 1
    agg_gather_bf<FIN, false><<<NN / 8, 256>>>(x, ah, al, 0);             // 2
    gemm_pp<false><<<gemm_grid, 256, GEMM_SMEM_BYTES>>>(                  // 3 (profiled)
        ah, al, wth + O_W01, wtl + O_W01, b0_1, nullptr, th, tl, FIN, nullptr);
    bn_zero_all_kernel<<<3, 512>>>();                                     // 4
    gemm_pp<true><<<gemm_grid, 256, GEMM_SMEM_BYTES>>>(                   // 5
        th, tl, wth + O_W02, wtl + O_W02, b0_2, zb, nullptr, nullptr, HH, stats);
    bn_finalize_kernel<<<1, 256>>>(g0, be0, 0);

    const int offs1[2] = {O_L1A, O_L1B};
    const int offs2[2] = {O_L2A, O_L2B};
    for (int i = 0; i < 2; ++i) {
        agg_gather_bf<HH, true><<<NN / 8, 256>>>(zb, ah, al, i);
        gemm_pp<false><<<gemm_grid, 256, GEMM_SMEM_BYTES>>>(
            ah, al, wth + offs1[i], wtl + offs1[i], bl1 + i * HH,
            nullptr, th, tl, HH, nullptr);
        gemm_pp<true><<<gemm_grid, 256, GEMM_SMEM_BYTES>>>(
            th, tl, wth + offs2[i], wtl + offs2[i], bl2 + i * HH,
            zb, nullptr, nullptr, HH, stats + (1 + i) * 2 * HH);
        bn_finalize_kernel<<<1, 256>>>(gl + i * HH, bel + i * HH, 1 + i);
    }

    // ---- assignment (A = bn2(z) applied in-GEMM, tanh) ----
    gemm_f2f<<<gemm_grid, 256, GEMM_SMEM_BYTES>>>(
        zb, wth + O_C1, wtl + O_C1, c1b, tb, HH, bnsb + 2 * 2 * HH);
    assign_kernel<<<NN / 8, 256>>>(tb, c2w, c2b, ab);

    // ---- pooling / penalty / head ----
    pool_kernel<<<BB, 256>>>(zb, ab, out_sub, out_graph);
    adj_kernel<<<BB, 128>>>(ab, src, dst);
    pen_reduce_kernel<<<1, BB>>>(out_pen);
    head_kernel<<<BB, 256>>>(out_sub, l1w, l1b, l2w, l2b, out_logits);
}

// round 12
// speedup vs baseline: 1.1347x; 1.0768x over previous
#include <cuda_runtime.h>
#include <cuda_bf16.h>
#include <math.h>

// Problem constants (fixed by setup_inputs)
#define NN      65536
#define BB      512
#define NPG     128
#define EE      262144
#define EPG     512
#define HH      256
#define FIN     128
#define BN_EPS  1e-5f

// ---------------- scratch (device globals; no cudaMalloc allowed) ----------
__device__ float d_z[NN * HH];
__device__ float d_t[NN * HH];
__device__ float d_h[NN * HH];
__device__ float d_a[NN * 2];
__device__ float d_alog[NN * 2];
__device__ float d_stats[3 * 2 * HH];   // per layer: [sum(256) | sumsq(256)]
__device__ float d_bnsb[3 * 2 * HH];    // per layer: [s(256) | b(256)]
__device__ float d_pen[BB];
__device__ int   d_csr[EE];
__device__ int   d_rowstart[NN];
__device__ int   d_deg[NN];
#define WSPLIT_TOTAL (256 * (128 + 6 * 256))
__device__ __nv_bfloat16 d_wth[WSPLIT_TOTAL];
__device__ __nv_bfloat16 d_wtl[WSPLIT_TOTAL];

// ---------------- helpers ----------------------------------------------------
__device__ __forceinline__ unsigned smem_u32(const void* p) {
    return (unsigned)__cvta_generic_to_shared(p);
}
__device__ __forceinline__ void ldsm_x4(unsigned addr, unsigned& r0, unsigned& r1,
                                        unsigned& r2, unsigned& r3) {
    asm volatile("ldmatrix.sync.aligned.m8n8.x4.shared.b16 {%0,%1,%2,%3}, [%4];"
                 : "=r"(r0), "=r"(r1), "=r"(r2), "=r"(r3) : "r"(addr));
}
__device__ __forceinline__ void ldsm_x4t(unsigned addr, unsigned& r0, unsigned& r1,
                                         unsigned& r2, unsigned& r3) {
    asm volatile("ldmatrix.sync.aligned.m8n8.x4.trans.shared.b16 {%0,%1,%2,%3}, [%4];"
                 : "=r"(r0), "=r"(r1), "=r"(r2), "=r"(r3) : "r"(addr));
}
__device__ __forceinline__ void mma_bf16(float* d, const unsigned* a,
                                         unsigned b0, unsigned b1) {
    asm volatile("mma.sync.aligned.m16n8k16.row.col.f32.bf16.bf16.f32 "
                 "{%0,%1,%2,%3}, {%4,%5,%6,%7}, {%8,%9}, {%0,%1,%2,%3};"
                 : "+f"(d[0]), "+f"(d[1]), "+f"(d[2]), "+f"(d[3])
                 : "r"(a[0]), "r"(a[1]), "r"(a[2]), "r"(a[3]), "r"(b0), "r"(b1));
}
__device__ __forceinline__ void split_bf16(float v, __nv_bfloat16& h, __nv_bfloat16& l) {
    h = __float2bfloat16(v);
    l = __float2bfloat16(v - __bfloat162float(h));
}
#define CP_ASYNC16(dst, src) \
    asm volatile("cp.async.cg.shared.global [%0], [%1], 16;" \
                 :: "r"(dst), "l"(src))
#define CP_COMMIT() asm volatile("cp.async.commit_group;")
#define CP_WAIT0()  asm volatile("cp.async.wait_group 0;")

// ---------------- zero BN stats + assign logits -----------------------------
__global__ void zero_scratch_kernel() {
    int i = blockIdx.x * 512 + threadIdx.x;
    if (i < 3 * 2 * HH) d_stats[i] = 0.f;
    int j = i - 3 * 2 * HH;
    if (j >= 0 && j < NN * 2) d_alog[j] = 0.f;
}

// ---------------- BN finalize: stats -> (s, b) --------------------------------
__global__ void bn_finalize_kernel(const float* __restrict__ gamma,
                                   const float* __restrict__ beta, int layer) {
    const int f = threadIdx.x;
    const float* st = d_stats + layer * 2 * HH;
    const float mu  = st[f] * (1.f / NN);
    const float var = st[HH + f] * (1.f / NN) - mu * mu;
    const float s = rsqrtf(var + BN_EPS) * gamma[f];
    d_bnsb[layer * 2 * HH + f] = s;
    d_bnsb[layer * 2 * HH + HH + f] = beta[f] - mu * s;
}

// ---------------- weight prep ----------------------------------------------
__global__ void wsplit_all_kernel(const float* __restrict__ w01,
                                  const float* __restrict__ w02,
                                  const float* __restrict__ wl1,
                                  const float* __restrict__ wl2,
                                  const float* __restrict__ c1w,
                                  __nv_bfloat16* __restrict__ oh,
                                  __nv_bfloat16* __restrict__ ol) {
    int id = blockIdx.x * 256 + threadIdx.x;
    if (id >= WSPLIT_TOTAL) return;
    const float* src;
    if (id < 32768) {
        src = w01 + id;
    } else {
        int r = id - 32768;
        int m = r >> 16, off = r & 65535;
        const float* bases[6] = {w02, wl1, wl2, wl1 + 65536, wl2 + 65536, c1w};
        src = bases[m] + off;
    }
    __nv_bfloat16 h, l;
    split_bf16(*src, h, l);
    oh[id] = h; ol[id] = l;
}

// ---------------- CSR build --------------------------------------------------
__global__ void csr_kernel(const int* __restrict__ src,
                           const int* __restrict__ dst) {
    __shared__ int   ssrc[EPG];
    __shared__ short sdst[EPG];
    __shared__ int   sscan[NPG];
    const int g = blockIdx.x, t = threadIdx.x;
    const int ebase = g * EPG;
    for (int i = t; i < EPG; i += NPG) {
        ssrc[i] = src[ebase + i];
        sdst[i] = (short)(dst[ebase + i] - g * NPG);
    }
    __syncthreads();
    int cnt = 0;
    #pragma unroll 8
    for (int e = 0; e < EPG; ++e) cnt += (sdst[e] == t);
    sscan[t] = cnt;
    __syncthreads();
    for (int off = 1; off < NPG; off <<= 1) {
        int v = (t >= off) ? sscan[t - off] : 0;
        __syncthreads();
        sscan[t] += v;
        __syncthreads();
    }
    int o = ebase + sscan[t] - cnt;
    d_rowstart[g * NPG + t] = o;
    d_deg[g * NPG + t] = cnt;
    for (int e = 0; e < EPG; ++e)
        if (sdst[e] == t) d_csr[o++] = ssrc[e];
}

// -------- gather aggregation (+ optional fused BN affine on input) ---------
template <int F, bool BN>
__global__ void agg_gather(const float* __restrict__ h,
                           float* __restrict__ z, int layer) {
    const int node = blockIdx.x * 8 + (threadIdx.x >> 5);
    const int lane = threadIdx.x & 31;
    const int s = d_rowstart[node];
    const int dg = d_deg[node];
    const int c0 = lane * 4;
    const size_t rb = (size_t)node * F;
    float4 a0 = *reinterpret_cast<const float4*>(&h[rb + c0]);
    float4 a1;
    if (F == 256) a1 = *reinterpret_cast<const float4*>(&h[rb + c0 + 128]);
    for (int e = 0; e < dg; ++e) {
        const size_t sb = (size_t)__ldg(&d_csr[s + e]) * F;
        float4 b0 = *reinterpret_cast<const float4*>(&h[sb + c0]);
        a0.x += b0.x; a0.y += b0.y; a0.z += b0.z; a0.w += b0.w;
        if (F == 256) {
            float4 b1 = *reinterpret_cast<const float4*>(&h[sb + c0 + 128]);
            a1.x += b1.x; a1.y += b1.y; a1.z += b1.z; a1.w += b1.w;
        }
    }
    if (BN) {
        const float* sb = d_bnsb + layer * 2 * HH;
        const float dp1 = (float)(dg + 1);
        float4 sv = *reinterpret_cast<const float4*>(&sb[c0]);
        float4 bv = *reinterpret_cast<const float4*>(&sb[HH + c0]);
        a0.x = sv.x * a0.x + dp1 * bv.x;
        a0.y = sv.y * a0.y + dp1 * bv.y;
        a0.z = sv.z * a0.z + dp1 * bv.z;
        a0.w = sv.w * a0.w + dp1 * bv.w;
        if (F == 256) {
            float4 sv1 = *reinterpret_cast<const float4*>(&sb[c0 + 128]);
            float4 bv1 = *reinterpret_cast<const float4*>(&sb[HH + c0 + 128]);
            a1.x = sv1.x * a1.x + dp1 * bv1.x;
            a1.y = sv1.y * a1.y + dp1 * bv1.y;
            a1.z = sv1.z * a1.z + dp1 * bv1.z;
            a1.w = sv1.w * a1.w + dp1 * bv1.w;
        }
    }
    *reinterpret_cast<float4*>(&z[rb + c0]) = a0;
    if (F == 256) *reinterpret_cast<float4*>(&z[rb + c0 + 128]) = a1;
}

// ------- bf16x3 HMMA GEMM (R9 structure), templated epilogue ---------------
#define LDA 40
#define LDW 136
#define SM_AH  0
#define SM_AL  10240
#define SM_WH  20480
#define SM_WL  29184
#define GEMM_SMEM_BYTES (37888 * 2)

#define GEMM_LOAD_A(it) do {                                                  \
    const int k0 = (it) * 32;                                                 \
    _Pragma("unroll")                                                         \
    for (int i = 0; i < 4; ++i) {                                             \
        int idx = tid + i * 256;                                              \
        int row = idx >> 3;                                                   \
        int c = (idx & 7) * 4;                                                \
        a_reg[i] = *reinterpret_cast<const float4*>(                          \
            &A[(size_t)(rowBase + row) * K + k0 + c]);                        \
        if (ASB) {                                                            \
            float4 sv = *reinterpret_cast<const float4*>(&asb[k0 + c]);       \
            float4 bv = *reinterpret_cast<const float4*>(&asb[HH + k0 + c]);  \
            a_reg[i].x = sv.x * a_reg[i].x + bv.x;                            \
            a_reg[i].y = sv.y * a_reg[i].y + bv.y;                            \
            a_reg[i].z = sv.z * a_reg[i].z + bv.z;                            \
            a_reg[i].w = sv.w * a_reg[i].w + bv.w;                            \
        }                                                                     \
    }                                                                         \
} while (0)

#define GEMM_STORE_A(buf) do {                                                \
    __nv_bfloat16* ah = sm + SM_AH + (buf) * 5120;                            \
    __nv_bfloat16* al = sm + SM_AL + (buf) * 5120;                            \
    _Pragma("unroll")                                                         \
    for (int i = 0; i < 4; ++i) {                                             \
        int idx = tid + i * 256;                                              \
        int row = idx >> 3;                                                   \
        int c = (idx & 7) * 4;                                                \
        float vv[4] = {a_reg[i].x, a_reg[i].y, a_reg[i].z, a_reg[i].w};       \
        unsigned hp[2], lp[2];                                                \
        _Pragma("unroll")                                                     \
        for (int q = 0; q < 2; ++q) {                                         \
            __nv_bfloat16 h0, l0, h1, l1;                                     \
            split_bf16(vv[2 * q], h0, l0);                                    \
            split_bf16(vv[2 * q + 1], h1, l1);                                \
            hp[q] = ((unsigned)*(unsigned short*)&h1 << 16) |                 \
                    *(unsigned short*)&h0;                                    \
            lp[q] = ((unsigned)*(unsigned short*)&l1 << 16) |                 \
                    *(unsigned short*)&l0;                                    \
        }                                                                     \
        *reinterpret_cast<uint2*>(&ah[row * LDA + c]) =                       \
            make_uint2(hp[0], hp[1]);                                         \
        *reinterpret_cast<uint2*>(&al[row * LDA + c]) =                       \
            make_uint2(lp[0], lp[1]);                                         \
    }                                                                         \
} while (0)

#define GEMM_CP_W(it, buf) do {                                               \
    const int k0 = (it) * 32;                                                 \
    __nv_bfloat16* wh = sm + SM_WH + (buf) * 4352;                            \
    __nv_bfloat16* wl = sm + SM_WL + (buf) * 4352;                            \
    _Pragma("unroll")                                                         \
    for (int i = 0; i < 2; ++i) {                                             \
        int idx = tid + i * 256;                                              \
        int row = idx >> 4;                                                   \
        int c8 = (idx & 15) * 8;                                              \
        size_t go = (size_t)(k0 + row) * HH + colBase + c8;                   \
        CP_ASYNC16(smem_u32(&wh[row * LDW + c8]), &Wth[go]);                  \
        CP_ASYNC16(smem_u32(&wl[row * LDW + c8]), &Wtl[go]);                  \
    }                                                                         \
    CP_COMMIT();                                                              \
} while (0)

#define GEMM_MAINLOOP()                                                       \
    GEMM_LOAD_A(0);                                                           \
    GEMM_CP_W(0, 0);                                                          \
    for (int it = 0; it < niter; ++it) {                                      \
        const int buf = it & 1;                                               \
        CP_WAIT0();                                                           \
        GEMM_STORE_A(buf);                                                    \
        __syncthreads();                                                      \
        if (it + 1 < niter) {                                                 \
            GEMM_LOAD_A(it + 1);                                              \
            GEMM_CP_W(it + 1, buf ^ 1);                                       \
        }                                                                     \
        const __nv_bfloat16* ah = sm + SM_AH + buf * 5120;                    \
        const __nv_bfloat16* al = sm + SM_AL + buf * 5120;                    \
        const __nv_bfloat16* wh = sm + SM_WH + buf * 4352;                    \
        const __nv_bfloat16* wl = sm + SM_WL + buf * 4352;                    \
        _Pragma("unroll")                                                     \
        for (int ks = 0; ks < 2; ++ks) {                                      \
            const int kb = ks * 16;                                           \
            unsigned afr[2][2][4];                                            \
            _Pragma("unroll")                                                 \
            for (int mt = 0; mt < 2; ++mt) {                                  \
                int row = warp_m * 32 + mt * 16 + a_row_off;                  \
                int col = kb + a_col_off;                                     \
                ldsm_x4(smem_u32(&ah[row * LDA + col]),                       \
                        afr[0][mt][0], afr[0][mt][1], afr[0][mt][2],          \
                        afr[0][mt][3]);                                       \
                ldsm_x4(smem_u32(&al[row * LDA + col]),                       \
                        afr[1][mt][0], afr[1][mt][1], afr[1][mt][2],          \
                        afr[1][mt][3]);                                       \
            }                                                                 \
            unsigned bfr[4][4];                                               \
            _Pragma("unroll")                                                 \
            for (int p = 0; p < 4; ++p) {                                     \
                int kk = kb + b_k_off;                                        \
                int nn = warp_n * 64 + p * 16 + b_n_off;                      \
                ldsm_x4t(smem_u32(&wh[kk * LDW + nn]),                        \
                         bfr[p][0], bfr[p][1], bfr[p][2], bfr[p][3]);         \
            }                                                                 \
            _Pragma("unroll")                                                 \
            for (int s = 0; s < 2; ++s)                                       \
                _Pragma("unroll")                                             \
                for (int mt = 0; mt < 2; ++mt)                                \
                    _Pragma("unroll")                                         \
                    for (int p = 0; p < 4; ++p) {                             \
                        mma_bf16(acc[mt][2 * p],     afr[s][mt],              \
                                 bfr[p][0], bfr[p][1]);                       \
                        mma_bf16(acc[mt][2 * p + 1], afr[s][mt],              \
                                 bfr[p][2], bfr[p][3]);                       \
                    }                                                         \
            _Pragma("unroll")                                                 \
            for (int p = 0; p < 4; ++p) {                                     \
                int kk = kb + b_k_off;                                        \
                int nn = warp_n * 64 + p * 16 + b_n_off;                      \
                ldsm_x4t(smem_u32(&wl[kk * LDW + nn]),                        \
                         bfr[p][0], bfr[p][1], bfr[p][2], bfr[p][3]);         \
            }                                                                 \
            _Pragma("unroll")                                                 \
            for (int mt = 0; mt < 2; ++mt)                                    \
                _Pragma("unroll")                                             \
                for (int p = 0; p < 4; ++p) {                                 \
                    mma_bf16(acc[mt][2 * p],     afr[0][mt],                  \
                             bfr[p][0], bfr[p][1]);                           \
                    mma_bf16(acc[mt][2 * p + 1], afr[0][mt],                  \
                             bfr[p][2], bfr[p][3]);                           \
                }                                                             \
        }                                                                     \
        __syncthreads();                                                      \
    }

template <bool STATS, bool ASB>
__global__ void __launch_bounds__(256)
gemm_hmma(const float* __restrict__ A,
          const __nv_bfloat16* __restrict__ Wth,
          const __nv_bfloat16* __restrict__ Wtl,
          const float* __restrict__ bias, float* __restrict__ C,
          int K, int act, float* __restrict__ stats,
          const float* __restrict__ asb) {
    extern __shared__ __nv_bfloat16 sm[];
    __shared__ float s_sum[128], s_sq[128];

    const int tid = threadIdx.x;
    const int lane = tid & 31;
    const int wid = tid >> 5;
    const int warp_m = wid & 3;
    const int warp_n = wid >> 2;
    const int rowBase = blockIdx.y * 128;
    const int colBase = blockIdx.x * 128;

    if (STATS && tid < 128) { s_sum[tid] = 0.f; s_sq[tid] = 0.f; }

    float acc[2][8][4] = {};
    float4 a_reg[4];

    const int lg = lane >> 3, lj = lane & 7;
    const int a_row_off = (lg & 1) * 8 + lj;
    const int a_col_off = (lg >> 1) * 8;
    const int b_k_off = (lg & 1) * 8 + lj;
    const int b_n_off = (lg >> 1) * 8;

    const int niter = K >> 5;
    GEMM_MAINLOOP();

    // ---- epilogue: bias + act + store (+ per-column stats) ----
    const int g = lane >> 2, tq = lane & 3;
    float cs[16], cq[16];
    if (STATS) {
        #pragma unroll
        for (int i = 0; i < 16; ++i) { cs[i] = 0.f; cq[i] = 0.f; }
    }
    #pragma unroll
    for (int mt = 0; mt < 2; ++mt) {
        #pragma unroll
        for (int nt = 0; nt < 8; ++nt) {
            int row0 = rowBase + warp_m * 32 + mt * 16 + g;
            int col = colBase + warp_n * 64 + nt * 8 + 2 * tq;
            float b0 = bias[col], b1 = bias[col + 1];
            float v[4] = {acc[mt][nt][0] + b0, acc[mt][nt][1] + b1,
                          acc[mt][nt][2] + b0, acc[mt][nt][3] + b1};
            if (act == 1) {
                #pragma unroll
                for (int q = 0; q < 4; ++q) v[q] = fmaxf(v[q], 0.f);
            }
            if (STATS) {
                cs[nt * 2 + 0] += v[0] + v[2];
                cs[nt * 2 + 1] += v[1] + v[3];
                cq[nt * 2 + 0] += v[0] * v[0] + v[2] * v[2];
                cq[nt * 2 + 1] += v[1] * v[1] + v[3] * v[3];
            }
            *reinterpret_cast<float2*>(&C[(size_t)row0 * HH + col]) =
                make_float2(v[0], v[1]);
            *reinterpret_cast<float2*>(&C[(size_t)(row0 + 8) * HH + col]) =
                make_float2(v[2], v[3]);
        }
    }
    if (STATS) {
        #pragma unroll
        for (int i = 0; i < 16; ++i) {
            #pragma unroll
            for (int off = 16; off >= 4; off >>= 1) {
                cs[i] += __shfl_down_sync(0xffffffffu, cs[i], off);
                cq[i] += __shfl_down_sync(0xffffffffu, cq[i], off);
            }
        }
        if (lane < 4) {
            #pragma unroll
            for (int nt = 0; nt < 8; ++nt) {
                #pragma unroll
                for (int c = 0; c < 2; ++c) {
                    int lc = warp_n * 64 + nt * 8 + 2 * lane + c;
                    atomicAdd(&s_sum[lc], cs[nt * 2 + c]);
                    atomicAdd(&s_sq[lc], cq[nt * 2 + c]);
                }
            }
        }
        __syncthreads();
        int c = tid & 127;
        if (tid < 128) atomicAdd(&stats[colBase + c], s_sum[c]);
        else           atomicAdd(&stats[HH + colBase + c], s_sq[c]);
    }
}

// ------- c1 GEMM: bn2 affine on A, tanh, fused c2 projection -> logits ------
__global__ void __launch_bounds__(256)
gemm_c1(const float* __restrict__ A,
        const __nv_bfloat16* __restrict__ Wth,
        const __nv_bfloat16* __restrict__ Wtl,
        const float* __restrict__ bias,
        int K, const float* __restrict__ asb,
        const float* __restrict__ c2w, float* __restrict__ alog) {
    extern __shared__ __nv_bfloat16 sm[];
    const int tid = threadIdx.x;
    const int lane = tid & 31;
    const int wid = tid >> 5;
    const int warp_m = wid & 3;
    const int warp_n = wid >> 2;
    const int rowBase = blockIdx.y * 128;
    const int colBase = blockIdx.x * 128;
    const bool ASB = true;

    float acc[2][8][4] = {};
    float4 a_reg[4];

    const int lg = lane >> 3, lj = lane & 7;
    const int a_row_off = (lg & 1) * 8 + lj;
    const int a_col_off = (lg >> 1) * 8;
    const int b_k_off = (lg & 1) * 8 + lj;
    const int b_n_off = (lg >> 1) * 8;

    const int niter = K >> 5;
    GEMM_MAINLOOP();

    // ---- epilogue: tanh + c2 projection; no C store ----
    const int g = lane >> 2, tq = lane & 3;
    float p[2][2][2] = {};   // [mt][row half (g vs g+8)][class]
    #pragma unroll
    for (int mt = 0; mt < 2; ++mt) {
        #pragma unroll
        for (int nt = 0; nt < 8; ++nt) {
            int col = colBase + warp_n * 64 + nt * 8 + 2 * tq;
            float b0 = bias[col], b1 = bias[col + 1];
            float v0 = tanhf(acc[mt][nt][0] + b0);
            float v1 = tanhf(acc[mt][nt][1] + b1);
            float v2 = tanhf(acc[mt][nt][2] + b0);
            float v3 = tanhf(acc[mt][nt][3] + b1);
            float w00 = __ldg(&c2w[col * 2 + 0]);
            float w01 = __ldg(&c2w[col * 2 + 1]);
            float w10 = __ldg(&c2w[col * 2 + 2]);
            float w11 = __ldg(&c2w[col * 2 + 3]);
            p[mt][0][0] += v0 * w00 + v1 * w10;
            p[mt][0][1] += v0 * w01 + v1 * w11;
            p[mt][1][0] += v2 * w00 + v3 * w10;
            p[mt][1][1] += v2 * w01 + v3 * w11;
        }
    }
    // reduce over the 4 tq lanes (same row)
    #pragma unroll
    for (int mt = 0; mt < 2; ++mt)
        #pragma unroll
        for (int hh = 0; hh < 2; ++hh)
            #pragma unroll
            for (int c = 0; c < 2; ++c) {
                float v = p[mt][hh][c];
                v += __shfl_xor_sync(0xffffffffu, v, 1);
                v += __shfl_xor_sync(0xffffffffu, v, 2);
                p[mt][hh][c] = v;
            }
    if (tq == 0) {
        #pragma unroll
        for (int mt = 0; mt < 2; ++mt)
            #pragma unroll
            for (int hh = 0; hh < 2; ++hh) {
                int row = rowBase + warp_m * 32 + mt * 16 + g + hh * 8;
                atomicAdd(&alog[row * 2 + 0], p[mt][hh][0]);
                atomicAdd(&alog[row * 2 + 1], p[mt][hh][1]);
            }
    }
}

// ---------------- softmax over fused logits ---------------------------------
__global__ void softmax2_kernel(const float* __restrict__ alog,
                                const float* __restrict__ c2b,
                                float* __restrict__ Aout) {
    const int r = blockIdx.x * 256 + threadIdx.x;
    float s0 = alog[2 * r + 0] + c2b[0];
    float s1 = alog[2 * r + 1] + c2b[1];
    float m = fmaxf(s0, s1);
    float e0 = expf(s0 - m), e1 = expf(s1 - m);
    float inv = 1.f / (e0 + e1);
    Aout[2 * r + 0] = e0 * inv;
    Aout[2 * r + 1] = e1 * inv;
}

// ---------------- pooling (applies layer-2 BN affine on the fly) -----------
__global__ void pool_kernel(const float* __restrict__ Z,
                            const float* __restrict__ Aa,
                            float* __restrict__ sub_out,
                            float* __restrict__ graph_out) {
    __shared__ float sa0[NPG];
    const int g = blockIdx.x, t = threadIdx.x;
    if (t < NPG) sa0[t] = Aa[(g * NPG + t) * 2];
    __syncthreads();
    const float sf = d_bnsb[2 * 2 * HH + t];
    const float bf = d_bnsb[2 * 2 * HH + HH + t];
    float sh = 0.f, ss = 0.f;
    const size_t base = (size_t)g * NPG * HH;
    for (int r = 0; r < NPG; ++r) {
        float hv = sf * Z[base + r * HH + t] + bf;
        sh += hv;
        ss += sa0[r] * hv;
    }
    sub_out[g * HH + t] = ss;
    graph_out[g * HH + t] = sh * (1.f / NPG);
}

// ---------------- pooled adjacency diag penalty -----------------------------
__global__ void adj_kernel(const float* __restrict__ Aa,
                           const int* __restrict__ src,
                           const int* __restrict__ dst) {
    const int g = blockIdx.x, t = threadIdx.x;
    float m00 = 0.f, m01 = 0.f, m10 = 0.f, m11 = 0.f;
    for (int e = t; e < EPG; e += 128) {
        int se = src[g * EPG + e], de = dst[g * EPG + e];
        float a0 = Aa[se * 2], a1 = Aa[se * 2 + 1];
        float b0 = Aa[de * 2], b1 = Aa[de * 2 + 1];
        m00 += a0 * b0; m01 += a0 * b1;
        m10 += a1 * b0; m11 += a1 * b1;
    }
    __shared__ float red[4][128];
    red[0][t] = m00; red[1][t] = m01; red[2][t] = m10; red[3][t] = m11;
    __syncthreads();
    for (int s = 64; s > 0; s >>= 1) {
        if (t < s) {
            red[0][t] += red[0][t + s]; red[1][t] += red[1][t + s];
            red[2][t] += red[2][t + s]; red[3][t] += red[3][t + s];
        }
        __syncthreads();
    }
    if (t == 0) {
        float r0 = fmaxf(fabsf(red[0][0]) + fabsf(red[1][0]), 1e-12f);
        float r1 = fmaxf(fabsf(red[2][0]) + fabsf(red[3][0]), 1e-12f);
        float e0 = red[0][0] / r0 - 1.f;
        float e1 = red[3][0] / r1 - 1.f;
        d_pen[g] = 0.5f * (e0 * e0 + e1 * e1);
    }
}

__global__ void pen_reduce_kernel(float* __restrict__ outp) {
    __shared__ float s[BB];
    s[threadIdx.x] = d_pen[threadIdx.x];
    __syncthreads();
    for (int st = BB / 2; st > 0; st >>= 1) {
        if (threadIdx.x < st) s[threadIdx.x] += s[threadIdx.x + st];
        __syncthreads();
    }
    if (threadIdx.x == 0) outp[0] = s[0] * (1.f / BB);
}

// ---------------- classifier head -------------------------------------------
__global__ void head_kernel(const float* __restrict__ sub,
                            const float* __restrict__ l1w,
                            const float* __restrict__ l1b,
                            const float* __restrict__ l2w,
                            const float* __restrict__ l2b,
                            float* __restrict__ outp) {
    __shared__ float ssub[HH];
    __shared__ float red0[HH], red1[HH];
    const int r = blockIdx.x, t = threadIdx.x;
    ssub[t] = sub[r * HH + t];
    __syncthreads();
    float acc = l1b[t];
    #pragma unroll 8
    for (int k = 0; k < HH; ++k) acc += ssub[k] * l1w[k * HH + t];
    float zc = fmaxf(acc, 0.f);
    red0[t] = zc * l2w[t * 2 + 0];
    red1[t] = zc * l2w[t * 2 + 1];
    __syncthreads();
    for (int s = 128; s > 0; s >>= 1) {
        if (t < s) { red0[t] += red0[t + s]; red1[t] += red1[t + s]; }
        __syncthreads();
    }
    if (t == 0) {
        float s0 = red0[0] + l2b[0], s1 = red1[0] + l2b[1];
        float m = fmaxf(s0, s1);
        float lse = m + logf(expf(s0 - m) + expf(s1 - m));
        outp[r * 2 + 0] = s0 - lse;
        outp[r * 2 + 1] = s1 - lse;
    }
}

// ---------------- launch ------------------------------------------------------
extern "C" void kernel_launch(void* const* d_in, const int* in_sizes, int n_in,
                              void* d_out, int out_size) {
    const float* x    = (const float*)d_in[0];
    const int*   ei   = (const int*)d_in[1];
    const int*   src  = ei;
    const int*   dst  = ei + EE;
    const float* w0_1 = (const float*)d_in[3];
    const float* b0_1 = (const float*)d_in[4];
    const float* w0_2 = (const float*)d_in[5];
    const float* b0_2 = (const float*)d_in[6];
    const float* g0   = (const float*)d_in[7];
    const float* be0  = (const float*)d_in[8];
    const float* wl1  = (const float*)d_in[9];
    const float* bl1  = (const float*)d_in[10];
    const float* wl2  = (const float*)d_in[11];
    const float* bl2  = (const float*)d_in[12];
    const float* gl   = (const float*)d_in[13];
    const float* bel  = (const float*)d_in[14];
    const float* c1w  = (const float*)d_in[15];
    const float* c1b  = (const float*)d_in[16];
    const float* c2w  = (const float*)d_in[17];
    const float* c2b  = (const float*)d_in[18];
    const float* l1w  = (const float*)d_in[19];
    const float* l1b  = (const float*)d_in[20];
    const float* l2w  = (const float*)d_in[21];
    const float* l2b  = (const float*)d_in[22];

    float* out        = (float*)d_out;
    float* out_logits = out;
    float* out_sub    = out + BB * 2;
    float* out_graph  = out + BB * 2 + BB * HH;
    float* out_pen    = out + BB * 2 + 2 * BB * HH;

    float *zb, *tb, *hb, *ab, *alog, *stats, *bnsb;
    cudaGetSymbolAddress((void**)&zb, d_z);
    cudaGetSymbolAddress((void**)&tb, d_t);
    cudaGetSymbolAddress((void**)&hb, d_h);
    cudaGetSymbolAddress((void**)&ab, d_a);
    cudaGetSymbolAddress((void**)&alog, d_alog);
    cudaGetSymbolAddress((void**)&stats, d_stats);
    cudaGetSymbolAddress((void**)&bnsb, d_bnsb);
    __nv_bfloat16 *wth, *wtl;
    cudaGetSymbolAddress((void**)&wth, d_wth);
    cudaGetSymbolAddress((void**)&wtl, d_wtl);

    cudaFuncSetAttribute(gemm_hmma<false, false>,
                         cudaFuncAttributeMaxDynamicSharedMemorySize, GEMM_SMEM_BYTES);
    cudaFuncSetAttribute(gemm_hmma<true, false>,
                         cudaFuncAttributeMaxDynamicSharedMemorySize, GEMM_SMEM_BYTES);
    cudaFuncSetAttribute(gemm_c1,
                         cudaFuncAttributeMaxDynamicSharedMemorySize, GEMM_SMEM_BYTES);

    const int O_W01 = 0;
    const int O_W02 = 32768;
    const int O_L1A = 98304;
    const int O_L2A = 163840;
    const int O_L1B = 229376;
    const int O_L2B = 294912;
    const int O_C1  = 360448;

    const dim3 gemm_grid(HH / 128, NN / 128);
    const int ZERO_TOTAL = 3 * 2 * HH + NN * 2;

    wsplit_all_kernel<<<(WSPLIT_TOTAL + 255) / 256, 256>>>(
        w0_1, w0_2, wl1, wl2, c1w, wth, wtl);                             // 0
    csr_kernel<<<BB, NPG>>>(src, dst);                                    // 1
    agg_gather<FIN, false><<<NN / 8, 256>>>(x, hb, 0);                    // 2
    gemm_hmma<false, false><<<gemm_grid, 256, GEMM_SMEM_BYTES>>>(         // 3 (profiled)
        hb, wth + O_W01, wtl + O_W01, b0_1, tb, FIN, 1, nullptr, nullptr);
    zero_scratch_kernel<<<(ZERO_TOTAL + 511) / 512, 512>>>();             // 4
    gemm_hmma<true, false><<<gemm_grid, 256, GEMM_SMEM_BYTES>>>(          // 5
        tb, wth + O_W02, wtl + O_W02, b0_2, zb, HH, 1, stats, nullptr);
    bn_finalize_kernel<<<1, 256>>>(g0, be0, 0);

    const int offs1[2] = {O_L1A, O_L1B};
    const int offs2[2] = {O_L2A, O_L2B};
    for (int i = 0; i < 2; ++i) {
        agg_gather<HH, true><<<NN / 8, 256>>>(zb, hb, i);
        gemm_hmma<false, false><<<gemm_grid, 256, GEMM_SMEM_BYTES>>>(
            hb, wth + offs1[i], wtl + offs1[i], bl1 + i * HH, tb, HH, 1,
            nullptr, nullptr);
        gemm_hmma<true, false><<<gemm_grid, 256, GEMM_SMEM_BYTES>>>(
            tb, wth + offs2[i], wtl + offs2[i], bl2 + i * HH, zb, HH, 1,
            stats + (1 + i) * 2 * HH, nullptr);
        bn_finalize_kernel<<<1, 256>>>(gl + i * HH, bel + i * HH, 1 + i);
    }

    // ---- assignment: c1 GEMM with fused c2 projection, then softmax ----
    gemm_c1<<<gemm_grid, 256, GEMM_SMEM_BYTES>>>(
        zb, wth + O_C1, wtl + O_C1, c1b, HH, bnsb + 2 * 2 * HH, c2w, alog);
    softmax2_kernel<<<NN / 256, 256>>>(alog, c2b, ab);

    // ---- pooling / penalty / head ----
    pool_kernel<<<BB, 256>>>(zb, ab, out_sub, out_graph);
    adj_kernel<<<BB, 128>>>(ab, src, dst);
    pen_reduce_kernel<<<1, BB>>>(out_pen);
    head_kernel<<<BB, 256>>>(out_sub, l1w, l1b, l2w, l2b, out_logits);
}

// round 13
// speedup vs baseline: 1.1423x; 1.0066x over previous
#include <cuda_runtime.h>
#include <cuda_bf16.h>
#include <math.h>

// Problem constants (fixed by setup_inputs)
#define NN      65536
#define BB      512
#define NPG     128
#define EE      262144
#define EPG     512
#define HH      256
#define FIN     128
#define BN_EPS  1e-5f

// ---------------- scratch (device globals; no cudaMalloc allowed) ----------
__device__ float d_z[NN * HH];
__device__ float d_t[NN * HH];
__device__ float d_h[NN * HH];
__device__ float d_a[NN * 2];
__device__ float d_alog[NN * 2];
__device__ float d_stats[3 * 2 * HH];   // per layer: [sum(256) | sumsq(256)]
__device__ int   d_csr[EE];
__device__ int   d_rowstart[NN];
__device__ int   d_deg[NN];
#define WSPLIT_TOTAL (256 * (128 + 6 * 256))
__device__ __nv_bfloat16 d_wth[WSPLIT_TOTAL];
__device__ __nv_bfloat16 d_wtl[WSPLIT_TOTAL];

// ---------------- helpers ----------------------------------------------------
__device__ __forceinline__ unsigned smem_u32(const void* p) {
    return (unsigned)__cvta_generic_to_shared(p);
}
__device__ __forceinline__ void ldsm_x4(unsigned addr, unsigned& r0, unsigned& r1,
                                        unsigned& r2, unsigned& r3) {
    asm volatile("ldmatrix.sync.aligned.m8n8.x4.shared.b16 {%0,%1,%2,%3}, [%4];"
                 : "=r"(r0), "=r"(r1), "=r"(r2), "=r"(r3) : "r"(addr));
}
__device__ __forceinline__ void ldsm_x4t(unsigned addr, unsigned& r0, unsigned& r1,
                                         unsigned& r2, unsigned& r3) {
    asm volatile("ldmatrix.sync.aligned.m8n8.x4.trans.shared.b16 {%0,%1,%2,%3}, [%4];"
                 : "=r"(r0), "=r"(r1), "=r"(r2), "=r"(r3) : "r"(addr));
}
__device__ __forceinline__ void mma_bf16(float* d, const unsigned* a,
                                         unsigned b0, unsigned b1) {
    asm volatile("mma.sync.aligned.m16n8k16.row.col.f32.bf16.bf16.f32 "
                 "{%0,%1,%2,%3}, {%4,%5,%6,%7}, {%8,%9}, {%0,%1,%2,%3};"
                 : "+f"(d[0]), "+f"(d[1]), "+f"(d[2]), "+f"(d[3])
                 : "r"(a[0]), "r"(a[1]), "r"(a[2]), "r"(a[3]), "r"(b0), "r"(b1));
}
__device__ __forceinline__ void split_bf16(float v, __nv_bfloat16& h, __nv_bfloat16& l) {
    h = __float2bfloat16(v);
    l = __float2bfloat16(v - __bfloat162float(h));
}
// compute BN affine (s, b) for feature f of a layer from raw stats
__device__ __forceinline__ void bn_sb(const float* __restrict__ st,
                                      const float* __restrict__ gamma,
                                      const float* __restrict__ beta,
                                      int f, float& s, float& b) {
    const float inv_n = 1.f / NN;
    float mu  = st[f] * inv_n;
    float var = st[HH + f] * inv_n - mu * mu;
    s = rsqrtf(var + BN_EPS) * gamma[f];
    b = beta[f] - mu * s;
}
#define CP_ASYNC16(dst, src) \
    asm volatile("cp.async.cg.shared.global [%0], [%1], 16;" \
                 :: "r"(dst), "l"(src))
#define CP_COMMIT() asm volatile("cp.async.commit_group;")
#define CP_WAIT0()  asm volatile("cp.async.wait_group 0;")

// ---------------- weight prep + scratch zeroing ------------------------------
__global__ void wsplit_all_kernel(const float* __restrict__ w01,
                                  const float* __restrict__ w02,
                                  const float* __restrict__ wl1,
                                  const float* __restrict__ wl2,
                                  const float* __restrict__ c1w,
                                  __nv_bfloat16* __restrict__ oh,
                                  __nv_bfloat16* __restrict__ ol,
                                  float* __restrict__ out_pen) {
    int id = blockIdx.x * 256 + threadIdx.x;
    if (id == 0) out_pen[0] = 0.f;
    if (id < 3 * 2 * HH) d_stats[id] = 0.f;
    if (id < NN * 2) d_alog[id] = 0.f;
    if (id >= WSPLIT_TOTAL) return;
    const float* src;
    if (id < 32768) {
        src = w01 + id;
    } else {
        int r = id - 32768;
        int m = r >> 16, off = r & 65535;
        const float* bases[6] = {w02, wl1, wl2, wl1 + 65536, wl2 + 65536, c1w};
        src = bases[m] + off;
    }
    __nv_bfloat16 h, l;
    split_bf16(*src, h, l);
    oh[id] = h; ol[id] = l;
}

// ---------------- CSR build (atomic, one block/graph) -----------------------
__global__ void csr_kernel(const int* __restrict__ src,
                           const int* __restrict__ dst) {
    __shared__ int cnt[NPG];
    __shared__ int sscan[NPG];
    __shared__ int pos[NPG];
    const int g = blockIdx.x, t = threadIdx.x;     // 128 threads
    const int ebase = g * EPG;
    cnt[t] = 0;
    __syncthreads();
    int mys[4], myd[4];
    #pragma unroll
    for (int i = 0; i < 4; ++i) {
        int e = ebase + t * 4 + i;
        mys[i] = src[e];
        myd[i] = dst[e] - g * NPG;
        atomicAdd(&cnt[myd[i]], 1);
    }
    __syncthreads();
    int c = cnt[t];
    sscan[t] = c;
    __syncthreads();
    for (int off = 1; off < NPG; off <<= 1) {
        int v = (t >= off) ? sscan[t - off] : 0;
        __syncthreads();
        sscan[t] += v;
        __syncthreads();
    }
    int excl = sscan[t] - c;
    d_rowstart[g * NPG + t] = ebase + excl;
    d_deg[g * NPG + t] = c;
    pos[t] = ebase + excl;
    __syncthreads();
    #pragma unroll
    for (int i = 0; i < 4; ++i) {
        int p = atomicAdd(&pos[myd[i]], 1);
        d_csr[p] = mys[i];
    }
}

// -------- gather aggregation (+ optional inline-BN affine on input) --------
template <int F, bool BN>
__global__ void agg_gather(const float* __restrict__ h,
                           float* __restrict__ z,
                           const float* __restrict__ st,
                           const float* __restrict__ gamma,
                           const float* __restrict__ beta) {
    const int node = blockIdx.x * 8 + (threadIdx.x >> 5);
    const int lane = threadIdx.x & 31;
    const int s = d_rowstart[node];
    const int dg = d_deg[node];
    const int c0 = lane * 4;
    const size_t rb = (size_t)node * F;
    float4 a0 = *reinterpret_cast<const float4*>(&h[rb + c0]);
    float4 a1;
    if (F == 256) a1 = *reinterpret_cast<const float4*>(&h[rb + c0 + 128]);
    for (int e = 0; e < dg; ++e) {
        const size_t sb = (size_t)__ldg(&d_csr[s + e]) * F;
        float4 b0 = *reinterpret_cast<const float4*>(&h[sb + c0]);
        a0.x += b0.x; a0.y += b0.y; a0.z += b0.z; a0.w += b0.w;
        if (F == 256) {
            float4 b1 = *reinterpret_cast<const float4*>(&h[sb + c0 + 128]);
            a1.x += b1.x; a1.y += b1.y; a1.z += b1.z; a1.w += b1.w;
        }
    }
    if (BN) {
        const float dp1 = (float)(dg + 1);
        float sv, bv;
        bn_sb(st, gamma, beta, c0 + 0, sv, bv); a0.x = sv * a0.x + dp1 * bv;
        bn_sb(st, gamma, beta, c0 + 1, sv, bv); a0.y = sv * a0.y + dp1 * bv;
        bn_sb(st, gamma, beta, c0 + 2, sv, bv); a0.z = sv * a0.z + dp1 * bv;
        bn_sb(st, gamma, beta, c0 + 3, sv, bv); a0.w = sv * a0.w + dp1 * bv;
        if (F == 256) {
            bn_sb(st, gamma, beta, c0 + 128, sv, bv); a1.x = sv * a1.x + dp1 * bv;
            bn_sb(st, gamma, beta, c0 + 129, sv, bv); a1.y = sv * a1.y + dp1 * bv;
            bn_sb(st, gamma, beta, c0 + 130, sv, bv); a1.z = sv * a1.z + dp1 * bv;
            bn_sb(st, gamma, beta, c0 + 131, sv, bv); a1.w = sv * a1.w + dp1 * bv;
        }
    }
    *reinterpret_cast<float4*>(&z[rb + c0]) = a0;
    if (F == 256) *reinterpret_cast<float4*>(&z[rb + c0 + 128]) = a1;
}

// ------- bf16x3 HMMA GEMM (R9 structure), templated epilogue ---------------
#define LDA 40
#define LDW 136
#define SM_AH  0
#define SM_AL  10240
#define SM_WH  20480
#define SM_WL  29184
#define GEMM_SMEM_BYTES (37888 * 2)

#define GEMM_LOAD_A(it) do {                                                  \
    const int k0 = (it) * 32;                                                 \
    _Pragma("unroll")                                                         \
    for (int i = 0; i < 4; ++i) {                                             \
        int idx = tid + i * 256;                                              \
        int row = idx >> 3;                                                   \
        int c = (idx & 7) * 4;                                                \
        a_reg[i] = *reinterpret_cast<const float4*>(                          \
            &A[(size_t)(rowBase + row) * K + k0 + c]);                        \
        if (ASB) {                                                            \
            float4 sv = *reinterpret_cast<const float4*>(&asb[k0 + c]);       \
            float4 bv = *reinterpret_cast<const float4*>(&asb[HH + k0 + c]);  \
            a_reg[i].x = sv.x * a_reg[i].x + bv.x;                            \
            a_reg[i].y = sv.y * a_reg[i].y + bv.y;                            \
            a_reg[i].z = sv.z * a_reg[i].z + bv.z;                            \
            a_reg[i].w = sv.w * a_reg[i].w + bv.w;                            \
        }                                                                     \
    }                                                                         \
} while (0)

#define GEMM_STORE_A(buf) do {                                                \
    __nv_bfloat16* ah = sm + SM_AH + (buf) * 5120;                            \
    __nv_bfloat16* al = sm + SM_AL + (buf) * 5120;                            \
    _Pragma("unroll")                                                         \
    for (int i = 0; i < 4; ++i) {                                             \
        int idx = tid + i * 256;                                              \
        int row = idx >> 3;                                                   \
        int c = (idx & 7) * 4;                                                \
        float vv[4] = {a_reg[i].x, a_reg[i].y, a_reg[i].z, a_reg[i].w};       \
        unsigned hp[2], lp[2];                                                \
        _Pragma("unroll")                                                     \
        for (int q = 0; q < 2; ++q) {                                         \
            __nv_bfloat16 h0, l0, h1, l1;                                     \
            split_bf16(vv[2 * q], h0, l0);                                    \
            split_bf16(vv[2 * q + 1], h1, l1);                                \
            hp[q] = ((unsigned)*(unsigned short*)&h1 << 16) |                 \
                    *(unsigned short*)&h0;                                    \
            lp[q] = ((unsigned)*(unsigned short*)&l1 << 16) |                 \
                    *(unsigned short*)&l0;                                    \
        }                                                                     \
        *reinterpret_cast<uint2*>(&ah[row * LDA + c]) =                       \
            make_uint2(hp[0], hp[1]);                                         \
        *reinterpret_cast<uint2*>(&al[row * LDA + c]) =                       \
            make_uint2(lp[0], lp[1]);                                         \
    }                                                                         \
} while (0)

#define GEMM_CP_W(it, buf) do {                                               \
    const int k0 = (it) * 32;                                                 \
    __nv_bfloat16* wh = sm + SM_WH + (buf) * 4352;                            \
    __nv_bfloat16* wl = sm + SM_WL + (buf) * 4352;                            \
    _Pragma("unroll")                                                         \
    for (int i = 0; i < 2; ++i) {                                             \
        int idx = tid + i * 256;                                              \
        int row = idx >> 4;                                                   \
        int c8 = (idx & 15) * 8;                                              \
        size_t go = (size_t)(k0 + row) * HH + colBase + c8;                   \
        CP_ASYNC16(smem_u32(&wh[row * LDW + c8]), &Wth[go]);                  \
        CP_ASYNC16(smem_u32(&wl[row * LDW + c8]), &Wtl[go]);                  \
    }                                                                         \
    CP_COMMIT();                                                              \
} while (0)

#define GEMM_MAINLOOP()                                                       \
    GEMM_LOAD_A(0);                                                           \
    GEMM_CP_W(0, 0);                                                          \
    for (int it = 0; it < niter; ++it) {                                      \
        const int buf = it & 1;                                               \
        CP_WAIT0();                                                           \
        GEMM_STORE_A(buf);                                                    \
        __syncthreads();                                                      \
        if (it + 1 < niter) {                                                 \
            GEMM_LOAD_A(it + 1);                                              \
            GEMM_CP_W(it + 1, buf ^ 1);                                       \
        }                                                                     \
        const __nv_bfloat16* ah = sm + SM_AH + buf * 5120;                    \
        const __nv_bfloat16* al = sm + SM_AL + buf * 5120;                    \
        const __nv_bfloat16* wh = sm + SM_WH + buf * 4352;                    \
        const __nv_bfloat16* wl = sm + SM_WL + buf * 4352;                    \
        _Pragma("unroll")                                                     \
        for (int ks = 0; ks < 2; ++ks) {                                      \
            const int kb = ks * 16;                                           \
            unsigned afr[2][2][4];                                            \
            _Pragma("unroll")                                                 \
            for (int mt = 0; mt < 2; ++mt) {                                  \
                int row = warp_m * 32 + mt * 16 + a_row_off;                  \
                int col = kb + a_col_off;                                     \
                ldsm_x4(smem_u32(&ah[row * LDA + col]),                       \
                        afr[0][mt][0], afr[0][mt][1], afr[0][mt][2],          \
                        afr[0][mt][3]);                                       \
                ldsm_x4(smem_u32(&al[row * LDA + col]),                       \
                        afr[1][mt][0], afr[1][mt][1], afr[1][mt][2],          \
                        afr[1][mt][3]);                                       \
            }                                                                 \
            unsigned bfr[4][4];                                               \
            _Pragma("unroll")                                                 \
            for (int p = 0; p < 4; ++p) {                                     \
                int kk = kb + b_k_off;                                        \
                int nn = warp_n * 64 + p * 16 + b_n_off;                      \
                ldsm_x4t(smem_u32(&wh[kk * LDW + nn]),                        \
                         bfr[p][0], bfr[p][1], bfr[p][2], bfr[p][3]);         \
            }                                                                 \
            _Pragma("unroll")                                                 \
            for (int s = 0; s < 2; ++s)                                       \
                _Pragma("unroll")                                             \
                for (int mt = 0; mt < 2; ++mt)                                \
                    _Pragma("unroll")                                         \
                    for (int p = 0; p < 4; ++p) {                             \
                        mma_bf16(acc[mt][2 * p],     afr[s][mt],              \
                                 bfr[p][0], bfr[p][1]);                       \
                        mma_bf16(acc[mt][2 * p + 1], afr[s][mt],              \
                                 bfr[p][2], bfr[p][3]);                       \
                    }                                                         \
            _Pragma("unroll")                                                 \
            for (int p = 0; p < 4; ++p) {                                     \
                int kk = kb + b_k_off;                                        \
                int nn = warp_n * 64 + p * 16 + b_n_off;                      \
                ldsm_x4t(smem_u32(&wl[kk * LDW + nn]),                        \
                         bfr[p][0], bfr[p][1], bfr[p][2], bfr[p][3]);         \
            }                                                                 \
            _Pragma("unroll")                                                 \
            for (int mt = 0; mt < 2; ++mt)                                    \
                _Pragma("unroll")                                             \
                for (int p = 0; p < 4; ++p) {                                 \
                    mma_bf16(acc[mt][2 * p],     afr[0][mt],                  \
                             bfr[p][0], bfr[p][1]);                           \
                    mma_bf16(acc[mt][2 * p + 1], afr[0][mt],                  \
                             bfr[p][2], bfr[p][3]);                           \
                }                                                             \
        }                                                                     \
        __syncthreads();                                                      \
    }

template <bool STATS>
__global__ void __launch_bounds__(256)
gemm_hmma(const float* __restrict__ A,
          const __nv_bfloat16* __restrict__ Wth,
          const __nv_bfloat16* __restrict__ Wtl,
          const float* __restrict__ bias, float* __restrict__ C,
          int K, float* __restrict__ stats) {
    extern __shared__ __nv_bfloat16 sm[];
    __shared__ float s_sum[128], s_sq[128];

    const int tid = threadIdx.x;
    const int lane = tid & 31;
    const int wid = tid >> 5;
    const int warp_m = wid & 3;
    const int warp_n = wid >> 2;
    const int rowBase = blockIdx.y * 128;
    const int colBase = blockIdx.x * 128;
    const bool ASB = false;
    const float* asb = nullptr;
    (void)asb;

    if (STATS && tid < 128) { s_sum[tid] = 0.f; s_sq[tid] = 0.f; }

    float acc[2][8][4] = {};
    float4 a_reg[4];

    const int lg = lane >> 3, lj = lane & 7;
    const int a_row_off = (lg & 1) * 8 + lj;
    const int a_col_off = (lg >> 1) * 8;
    const int b_k_off = (lg & 1) * 8 + lj;
    const int b_n_off = (lg >> 1) * 8;

    const int niter = K >> 5;
    GEMM_MAINLOOP();

    // ---- epilogue: bias + ReLU + store (+ per-column stats) ----
    const int g = lane >> 2, tq = lane & 3;
    float cs[16], cq[16];
    if (STATS) {
        #pragma unroll
        for (int i = 0; i < 16; ++i) { cs[i] = 0.f; cq[i] = 0.f; }
    }
    #pragma unroll
    for (int mt = 0; mt < 2; ++mt) {
        #pragma unroll
        for (int nt = 0; nt < 8; ++nt) {
            int row0 = rowBase + warp_m * 32 + mt * 16 + g;
            int col = colBase + warp_n * 64 + nt * 8 + 2 * tq;
            float b0 = bias[col], b1 = bias[col + 1];
            float v[4] = {fmaxf(acc[mt][nt][0] + b0, 0.f),
                          fmaxf(acc[mt][nt][1] + b1, 0.f),
                          fmaxf(acc[mt][nt][2] + b0, 0.f),
                          fmaxf(acc[mt][nt][3] + b1, 0.f)};
            if (STATS) {
                cs[nt * 2 + 0] += v[0] + v[2];
                cs[nt * 2 + 1] += v[1] + v[3];
                cq[nt * 2 + 0] += v[0] * v[0] + v[2] * v[2];
                cq[nt * 2 + 1] += v[1] * v[1] + v[3] * v[3];
            }
            *reinterpret_cast<float2*>(&C[(size_t)row0 * HH + col]) =
                make_float2(v[0], v[1]);
            *reinterpret_cast<float2*>(&C[(size_t)(row0 + 8) * HH + col]) =
                make_float2(v[2], v[3]);
        }
    }
    if (STATS) {
        #pragma unroll
        for (int i = 0; i < 16; ++i) {
            #pragma unroll
            for (int off = 16; off >= 4; off >>= 1) {
                cs[i] += __shfl_down_sync(0xffffffffu, cs[i], off);
                cq[i] += __shfl_down_sync(0xffffffffu, cq[i], off);
            }
        }
        if (lane < 4) {
            #pragma unroll
            for (int nt = 0; nt < 8; ++nt) {
                #pragma unroll
                for (int c = 0; c < 2; ++c) {
                    int lc = warp_n * 64 + nt * 8 + 2 * lane + c;
                    atomicAdd(&s_sum[lc], cs[nt * 2 + c]);
                    atomicAdd(&s_sq[lc], cq[nt * 2 + c]);
                }
            }
        }
        __syncthreads();
        int c = tid & 127;
        if (tid < 128) atomicAdd(&stats[colBase + c], s_sum[c]);
        else           atomicAdd(&stats[HH + colBase + c], s_sq[c]);
    }
}

// ------- c1 GEMM: inline bn2 affine on A, tanh, fused c2 proj -> logits -----
__global__ void __launch_bounds__(256)
gemm_c1(const float* __restrict__ A,
        const __nv_bfloat16* __restrict__ Wth,
        const __nv_bfloat16* __restrict__ Wtl,
        const float* __restrict__ bias,
        int K,
        const float* __restrict__ st2,
        const float* __restrict__ gamma2,
        const float* __restrict__ beta2,
        const float* __restrict__ c2w, float* __restrict__ alog) {
    extern __shared__ __nv_bfloat16 sm[];
    __shared__ float s_asb[2 * HH];
    const int tid = threadIdx.x;
    const int lane = tid & 31;
    const int wid = tid >> 5;
    const int warp_m = wid & 3;
    const int warp_n = wid >> 2;
    const int rowBase = blockIdx.y * 128;
    const int colBase = blockIdx.x * 128;
    const bool ASB = true;

    // stage BN layer-2 affine into smem
    {
        float sv, bv;
        bn_sb(st2, gamma2, beta2, tid, sv, bv);
        s_asb[tid] = sv;
        s_asb[HH + tid] = bv;
    }
    __syncthreads();
    const float* asb = s_asb;

    float acc[2][8][4] = {};
    float4 a_reg[4];

    const int lg = lane >> 3, lj = lane & 7;
    const int a_row_off = (lg & 1) * 8 + lj;
    const int a_col_off = (lg >> 1) * 8;
    const int b_k_off = (lg & 1) * 8 + lj;
    const int b_n_off = (lg >> 1) * 8;

    const int niter = K >> 5;
    GEMM_MAINLOOP();

    // ---- epilogue: tanh + c2 projection; no C store ----
    const int g = lane >> 2, tq = lane & 3;
    float p[2][2][2] = {};
    #pragma unroll
    for (int mt = 0; mt < 2; ++mt) {
        #pragma unroll
        for (int nt = 0; nt < 8; ++nt) {
            int col = colBase + warp_n * 64 + nt * 8 + 2 * tq;
            float b0 = bias[col], b1 = bias[col + 1];
            float v0 = tanhf(acc[mt][nt][0] + b0);
            float v1 = tanhf(acc[mt][nt][1] + b1);
            float v2 = tanhf(acc[mt][nt][2] + b0);
            float v3 = tanhf(acc[mt][nt][3] + b1);
            float w00 = __ldg(&c2w[col * 2 + 0]);
            float w01 = __ldg(&c2w[col * 2 + 1]);
            float w10 = __ldg(&c2w[col * 2 + 2]);
            float w11 = __ldg(&c2w[col * 2 + 3]);
            p[mt][0][0] += v0 * w00 + v1 * w10;
            p[mt][0][1] += v0 * w01 + v1 * w11;
            p[mt][1][0] += v2 * w00 + v3 * w10;
            p[mt][1][1] += v2 * w01 + v3 * w11;
        }
    }
    #pragma unroll
    for (int mt = 0; mt < 2; ++mt)
        #pragma unroll
        for (int hh = 0; hh < 2; ++hh)
            #pragma unroll
            for (int c = 0; c < 2; ++c) {
                float v = p[mt][hh][c];
                v += __shfl_xor_sync(0xffffffffu, v, 1);
                v += __shfl_xor_sync(0xffffffffu, v, 2);
                p[mt][hh][c] = v;
            }
    if (tq == 0) {
        #pragma unroll
        for (int mt = 0; mt < 2; ++mt)
            #pragma unroll
            for (int hh = 0; hh < 2; ++hh) {
                int row = rowBase + warp_m * 32 + mt * 16 + g + hh * 8;
                atomicAdd(&alog[row * 2 + 0], p[mt][hh][0]);
                atomicAdd(&alog[row * 2 + 1], p[mt][hh][1]);
            }
    }
}

// ---------------- softmax over fused logits ---------------------------------
__global__ void softmax2_kernel(const float* __restrict__ alog,
                                const float* __restrict__ c2b,
                                float* __restrict__ Aout) {
    const int r = blockIdx.x * 256 + threadIdx.x;
    float s0 = alog[2 * r + 0] + c2b[0];
    float s1 = alog[2 * r + 1] + c2b[1];
    float m = fmaxf(s0, s1);
    float e0 = expf(s0 - m), e1 = expf(s1 - m);
    float inv = 1.f / (e0 + e1);
    Aout[2 * r + 0] = e0 * inv;
    Aout[2 * r + 1] = e1 * inv;
}

// -------- pooling + classifier head fused (block per graph) -----------------
__global__ void pool_head_kernel(const float* __restrict__ Z,
                                 const float* __restrict__ Aa,
                                 const float* __restrict__ st2,
                                 const float* __restrict__ gamma2,
                                 const float* __restrict__ beta2,
                                 const float* __restrict__ l1w,
                                 const float* __restrict__ l1b,
                                 const float* __restrict__ l2w,
                                 const float* __restrict__ l2b,
                                 float* __restrict__ sub_out,
                                 float* __restrict__ graph_out,
                                 float* __restrict__ logits_out) {
    __shared__ float sa0[NPG];
    __shared__ float ssub[HH];
    __shared__ float red0[HH], red1[HH];
    const int g = blockIdx.x, t = threadIdx.x;   // 256 threads
    if (t < NPG) sa0[t] = Aa[(g * NPG + t) * 2];
    float sf, bf;
    bn_sb(st2, gamma2, beta2, t, sf, bf);
    __syncthreads();
    float sh = 0.f, ss = 0.f;
    const size_t base = (size_t)g * NPG * HH;
    for (int r = 0; r < NPG; ++r) {
        float hv = sf * Z[base + r * HH + t] + bf;
        sh += hv;
        ss += sa0[r] * hv;
    }
    sub_out[g * HH + t] = ss;
    graph_out[g * HH + t] = sh * (1.f / NPG);
    ssub[t] = ss;
    __syncthreads();
    // head: z = relu(sub @ l1w + l1b); logits = log_softmax(z @ l2w + l2b)
    float acc = l1b[t];
    #pragma unroll 8
    for (int k = 0; k < HH; ++k) acc += ssub[k] * l1w[k * HH + t];
    float zc = fmaxf(acc, 0.f);
    red0[t] = zc * l2w[t * 2 + 0];
    red1[t] = zc * l2w[t * 2 + 1];
    __syncthreads();
    for (int s = 128; s > 0; s >>= 1) {
        if (t < s) { red0[t] += red0[t + s]; red1[t] += red1[t + s]; }
        __syncthreads();
    }
    if (t == 0) {
        float s0 = red0[0] + l2b[0], s1 = red1[0] + l2b[1];
        float m = fmaxf(s0, s1);
        float lse = m + logf(expf(s0 - m) + expf(s1 - m));
        logits_out[g * 2 + 0] = s0 - lse;
        logits_out[g * 2 + 1] = s1 - lse;
    }
}

// -------- pooled adjacency diag penalty + mean (block per graph) ------------
__global__ void adj_pen_kernel(const float* __restrict__ Aa,
                               const int* __restrict__ src,
                               const int* __restrict__ dst,
                               float* __restrict__ out_pen) {
    const int g = blockIdx.x, t = threadIdx.x;   // 128 threads
    float m00 = 0.f, m01 = 0.f, m10 = 0.f, m11 = 0.f;
    for (int e = t; e < EPG; e += 128) {
        int se = src[g * EPG + e], de = dst[g * EPG + e];
        float a0 = Aa[se * 2], a1 = Aa[se * 2 + 1];
        float b0 = Aa[de * 2], b1 = Aa[de * 2 + 1];
        m00 += a0 * b0; m01 += a0 * b1;
        m10 += a1 * b0; m11 += a1 * b1;
    }
    __shared__ float red[4][128];
    red[0][t] = m00; red[1][t] = m01; red[2][t] = m10; red[3][t] = m11;
    __syncthreads();
    for (int s = 64; s > 0; s >>= 1) {
        if (t < s) {
            red[0][t] += red[0][t + s]; red[1][t] += red[1][t + s];
            red[2][t] += red[2][t + s]; red[3][t] += red[3][t + s];
        }
        __syncthreads();
    }
    if (t == 0) {
        float r0 = fmaxf(fabsf(red[0][0]) + fabsf(red[1][0]), 1e-12f);
        float r1 = fmaxf(fabsf(red[2][0]) + fabsf(red[3][0]), 1e-12f);
        float e0 = red[0][0] / r0 - 1.f;
        float e1 = red[3][0] / r1 - 1.f;
        atomicAdd(out_pen, 0.5f * (e0 * e0 + e1 * e1) * (1.f / BB));
    }
}

// ---------------- launch ------------------------------------------------------
extern "C" void kernel_launch(void* const* d_in, const int* in_sizes, int n_in,
                              void* d_out, int out_size) {
    const float* x    = (const float*)d_in[0];
    const int*   ei   = (const int*)d_in[1];
    const int*   src  = ei;
    const int*   dst  = ei + EE;
    const float* w0_1 = (const float*)d_in[3];
    const float* b0_1 = (const float*)d_in[4];
    const float* w0_2 = (const float*)d_in[5];
    const float* b0_2 = (const float*)d_in[6];
    const float* g0   = (const float*)d_in[7];
    const float* be0  = (const float*)d_in[8];
    const float* wl1  = (const float*)d_in[9];
    const float* bl1  = (const float*)d_in[10];
    const float* wl2  = (const float*)d_in[11];
    const float* bl2  = (const float*)d_in[12];
    const float* gl   = (const float*)d_in[13];
    const float* bel  = (const float*)d_in[14];
    const float* c1w  = (const float*)d_in[15];
    const float* c1b  = (const float*)d_in[16];
    const float* c2w  = (const float*)d_in[17];
    const float* c2b  = (const float*)d_in[18];
    const float* l1w  = (const float*)d_in[19];
    const float* l1b  = (const float*)d_in[20];
    const float* l2w  = (const float*)d_in[21];
    const float* l2b  = (const float*)d_in[22];

    float* out        = (float*)d_out;
    float* out_logits = out;
    float* out_sub    = out + BB * 2;
    float* out_graph  = out + BB * 2 + BB * HH;
    float* out_pen    = out + BB * 2 + 2 * BB * HH;

    float *zb, *tb, *hb, *ab, *alog, *stats;
    cudaGetSymbolAddress((void**)&zb, d_z);
    cudaGetSymbolAddress((void**)&tb, d_t);
    cudaGetSymbolAddress((void**)&hb, d_h);
    cudaGetSymbolAddress((void**)&ab, d_a);
    cudaGetSymbolAddress((void**)&alog, d_alog);
    cudaGetSymbolAddress((void**)&stats, d_stats);
    __nv_bfloat16 *wth, *wtl;
    cudaGetSymbolAddress((void**)&wth, d_wth);
    cudaGetSymbolAddress((void**)&wtl, d_wtl);

    cudaFuncSetAttribute(gemm_hmma<false>,
                         cudaFuncAttributeMaxDynamicSharedMemorySize, GEMM_SMEM_BYTES);
    cudaFuncSetAttribute(gemm_hmma<true>,
                         cudaFuncAttributeMaxDynamicSharedMemorySize, GEMM_SMEM_BYTES);
    cudaFuncSetAttribute(gemm_c1,
                         cudaFuncAttributeMaxDynamicSharedMemorySize, GEMM_SMEM_BYTES);

    const int O_W01 = 0;
    const int O_W02 = 32768;
    const int O_L1A = 98304;
    const int O_L2A = 163840;
    const int O_L1B = 229376;
    const int O_L2B = 294912;
    const int O_C1  = 360448;

    const dim3 gemm_grid(HH / 128, NN / 128);

    wsplit_all_kernel<<<(WSPLIT_TOTAL + 255) / 256, 256>>>(
        w0_1, w0_2, wl1, wl2, c1w, wth, wtl, out_pen);                    // 0
    csr_kernel<<<BB, NPG>>>(src, dst);                                    // 1
    agg_gather<FIN, false><<<NN / 8, 256>>>(x, hb, nullptr, nullptr, nullptr); // 2
    gemm_hmma<false><<<gemm_grid, 256, GEMM_SMEM_BYTES>>>(                // 3 (profiled)
        hb, wth + O_W01, wtl + O_W01, b0_1, tb, FIN, nullptr);
    gemm_hmma<true><<<gemm_grid, 256, GEMM_SMEM_BYTES>>>(                 // 4
        tb, wth + O_W02, wtl + O_W02, b0_2, zb, HH, stats);

    const int offs1[2] = {O_L1A, O_L1B};
    const int offs2[2] = {O_L2A, O_L2B};
    const float* gammas[2] = {g0, gl};
    const float* betas[2]  = {be0, bel};
    for (int i = 0; i < 2; ++i) {
        agg_gather<HH, true><<<NN / 8, 256>>>(zb, hb, stats + i * 2 * HH,
                                              gammas[i], betas[i]);
        gemm_hmma<false><<<gemm_grid, 256, GEMM_SMEM_BYTES>>>(
            hb, wth + offs1[i], wtl + offs1[i], bl1 + i * HH, tb, HH, nullptr);
        gemm_hmma<true><<<gemm_grid, 256, GEMM_SMEM_BYTES>>>(
            tb, wth + offs2[i], wtl + offs2[i], bl2 + i * HH, zb, HH,
            stats + (1 + i) * 2 * HH);
    }

    // ---- assignment: c1 GEMM (inline BN2 affine) + fused c2 proj ----
    gemm_c1<<<gemm_grid, 256, GEMM_SMEM_BYTES>>>(
        zb, wth + O_C1, wtl + O_C1, c1b, HH,
        stats + 2 * 2 * HH, gl + HH, bel + HH, c2w, alog);
    softmax2_kernel<<<NN / 256, 256>>>(alog, c2b, ab);

    // ---- pooling+head / adjacency penalty ----
    pool_head_kernel<<<BB, 256>>>(zb, ab, stats + 2 * 2 * HH, gl + HH, bel + HH,
                                  l1w, l1b, l2w, l2b,
                                  out_sub, out_graph, out_logits);
    adj_pen_kernel<<<BB, 128>>>(ab, src, dst, out_pen);
}

// round 14
// speedup vs baseline: 1.1601x; 1.0156x over previous
#include <cuda_runtime.h>
#include <cuda_bf16.h>
#include <math.h>

// Problem constants (fixed by setup_inputs)
#define NN      65536
#define BB      512
#define NPG     128
#define EE      262144
#define EPG     512
#define HH      256
#define FIN     128
#define BN_EPS  1e-5f

// ---------------- scratch (device globals; no cudaMalloc allowed) ----------
__device__ float d_z[NN * HH];
__device__ float d_t[NN * HH];
__device__ float d_h[NN * HH];
__device__ float d_a[NN * 2];
__device__ float d_alog[NN * 2];
__device__ float d_stats[3 * 2 * HH];   // per layer: [sum(256) | sumsq(256)]
__device__ int   d_csr[EE];
__device__ int   d_rowstart[NN];
__device__ int   d_deg[NN];
#define WSPLIT_TOTAL (256 * (128 + 6 * 256))
__device__ __nv_bfloat16 d_wth[WSPLIT_TOTAL];
__device__ __nv_bfloat16 d_wtl[WSPLIT_TOTAL];

// ---------------- helpers ----------------------------------------------------
__device__ __forceinline__ unsigned smem_u32(const void* p) {
    return (unsigned)__cvta_generic_to_shared(p);
}
__device__ __forceinline__ void ldsm_x4(unsigned addr, unsigned& r0, unsigned& r1,
                                        unsigned& r2, unsigned& r3) {
    asm volatile("ldmatrix.sync.aligned.m8n8.x4.shared.b16 {%0,%1,%2,%3}, [%4];"
                 : "=r"(r0), "=r"(r1), "=r"(r2), "=r"(r3) : "r"(addr));
}
__device__ __forceinline__ void ldsm_x4t(unsigned addr, unsigned& r0, unsigned& r1,
                                         unsigned& r2, unsigned& r3) {
    asm volatile("ldmatrix.sync.aligned.m8n8.x4.trans.shared.b16 {%0,%1,%2,%3}, [%4];"
                 : "=r"(r0), "=r"(r1), "=r"(r2), "=r"(r3) : "r"(addr));
}
__device__ __forceinline__ void mma_bf16(float* d, const unsigned* a,
                                         unsigned b0, unsigned b1) {
    asm volatile("mma.sync.aligned.m16n8k16.row.col.f32.bf16.bf16.f32 "
                 "{%0,%1,%2,%3}, {%4,%5,%6,%7}, {%8,%9}, {%0,%1,%2,%3};"
                 : "+f"(d[0]), "+f"(d[1]), "+f"(d[2]), "+f"(d[3])
                 : "r"(a[0]), "r"(a[1]), "r"(a[2]), "r"(a[3]), "r"(b0), "r"(b1));
}
__device__ __forceinline__ void split_bf16(float v, __nv_bfloat16& h, __nv_bfloat16& l) {
    h = __float2bfloat16(v);
    l = __float2bfloat16(v - __bfloat162float(h));
}
// compute BN affine (s, b) for feature f of a layer from raw stats
__device__ __forceinline__ void bn_sb(const float* __restrict__ st,
                                      const float* __restrict__ gamma,
                                      const float* __restrict__ beta,
                                      int f, float& s, float& b) {
    const float inv_n = 1.f / NN;
    float mu  = st[f] * inv_n;
    float var = st[HH + f] * inv_n - mu * mu;
    s = rsqrtf(var + BN_EPS) * gamma[f];
    b = beta[f] - mu * s;
}
#define CP_ASYNC16(dst, src) \
    asm volatile("cp.async.cg.shared.global [%0], [%1], 16;" \
                 :: "r"(dst), "l"(src))
#define CP_COMMIT() asm volatile("cp.async.commit_group;")
#define CP_WAIT0()  asm volatile("cp.async.wait_group 0;")

// ---------------- weight prep + scratch zeroing ------------------------------
__global__ void wsplit_all_kernel(const float* __restrict__ w01,
                                  const float* __restrict__ w02,
                                  const float* __restrict__ wl1,
                                  const float* __restrict__ wl2,
                                  const float* __restrict__ c1w,
                                  __nv_bfloat16* __restrict__ oh,
                                  __nv_bfloat16* __restrict__ ol,
                                  float* __restrict__ out_pen) {
    int id = blockIdx.x * 256 + threadIdx.x;
    if (id == 0) out_pen[0] = 0.f;
    if (id < 3 * 2 * HH) d_stats[id] = 0.f;
    if (id < NN * 2) d_alog[id] = 0.f;
    if (id >= WSPLIT_TOTAL) return;
    const float* src;
    if (id < 32768) {
        src = w01 + id;
    } else {
        int r = id - 32768;
        int m = r >> 16, off = r & 65535;
        const float* bases[6] = {w02, wl1, wl2, wl1 + 65536, wl2 + 65536, c1w};
        src = bases[m] + off;
    }
    __nv_bfloat16 h, l;
    split_bf16(*src, h, l);
    oh[id] = h; ol[id] = l;
}

// ---------------- CSR build (atomic, one block/graph) -----------------------
__global__ void csr_kernel(const int* __restrict__ src,
                           const int* __restrict__ dst) {
    __shared__ int cnt[NPG];
    __shared__ int sscan[NPG];
    __shared__ int pos[NPG];
    const int g = blockIdx.x, t = threadIdx.x;     // 128 threads
    const int ebase = g * EPG;
    cnt[t] = 0;
    __syncthreads();
    int mys[4], myd[4];
    #pragma unroll
    for (int i = 0; i < 4; ++i) {
        int e = ebase + t * 4 + i;
        mys[i] = src[e];
        myd[i] = dst[e] - g * NPG;
        atomicAdd(&cnt[myd[i]], 1);
    }
    __syncthreads();
    int c = cnt[t];
    sscan[t] = c;
    __syncthreads();
    for (int off = 1; off < NPG; off <<= 1) {
        int v = (t >= off) ? sscan[t - off] : 0;
        __syncthreads();
        sscan[t] += v;
        __syncthreads();
    }
    int excl = sscan[t] - c;
    d_rowstart[g * NPG + t] = ebase + excl;
    d_deg[g * NPG + t] = c;
    pos[t] = ebase + excl;
    __syncthreads();
    #pragma unroll
    for (int i = 0; i < 4; ++i) {
        int p = atomicAdd(&pos[myd[i]], 1);
        d_csr[p] = mys[i];
    }
}

// -------- gather aggregation (+ optional inline-BN affine on input) --------
template <int F, bool BN>
__global__ void agg_gather(const float* __restrict__ h,
                           float* __restrict__ z,
                           const float* __restrict__ st,
                           const float* __restrict__ gamma,
                           const float* __restrict__ beta) {
    const int node = blockIdx.x * 8 + (threadIdx.x >> 5);
    const int lane = threadIdx.x & 31;
    const int s = d_rowstart[node];
    const int dg = d_deg[node];
    const int c0 = lane * 4;
    const size_t rb = (size_t)node * F;
    float4 a0 = *reinterpret_cast<const float4*>(&h[rb + c0]);
    float4 a1;
    if (F == 256) a1 = *reinterpret_cast<const float4*>(&h[rb + c0 + 128]);
    for (int e = 0; e < dg; ++e) {
        const size_t sb = (size_t)__ldg(&d_csr[s + e]) * F;
        float4 b0 = *reinterpret_cast<const float4*>(&h[sb + c0]);
        a0.x += b0.x; a0.y += b0.y; a0.z += b0.z; a0.w += b0.w;
        if (F == 256) {
            float4 b1 = *reinterpret_cast<const float4*>(&h[sb + c0 + 128]);
            a1.x += b1.x; a1.y += b1.y; a1.z += b1.z; a1.w += b1.w;
        }
    }
    if (BN) {
        const float dp1 = (float)(dg + 1);
        float sv, bv;
        bn_sb(st, gamma, beta, c0 + 0, sv, bv); a0.x = sv * a0.x + dp1 * bv;
        bn_sb(st, gamma, beta, c0 + 1, sv, bv); a0.y = sv * a0.y + dp1 * bv;
        bn_sb(st, gamma, beta, c0 + 2, sv, bv); a0.z = sv * a0.z + dp1 * bv;
        bn_sb(st, gamma, beta, c0 + 3, sv, bv); a0.w = sv * a0.w + dp1 * bv;
        if (F == 256) {
            bn_sb(st, gamma, beta, c0 + 128, sv, bv); a1.x = sv * a1.x + dp1 * bv;
            bn_sb(st, gamma, beta, c0 + 129, sv, bv); a1.y = sv * a1.y + dp1 * bv;
            bn_sb(st, gamma, beta, c0 + 130, sv, bv); a1.z = sv * a1.z + dp1 * bv;
            bn_sb(st, gamma, beta, c0 + 131, sv, bv); a1.w = sv * a1.w + dp1 * bv;
        }
    }
    *reinterpret_cast<float4*>(&z[rb + c0]) = a0;
    if (F == 256) *reinterpret_cast<float4*>(&z[rb + c0 + 128]) = a1;
}

// ------- bf16x3 HMMA GEMM (single mid-loop barrier schedule) ----------------
#define LDA 40
#define LDW 136
#define SM_AH  0
#define SM_AL  10240
#define SM_WH  20480
#define SM_WL  29184
#define GEMM_SMEM_BYTES (37888 * 2)

#define GEMM_LOAD_A(it) do {                                                  \
    const int k0 = (it) * 32;                                                 \
    _Pragma("unroll")                                                         \
    for (int i = 0; i < 4; ++i) {                                             \
        int idx = tid + i * 256;                                              \
        int row = idx >> 3;                                                   \
        int c = (idx & 7) * 4;                                                \
        a_reg[i] = *reinterpret_cast<const float4*>(                          \
            &A[(size_t)(rowBase + row) * K + k0 + c]);                        \
        if (ASB) {                                                            \
            float4 sv = *reinterpret_cast<const float4*>(&asb[k0 + c]);       \
            float4 bv = *reinterpret_cast<const float4*>(&asb[HH + k0 + c]);  \
            a_reg[i].x = sv.x * a_reg[i].x + bv.x;                            \
            a_reg[i].y = sv.y * a_reg[i].y + bv.y;                            \
            a_reg[i].z = sv.z * a_reg[i].z + bv.z;                            \
            a_reg[i].w = sv.w * a_reg[i].w + bv.w;                            \
        }                                                                     \
    }                                                                         \
} while (0)

#define GEMM_STORE_A(buf) do {                                                \
    __nv_bfloat16* ah = sm + SM_AH + (buf) * 5120;                            \
    __nv_bfloat16* al = sm + SM_AL + (buf) * 5120;                            \
    _Pragma("unroll")                                                         \
    for (int i = 0; i < 4; ++i) {                                             \
        int idx = tid + i * 256;                                              \
        int row = idx >> 3;                                                   \
        int c = (idx & 7) * 4;                                                \
        float vv[4] = {a_reg[i].x, a_reg[i].y, a_reg[i].z, a_reg[i].w};       \
        unsigned hp[2], lp[2];                                                \
        _Pragma("unroll")                                                     \
        for (int q = 0; q < 2; ++q) {                                         \
            __nv_bfloat16 h0, l0, h1, l1;                                     \
            split_bf16(vv[2 * q], h0, l0);                                    \
            split_bf16(vv[2 * q + 1], h1, l1);                                \
            hp[q] = ((unsigned)*(unsigned short*)&h1 << 16) |                 \
                    *(unsigned short*)&h0;                                    \
            lp[q] = ((unsigned)*(unsigned short*)&l1 << 16) |                 \
                    *(unsigned short*)&l0;                                    \
        }                                                                     \
        *reinterpret_cast<uint2*>(&ah[row * LDA + c]) =                       \
            make_uint2(hp[0], hp[1]);                                         \
        *reinterpret_cast<uint2*>(&al[row * LDA + c]) =                       \
            make_uint2(lp[0], lp[1]);                                         \
    }                                                                         \
} while (0)

#define GEMM_CP_W(it, buf) do {                                               \
    const int k0 = (it) * 32;                                                 \
    __nv_bfloat16* wh = sm + SM_WH + (buf) * 4352;                            \
    __nv_bfloat16* wl = sm + SM_WL + (buf) * 4352;                            \
    _Pragma("unroll")                                                         \
    for (int i = 0; i < 2; ++i) {                                             \
        int idx = tid + i * 256;                                              \
        int row = idx >> 4;                                                   \
        int c8 = (idx & 15) * 8;                                              \
        size_t go = (size_t)(k0 + row) * HH + colBase + c8;                   \
        CP_ASYNC16(smem_u32(&wh[row * LDW + c8]), &Wth[go]);                  \
        CP_ASYNC16(smem_u32(&wl[row * LDW + c8]), &Wtl[go]);                  \
    }                                                                         \
    CP_COMMIT();                                                              \
} while (0)

// One __syncthreads per K-iter. Safety: STORE_A(it) writes buf(it), last read
// at compute(it-2), ordered by mid-sync(it-1) (every warp's compute(it-2)
// precedes its arrival there). CP_W(it+1) writes W-buf(it+1), last read at
// compute(it-1), ordered by mid-sync(it). STORE_A/LOAD_A precede CP_WAIT0
// (no dependence on cp.async), hiding the A split under the W-copy drain.
#define GEMM_MAINLOOP()                                                       \
    GEMM_LOAD_A(0);                                                           \
    GEMM_CP_W(0, 0);                                                          \
    for (int it = 0; it < niter; ++it) {                                      \
        const int buf = it & 1;                                               \
        GEMM_STORE_A(buf);                                                    \
        if (it + 1 < niter) GEMM_LOAD_A(it + 1);                              \
        CP_WAIT0();                                                           \
        __syncthreads();                                                      \
        if (it + 1 < niter) GEMM_CP_W(it + 1, buf ^ 1);                       \
        const __nv_bfloat16* ah = sm + SM_AH + buf * 5120;                    \
        const __nv_bfloat16* al = sm + SM_AL + buf * 5120;                    \
        const __nv_bfloat16* wh = sm + SM_WH + buf * 4352;                    \
        const __nv_bfloat16* wl = sm + SM_WL + buf * 4352;                    \
        _Pragma("unroll")                                                     \
        for (int ks = 0; ks < 2; ++ks) {                                      \
            const int kb = ks * 16;                                           \
            unsigned afr[2][2][4];                                            \
            _Pragma("unroll")                                                 \
            for (int mt = 0; mt < 2; ++mt) {                                  \
                int row = warp_m * 32 + mt * 16 + a_row_off;                  \
                int col = kb + a_col_off;                                     \
                ldsm_x4(smem_u32(&ah[row * LDA + col]),                       \
                        afr[0][mt][0], afr[0][mt][1], afr[0][mt][2],          \
                        afr[0][mt][3]);                                       \
                ldsm_x4(smem_u32(&al[row * LDA + col]),                       \
                        afr[1][mt][0], afr[1][mt][1], afr[1][mt][2],          \
                        afr[1][mt][3]);                                       \
            }                                                                 \
            unsigned bfr[4][4];                                               \
            _Pragma("unroll")                                                 \
            for (int p = 0; p < 4; ++p) {                                     \
                int kk = kb + b_k_off;                                        \
                int nn = warp_n * 64 + p * 16 + b_n_off;                      \
                ldsm_x4t(smem_u32(&wh[kk * LDW + nn]),                        \
                         bfr[p][0], bfr[p][1], bfr[p][2], bfr[p][3]);         \
            }                                                                 \
            _Pragma("unroll")                                                 \
            for (int s = 0; s < 2; ++s)                                       \
                _Pragma("unroll")                                             \
                for (int mt = 0; mt < 2; ++mt)                                \
                    _Pragma("unroll")                                         \
                    for (int p = 0; p < 4; ++p) {                             \
                        mma_bf16(acc[mt][2 * p],     afr[s][mt],              \
                                 bfr[p][0], bfr[p][1]);                       \
                        mma_bf16(acc[mt][2 * p + 1], afr[s][mt],              \
                                 bfr[p][2], bfr[p][3]);                       \
                    }                                                         \
            _Pragma("unroll")                                                 \
            for (int p = 0; p < 4; ++p) {                                     \
                int kk = kb + b_k_off;                                        \
                int nn = warp_n * 64 + p * 16 + b_n_off;                      \
                ldsm_x4t(smem_u32(&wl[kk * LDW + nn]),                        \
                         bfr[p][0], bfr[p][1], bfr[p][2], bfr[p][3]);         \
            }                                                                 \
            _Pragma("unroll")                                                 \
            for (int mt = 0; mt < 2; ++mt)                                    \
                _Pragma("unroll")                                             \
                for (int p = 0; p < 4; ++p) {                                 \
                    mma_bf16(acc[mt][2 * p],     afr[0][mt],                  \
                             bfr[p][0], bfr[p][1]);                           \
                    mma_bf16(acc[mt][2 * p + 1], afr[0][mt],                  \
                             bfr[p][2], bfr[p][3]);                           \
                }                                                             \
        }                                                                     \
    }

template <bool STATS>
__global__ void __launch_bounds__(256)
gemm_hmma(const float* __restrict__ A,
          const __nv_bfloat16* __restrict__ Wth,
          const __nv_bfloat16* __restrict__ Wtl,
          const float* __restrict__ bias, float* __restrict__ C,
          int K, float* __restrict__ stats) {
    extern __shared__ __nv_bfloat16 sm[];
    __shared__ float s_sum[128], s_sq[128];

    const int tid = threadIdx.x;
    const int lane = tid & 31;
    const int wid = tid >> 5;
    const int warp_m = wid & 3;
    const int warp_n = wid >> 2;
    const int rowBase = blockIdx.y * 128;
    const int colBase = blockIdx.x * 128;
    const bool ASB = false;
    const float* asb = nullptr;
    (void)asb;

    if (STATS && tid < 128) { s_sum[tid] = 0.f; s_sq[tid] = 0.f; }

    float acc[2][8][4] = {};
    float4 a_reg[4];

    const int lg = lane >> 3, lj = lane & 7;
    const int a_row_off = (lg & 1) * 8 + lj;
    const int a_col_off = (lg >> 1) * 8;
    const int b_k_off = (lg & 1) * 8 + lj;
    const int b_n_off = (lg >> 1) * 8;

    const int niter = K >> 5;
    GEMM_MAINLOOP();
    __syncthreads();   // protect s_sum/s_sq init + final smem state

    // ---- epilogue: bias + ReLU + store (+ per-column stats) ----
    const int g = lane >> 2, tq = lane & 3;
    float cs[16], cq[16];
    if (STATS) {
        #pragma unroll
        for (int i = 0; i < 16; ++i) { cs[i] = 0.f; cq[i] = 0.f; }
    }
    #pragma unroll
    for (int mt = 0; mt < 2; ++mt) {
        #pragma unroll
        for (int nt = 0; nt < 8; ++nt) {
            int row0 = rowBase + warp_m * 32 + mt * 16 + g;
            int col = colBase + warp_n * 64 + nt * 8 + 2 * tq;
            float b0 = bias[col], b1 = bias[col + 1];
            float v[4] = {fmaxf(acc[mt][nt][0] + b0, 0.f),
                          fmaxf(acc[mt][nt][1] + b1, 0.f),
                          fmaxf(acc[mt][nt][2] + b0, 0.f),
                          fmaxf(acc[mt][nt][3] + b1, 0.f)};
            if (STATS) {
                cs[nt * 2 + 0] += v[0] + v[2];
                cs[nt * 2 + 1] += v[1] + v[3];
                cq[nt * 2 + 0] += v[0] * v[0] + v[2] * v[2];
                cq[nt * 2 + 1] += v[1] * v[1] + v[3] * v[3];
            }
            *reinterpret_cast<float2*>(&C[(size_t)row0 * HH + col]) =
                make_float2(v[0], v[1]);
            *reinterpret_cast<float2*>(&C[(size_t)(row0 + 8) * HH + col]) =
                make_float2(v[2], v[3]);
        }
    }
    if (STATS) {
        #pragma unroll
        for (int i = 0; i < 16; ++i) {
            #pragma unroll
            for (int off = 16; off >= 4; off >>= 1) {
                cs[i] += __shfl_down_sync(0xffffffffu, cs[i], off);
                cq[i] += __shfl_down_sync(0xffffffffu, cq[i], off);
            }
        }
        if (lane < 4) {
            #pragma unroll
            for (int nt = 0; nt < 8; ++nt) {
                #pragma unroll
                for (int c = 0; c < 2; ++c) {
                    int lc = warp_n * 64 + nt * 8 + 2 * lane + c;
                    atomicAdd(&s_sum[lc], cs[nt * 2 + c]);
                    atomicAdd(&s_sq[lc], cq[nt * 2 + c]);
                }
            }
        }
        __syncthreads();
        int c = tid & 127;
        if (tid < 128) atomicAdd(&stats[colBase + c], s_sum[c]);
        else           atomicAdd(&stats[HH + colBase + c], s_sq[c]);
    }
}

// ------- c1 GEMM: inline bn2 affine on A, tanh, fused c2 proj -> logits -----
__global__ void __launch_bounds__(256)
gemm_c1(const float* __restrict__ A,
        const __nv_bfloat16* __restrict__ Wth,
        const __nv_bfloat16* __restrict__ Wtl,
        const float* __restrict__ bias,
        int K,
        const float* __restrict__ st2,
        const float* __restrict__ gamma2,
        const float* __restrict__ beta2,
        const float* __restrict__ c2w, float* __restrict__ alog) {
    extern __shared__ __nv_bfloat16 sm[];
    __shared__ float s_asb[2 * HH];
    const int tid = threadIdx.x;
    const int lane = tid & 31;
    const int wid = tid >> 5;
    const int warp_m = wid & 3;
    const int warp_n = wid >> 2;
    const int rowBase = blockIdx.y * 128;
    const int colBase = blockIdx.x * 128;
    const bool ASB = true;

    // stage BN layer-2 affine into smem
    {
        float sv, bv;
        bn_sb(st2, gamma2, beta2, tid, sv, bv);
        s_asb[tid] = sv;
        s_asb[HH + tid] = bv;
    }
    __syncthreads();
    const float* asb = s_asb;

    float acc[2][8][4] = {};
    float4 a_reg[4];

    const int lg = lane >> 3, lj = lane & 7;
    const int a_row_off = (lg & 1) * 8 + lj;
    const int a_col_off = (lg >> 1) * 8;
    const int b_k_off = (lg & 1) * 8 + lj;
    const int b_n_off = (lg >> 1) * 8;

    const int niter = K >> 5;
    GEMM_MAINLOOP();

    // ---- epilogue: tanh + c2 projection; no C store ----
    const int g = lane >> 2, tq = lane & 3;
    float p[2][2][2] = {};
    #pragma unroll
    for (int mt = 0; mt < 2; ++mt) {
        #pragma unroll
        for (int nt = 0; nt < 8; ++nt) {
            int col = colBase + warp_n * 64 + nt * 8 + 2 * tq;
            float b0 = bias[col], b1 = bias[col + 1];
            float v0 = tanhf(acc[mt][nt][0] + b0);
            float v1 = tanhf(acc[mt][nt][1] + b1);
            float v2 = tanhf(acc[mt][nt][2] + b0);
            float v3 = tanhf(acc[mt][nt][3] + b1);
            float w00 = __ldg(&c2w[col * 2 + 0]);
            float w01 = __ldg(&c2w[col * 2 + 1]);
            float w10 = __ldg(&c2w[col * 2 + 2]);
            float w11 = __ldg(&c2w[col * 2 + 3]);
            p[mt][0][0] += v0 * w00 + v1 * w10;
            p[mt][0][1] += v0 * w01 + v1 * w11;
            p[mt][1][0] += v2 * w00 + v3 * w10;
            p[mt][1][1] += v2 * w01 + v3 * w11;
        }
    }
    #pragma unroll
    for (int mt = 0; mt < 2; ++mt)
        #pragma unroll
        for (int hh = 0; hh < 2; ++hh)
            #pragma unroll
            for (int c = 0; c < 2; ++c) {
                float v = p[mt][hh][c];
                v += __shfl_xor_sync(0xffffffffu, v, 1);
                v += __shfl_xor_sync(0xffffffffu, v, 2);
                p[mt][hh][c] = v;
            }
    if (tq == 0) {
        #pragma unroll
        for (int mt = 0; mt < 2; ++mt)
            #pragma unroll
            for (int hh = 0; hh < 2; ++hh) {
                int row = rowBase + warp_m * 32 + mt * 16 + g + hh * 8;
                atomicAdd(&alog[row * 2 + 0], p[mt][hh][0]);
                atomicAdd(&alog[row * 2 + 1], p[mt][hh][1]);
            }
    }
}

// ---------------- softmax over fused logits ---------------------------------
__global__ void softmax2_kernel(const float* __restrict__ alog,
                                const float* __restrict__ c2b,
                                float* __restrict__ Aout) {
    const int r = blockIdx.x * 256 + threadIdx.x;
    float s0 = alog[2 * r + 0] + c2b[0];
    float s1 = alog[2 * r + 1] + c2b[1];
    float m = fmaxf(s0, s1);
    float e0 = expf(s0 - m), e1 = expf(s1 - m);
    float inv = 1.f / (e0 + e1);
    Aout[2 * r + 0] = e0 * inv;
    Aout[2 * r + 1] = e1 * inv;
}

// -------- pooling + classifier head fused (block per graph) -----------------
__global__ void pool_head_kernel(const float* __restrict__ Z,
                                 const float* __restrict__ Aa,
                                 const float* __restrict__ st2,
                                 const float* __restrict__ gamma2,
                                 const float* __restrict__ beta2,
                                 const float* __restrict__ l1w,
                                 const float* __restrict__ l1b,
                                 const float* __restrict__ l2w,
                                 const float* __restrict__ l2b,
                                 float* __restrict__ sub_out,
                                 float* __restrict__ graph_out,
                                 float* __restrict__ logits_out) {
    __shared__ float sa0[NPG];
    __shared__ float ssub[HH];
    __shared__ float red0[HH], red1[HH];
    const int g = blockIdx.x, t = threadIdx.x;   // 256 threads
    if (t < NPG) sa0[t] = Aa[(g * NPG + t) * 2];
    float sf, bf;
    bn_sb(st2, gamma2, beta2, t, sf, bf);
    __syncthreads();
    float sh = 0.f, ss = 0.f;
    const size_t base = (size_t)g * NPG * HH;
    for (int r = 0; r < NPG; ++r) {
        float hv = sf * Z[base + r * HH + t] + bf;
        sh += hv;
        ss += sa0[r] * hv;
    }
    sub_out[g * HH + t] = ss;
    graph_out[g * HH + t] = sh * (1.f / NPG);
    ssub[t] = ss;
    __syncthreads();
    float acc = l1b[t];
    #pragma unroll 8
    for (int k = 0; k < HH; ++k) acc += ssub[k] * l1w[k * HH + t];
    float zc = fmaxf(acc, 0.f);
    red0[t] = zc * l2w[t * 2 + 0];
    red1[t] = zc * l2w[t * 2 + 1];
    __syncthreads();
    for (int s = 128; s > 0; s >>= 1) {
        if (t < s) { red0[t] += red0[t + s]; red1[t] += red1[t + s]; }
        __syncthreads();
    }
    if (t == 0) {
        float s0 = red0[0] + l2b[0], s1 = red1[0] + l2b[1];
        float m = fmaxf(s0, s1);
        float lse = m + logf(expf(s0 - m) + expf(s1 - m));
        logits_out[g * 2 + 0] = s0 - lse;
        logits_out[g * 2 + 1] = s1 - lse;
    }
}

// -------- pooled adjacency diag penalty + mean (block per graph) ------------
__global__ void adj_pen_kernel(const float* __restrict__ Aa,
                               const int* __restrict__ src,
                               const int* __restrict__ dst,
                               float* __restrict__ out_pen) {
    const int g = blockIdx.x, t = threadIdx.x;   // 128 threads
    float m00 = 0.f, m01 = 0.f, m10 = 0.f, m11 = 0.f;
    for (int e = t; e < EPG; e += 128) {
        int se = src[g * EPG + e], de = dst[g * EPG + e];
        float a0 = Aa[se * 2], a1 = Aa[se * 2 + 1];
        float b0 = Aa[de * 2], b1 = Aa[de * 2 + 1];
        m00 += a0 * b0; m01 += a0 * b1;
        m10 += a1 * b0; m11 += a1 * b1;
    }
    __shared__ float red[4][128];
    red[0][t] = m00; red[1][t] = m01; red[2][t] = m10; red[3][t] = m11;
    __syncthreads();
    for (int s = 64; s > 0; s >>= 1) {
        if (t < s) {
            red[0][t] += red[0][t + s]; red[1][t] += red[1][t + s];
            red[2][t] += red[2][t + s]; red[3][t] += red[3][t + s];
        }
        __syncthreads();
    }
    if (t == 0) {
        float r0 = fmaxf(fabsf(red[0][0]) + fabsf(red[1][0]), 1e-12f);
        float r1 = fmaxf(fabsf(red[2][0]) + fabsf(red[3][0]), 1e-12f);
        float e0 = red[0][0] / r0 - 1.f;
        float e1 = red[3][0] / r1 - 1.f;
        atomicAdd(out_pen, 0.5f * (e0 * e0 + e1 * e1) * (1.f / BB));
    }
}

// ---------------- launch ------------------------------------------------------
extern "C" void kernel_launch(void* const* d_in, const int* in_sizes, int n_in,
                              void* d_out, int out_size) {
    const float* x    = (const float*)d_in[0];
    const int*   ei   = (const int*)d_in[1];
    const int*   src  = ei;
    const int*   dst  = ei + EE;
    const float* w0_1 = (const float*)d_in[3];
    const float* b0_1 = (const float*)d_in[4];
    const float* w0_2 = (const float*)d_in[5];
    const float* b0_2 = (const float*)d_in[6];
    const float* g0   = (const float*)d_in[7];
    const float* be0  = (const float*)d_in[8];
    const float* wl1  = (const float*)d_in[9];
    const float* bl1  = (const float*)d_in[10];
    const float* wl2  = (const float*)d_in[11];
    const float* bl2  = (const float*)d_in[12];
    const float* gl   = (const float*)d_in[13];
    const float* bel  = (const float*)d_in[14];
    const float* c1w  = (const float*)d_in[15];
    const float* c1b  = (const float*)d_in[16];
    const float* c2w  = (const float*)d_in[17];
    const float* c2b  = (const float*)d_in[18];
    const float* l1w  = (const float*)d_in[19];
    const float* l1b  = (const float*)d_in[20];
    const float* l2w  = (const float*)d_in[21];
    const float* l2b  = (const float*)d_in[22];

    float* out        = (float*)d_out;
    float* out_logits = out;
    float* out_sub    = out + BB * 2;
    float* out_graph  = out + BB * 2 + BB * HH;
    float* out_pen    = out + BB * 2 + 2 * BB * HH;

    float *zb, *tb, *hb, *ab, *alog, *stats;
    cudaGetSymbolAddress((void**)&zb, d_z);
    cudaGetSymbolAddress((void**)&tb, d_t);
    cudaGetSymbolAddress((void**)&hb, d_h);
    cudaGetSymbolAddress((void**)&ab, d_a);
    cudaGetSymbolAddress((void**)&alog, d_alog);
    cudaGetSymbolAddress((void**)&stats, d_stats);
    __nv_bfloat16 *wth, *wtl;
    cudaGetSymbolAddress((void**)&wth, d_wth);
    cudaGetSymbolAddress((void**)&wtl, d_wtl);

    cudaFuncSetAttribute(gemm_hmma<false>,
                         cudaFuncAttributeMaxDynamicSharedMemorySize, GEMM_SMEM_BYTES);
    cudaFuncSetAttribute(gemm_hmma<true>,
                         cudaFuncAttributeMaxDynamicSharedMemorySize, GEMM_SMEM_BYTES);
    cudaFuncSetAttribute(gemm_c1,
                         cudaFuncAttributeMaxDynamicSharedMemorySize, GEMM_SMEM_BYTES);

    const int O_W01 = 0;
    const int O_W02 = 32768;
    const int O_L1A = 98304;
    const int O_L2A = 163840;
    const int O_L1B = 229376;
    const int O_L2B = 294912;
    const int O_C1  = 360448;

    const dim3 gemm_grid(HH / 128, NN / 128);

    wsplit_all_kernel<<<(WSPLIT_TOTAL + 255) / 256, 256>>>(
        w0_1, w0_2, wl1, wl2, c1w, wth, wtl, out_pen);                    // 0
    csr_kernel<<<BB, NPG>>>(src, dst);                                    // 1
    agg_gather<FIN, false><<<NN / 8, 256>>>(x, hb, nullptr, nullptr, nullptr); // 2
    gemm_hmma<false><<<gemm_grid, 256, GEMM_SMEM_BYTES>>>(                // 3 (profiled)
        hb, wth + O_W01, wtl + O_W01, b0_1, tb, FIN, nullptr);
    gemm_hmma<true><<<gemm_grid, 256, GEMM_SMEM_BYTES>>>(                 // 4
        tb, wth + O_W02, wtl + O_W02, b0_2, zb, HH, stats);

    const int offs1[2] = {O_L1A, O_L1B};
    const int offs2[2] = {O_L2A, O_L2B};
    const float* gammas[2] = {g0, gl};
    const float* betas[2]  = {be0, bel};
    for (int i = 0; i < 2; ++i) {
        agg_gather<HH, true><<<NN / 8, 256>>>(zb, hb, stats + i * 2 * HH,
                                              gammas[i], betas[i]);
        gemm_hmma<false><<<gemm_grid, 256, GEMM_SMEM_BYTES>>>(
            hb, wth + offs1[i], wtl + offs1[i], bl1 + i * HH, tb, HH, nullptr);
        gemm_hmma<true><<<gemm_grid, 256, GEMM_SMEM_BYTES>>>(
            tb, wth + offs2[i], wtl + offs2[i], bl2 + i * HH, zb, HH,
            stats + (1 + i) * 2 * HH);
    }

    // ---- assignment: c1 GEMM (inline BN2 affine) + fused c2 proj ----
    gemm_c1<<<gemm_grid, 256, GEMM_SMEM_BYTES>>>(
        zb, wth + O_C1, wtl + O_C1, c1b, HH,
        stats + 2 * 2 * HH, gl + HH, bel + HH, c2w, alog);
    softmax2_kernel<<<NN / 256, 256>>>(alog, c2b, ab);

    // ---- pooling+head / adjacency penalty ----
    pool_head_kernel<<<BB, 256>>>(zb, ab, stats + 2 * 2 * HH, gl + HH, bel + HH,
                                  l1w, l1b, l2w, l2b,
                                  out_sub, out_graph, out_logits);
    adj_pen_kernel<<<BB, 128>>>(ab, src, dst, out_pen);
}

// round 15
// speedup vs baseline: 1.2183x; 1.0502x over previous
#include <cuda_runtime.h>
#include <cuda_bf16.h>
#include <math.h>

// Problem constants (fixed by setup_inputs)
#define NN      65536
#define BB      512
#define NPG     128
#define EE      262144
#define EPG     512
#define HH      256
#define FIN     128
#define BN_EPS  1e-5f

// ---------------- scratch (device globals; no cudaMalloc allowed) ----------
__device__ float d_z[NN * HH];
__device__ float d_t[NN * HH];
__device__ float d_h[NN * HH];
__device__ float d_a[NN * 2];
__device__ float d_alog[NN * 2];
__device__ float d_stats[3 * 2 * HH];   // per layer: [sum(256) | sumsq(256)]
__device__ int   d_csr[EE];
__device__ int   d_rowstart[NN];
__device__ int   d_deg[NN];
#define WSPLIT_TOTAL (256 * (128 + 6 * 256))
__device__ __nv_bfloat16 d_wth[WSPLIT_TOTAL];
__device__ __nv_bfloat16 d_wtl[WSPLIT_TOTAL];

// ---------------- helpers ----------------------------------------------------
__device__ __forceinline__ unsigned smem_u32(const void* p) {
    return (unsigned)__cvta_generic_to_shared(p);
}
__device__ __forceinline__ void ldsm_x4(unsigned addr, unsigned& r0, unsigned& r1,
                                        unsigned& r2, unsigned& r3) {
    asm volatile("ldmatrix.sync.aligned.m8n8.x4.shared.b16 {%0,%1,%2,%3}, [%4];"
                 : "=r"(r0), "=r"(r1), "=r"(r2), "=r"(r3) : "r"(addr));
}
__device__ __forceinline__ void ldsm_x4t(unsigned addr, unsigned& r0, unsigned& r1,
                                         unsigned& r2, unsigned& r3) {
    asm volatile("ldmatrix.sync.aligned.m8n8.x4.trans.shared.b16 {%0,%1,%2,%3}, [%4];"
                 : "=r"(r0), "=r"(r1), "=r"(r2), "=r"(r3) : "r"(addr));
}
__device__ __forceinline__ void mma_bf16(float* d, const unsigned* a,
                                         unsigned b0, unsigned b1) {
    asm volatile("mma.sync.aligned.m16n8k16.row.col.f32.bf16.bf16.f32 "
                 "{%0,%1,%2,%3}, {%4,%5,%6,%7}, {%8,%9}, {%0,%1,%2,%3};"
                 : "+f"(d[0]), "+f"(d[1]), "+f"(d[2]), "+f"(d[3])
                 : "r"(a[0]), "r"(a[1]), "r"(a[2]), "r"(a[3]), "r"(b0), "r"(b1));
}
__device__ __forceinline__ void split_bf16(float v, __nv_bfloat16& h, __nv_bfloat16& l) {
    h = __float2bfloat16(v);
    l = __float2bfloat16(v - __bfloat162float(h));
}
__device__ __forceinline__ void bn_sb(const float* __restrict__ st,
                                      const float* __restrict__ gamma,
                                      const float* __restrict__ beta,
                                      int f, float& s, float& b) {
    const float inv_n = 1.f / NN;
    float mu  = st[f] * inv_n;
    float var = st[HH + f] * inv_n - mu * mu;
    s = rsqrtf(var + BN_EPS) * gamma[f];
    b = beta[f] - mu * s;
}
#define CP_ASYNC16(dst, src) \
    asm volatile("cp.async.cg.shared.global [%0], [%1], 16;" \
                 :: "r"(dst), "l"(src))
#define CP_COMMIT() asm volatile("cp.async.commit_group;")
#define CP_WAIT0()  asm volatile("cp.async.wait_group 0;")

// ---------------- weight prep + scratch zeroing ------------------------------
__global__ void wsplit_all_kernel(const float* __restrict__ w01,
                                  const float* __restrict__ w02,
                                  const float* __restrict__ wl1,
                                  const float* __restrict__ wl2,
                                  const float* __restrict__ c1w,
                                  __nv_bfloat16* __restrict__ oh,
                                  __nv_bfloat16* __restrict__ ol,
                                  float* __restrict__ out_pen) {
    int id = blockIdx.x * 256 + threadIdx.x;
    if (id == 0) out_pen[0] = 0.f;
    if (id < 3 * 2 * HH) d_stats[id] = 0.f;
    if (id < NN * 2) d_alog[id] = 0.f;
    if (id >= WSPLIT_TOTAL) return;
    const float* src;
    if (id < 32768) {
        src = w01 + id;
    } else {
        int r = id - 32768;
        int m = r >> 16, off = r & 65535;
        const float* bases[6] = {w02, wl1, wl2, wl1 + 65536, wl2 + 65536, c1w};
        src = bases[m] + off;
    }
    __nv_bfloat16 h, l;
    split_bf16(*src, h, l);
    oh[id] = h; ol[id] = l;
}

// ---------------- CSR build (atomic, one block/graph) -----------------------
__global__ void csr_kernel(const int* __restrict__ src,
                           const int* __restrict__ dst) {
    __shared__ int cnt[NPG];
    __shared__ int sscan[NPG];
    __shared__ int pos[NPG];
    const int g = blockIdx.x, t = threadIdx.x;
    const int ebase = g * EPG;
    cnt[t] = 0;
    __syncthreads();
    int mys[4], myd[4];
    #pragma unroll
    for (int i = 0; i < 4; ++i) {
        int e = ebase + t * 4 + i;
        mys[i] = src[e];
        myd[i] = dst[e] - g * NPG;
        atomicAdd(&cnt[myd[i]], 1);
    }
    __syncthreads();
    int c = cnt[t];
    sscan[t] = c;
    __syncthreads();
    for (int off = 1; off < NPG; off <<= 1) {
        int v = (t >= off) ? sscan[t - off] : 0;
        __syncthreads();
        sscan[t] += v;
        __syncthreads();
    }
    int excl = sscan[t] - c;
    d_rowstart[g * NPG + t] = ebase + excl;
    d_deg[g * NPG + t] = c;
    pos[t] = ebase + excl;
    __syncthreads();
    #pragma unroll
    for (int i = 0; i < 4; ++i) {
        int p = atomicAdd(&pos[myd[i]], 1);
        d_csr[p] = mys[i];
    }
}

// -------- gather aggregation (first layer only, on x) -----------------------
__global__ void agg_gather_x(const float* __restrict__ h,
                             float* __restrict__ z) {
    const int node = blockIdx.x * 8 + (threadIdx.x >> 5);
    const int lane = threadIdx.x & 31;
    const int s = d_rowstart[node];
    const int dg = d_deg[node];
    const int c0 = lane * 4;
    const size_t rb = (size_t)node * FIN;
    float4 a0 = *reinterpret_cast<const float4*>(&h[rb + c0]);
    for (int e = 0; e < dg; ++e) {
        const size_t sb = (size_t)__ldg(&d_csr[s + e]) * FIN;
        float4 b0 = *reinterpret_cast<const float4*>(&h[sb + c0]);
        a0.x += b0.x; a0.y += b0.y; a0.z += b0.z; a0.w += b0.w;
    }
    *reinterpret_cast<float4*>(&z[rb + c0]) = a0;
}

// ------- bf16x3 HMMA GEMM (single mid-loop barrier schedule) ----------------
#define LDA 40
#define LDW 136
#define SM_AH  0
#define SM_AL  10240
#define SM_WH  20480
#define SM_WL  29184
#define GEMM_SMEM_BYTES (37888 * 2)
#define TILE_LD 132   // fp32 agg tile row stride (16B-aligned)

#define GEMM_LOAD_A(it) do {                                                  \
    const int k0 = (it) * 32;                                                 \
    _Pragma("unroll")                                                         \
    for (int i = 0; i < 4; ++i) {                                             \
        int idx = tid + i * 256;                                              \
        int row = idx >> 3;                                                   \
        int c = (idx & 7) * 4;                                                \
        a_reg[i] = *reinterpret_cast<const float4*>(                          \
            &A[(size_t)(rowBase + row) * K + k0 + c]);                        \
        if (ASB) {                                                            \
            float4 sv = *reinterpret_cast<const float4*>(&asb[k0 + c]);       \
            float4 bv = *reinterpret_cast<const float4*>(&asb[HH + k0 + c]);  \
            a_reg[i].x = sv.x * a_reg[i].x + dp1r[i] * bv.x;                  \
            a_reg[i].y = sv.y * a_reg[i].y + dp1r[i] * bv.y;                  \
            a_reg[i].z = sv.z * a_reg[i].z + dp1r[i] * bv.z;                  \
            a_reg[i].w = sv.w * a_reg[i].w + dp1r[i] * bv.w;                  \
        }                                                                     \
    }                                                                         \
} while (0)

#define GEMM_STORE_A(buf) do {                                                \
    __nv_bfloat16* ah = sm + SM_AH + (buf) * 5120;                            \
    __nv_bfloat16* al = sm + SM_AL + (buf) * 5120;                            \
    _Pragma("unroll")                                                         \
    for (int i = 0; i < 4; ++i) {                                             \
        int idx = tid + i * 256;                                              \
        int row = idx >> 3;                                                   \
        int c = (idx & 7) * 4;                                                \
        float vv[4] = {a_reg[i].x, a_reg[i].y, a_reg[i].z, a_reg[i].w};       \
        unsigned hp[2], lp[2];                                                \
        _Pragma("unroll")                                                     \
        for (int q = 0; q < 2; ++q) {                                         \
            __nv_bfloat16 h0, l0, h1, l1;                                     \
            split_bf16(vv[2 * q], h0, l0);                                    \
            split_bf16(vv[2 * q + 1], h1, l1);                                \
            hp[q] = ((unsigned)*(unsigned short*)&h1 << 16) |                 \
                    *(unsigned short*)&h0;                                    \
            lp[q] = ((unsigned)*(unsigned short*)&l1 << 16) |                 \
                    *(unsigned short*)&l0;                                    \
        }                                                                     \
        *reinterpret_cast<uint2*>(&ah[row * LDA + c]) =                       \
            make_uint2(hp[0], hp[1]);                                         \
        *reinterpret_cast<uint2*>(&al[row * LDA + c]) =                       \
            make_uint2(lp[0], lp[1]);                                         \
    }                                                                         \
} while (0)

#define GEMM_CP_W(it, buf) do {                                               \
    const int k0 = (it) * 32;                                                 \
    __nv_bfloat16* wh = sm + SM_WH + (buf) * 4352;                            \
    __nv_bfloat16* wl = sm + SM_WL + (buf) * 4352;                            \
    _Pragma("unroll")                                                         \
    for (int i = 0; i < 2; ++i) {                                             \
        int idx = tid + i * 256;                                              \
        int row = idx >> 4;                                                   \
        int c8 = (idx & 15) * 8;                                              \
        size_t go = (size_t)(k0 + row) * HH + colBase + c8;                   \
        CP_ASYNC16(smem_u32(&wh[row * LDW + c8]), &Wth[go]);                  \
        CP_ASYNC16(smem_u32(&wl[row * LDW + c8]), &Wtl[go]);                  \
    }                                                                         \
    CP_COMMIT();                                                              \
} while (0)

#define GEMM_MAINLOOP()                                                       \
    GEMM_LOAD_A(0);                                                           \
    GEMM_CP_W(0, 0);                                                          \
    for (int it = 0; it < niter; ++it) {                                      \
        const int buf = it & 1;                                               \
        GEMM_STORE_A(buf);                                                    \
        if (it + 1 < niter) GEMM_LOAD_A(it + 1);                              \
        CP_WAIT0();                                                           \
        __syncthreads();                                                      \
        if (it + 1 < niter) GEMM_CP_W(it + 1, buf ^ 1);                       \
        const __nv_bfloat16* ah = sm + SM_AH + buf * 5120;                    \
        const __nv_bfloat16* al = sm + SM_AL + buf * 5120;                    \
        const __nv_bfloat16* wh = sm + SM_WH + buf * 4352;                    \
        const __nv_bfloat16* wl = sm + SM_WL + buf * 4352;                    \
        _Pragma("unroll")                                                     \
        for (int ks = 0; ks < 2; ++ks) {                                      \
            const int kb = ks * 16;                                           \
            unsigned afr[2][2][4];                                            \
            _Pragma("unroll")                                                 \
            for (int mt = 0; mt < 2; ++mt) {                                  \
                int row = warp_m * 32 + mt * 16 + a_row_off;                  \
                int col = kb + a_col_off;                                     \
                ldsm_x4(smem_u32(&ah[row * LDA + col]),                       \
                        afr[0][mt][0], afr[0][mt][1], afr[0][mt][2],          \
                        afr[0][mt][3]);                                       \
                ldsm_x4(smem_u32(&al[row * LDA + col]),                       \
                        afr[1][mt][0], afr[1][mt][1], afr[1][mt][2],          \
                        afr[1][mt][3]);                                       \
            }                                                                 \
            unsigned bfr[4][4];                                               \
            _Pragma("unroll")                                                 \
            for (int p = 0; p < 4; ++p) {                                     \
                int kk = kb + b_k_off;                                        \
                int nn = warp_n * 64 + p * 16 + b_n_off;                      \
                ldsm_x4t(smem_u32(&wh[kk * LDW + nn]),                        \
                         bfr[p][0], bfr[p][1], bfr[p][2], bfr[p][3]);         \
            }                                                                 \
            _Pragma("unroll")                                                 \
            for (int s = 0; s < 2; ++s)                                       \
                _Pragma("unroll")                                             \
                for (int mt = 0; mt < 2; ++mt)                                \
                    _Pragma("unroll")                                         \
                    for (int p = 0; p < 4; ++p) {                             \
                        mma_bf16(acc[mt][2 * p],     afr[s][mt],              \
                                 bfr[p][0], bfr[p][1]);                       \
                        mma_bf16(acc[mt][2 * p + 1], afr[s][mt],              \
                                 bfr[p][2], bfr[p][3]);                       \
                    }                                                         \
            _Pragma("unroll")                                                 \
            for (int p = 0; p < 4; ++p) {                                     \
                int kk = kb + b_k_off;                                        \
                int nn = warp_n * 64 + p * 16 + b_n_off;                      \
                ldsm_x4t(smem_u32(&wl[kk * LDW + nn]),                        \
                         bfr[p][0], bfr[p][1], bfr[p][2], bfr[p][3]);         \
            }                                                                 \
            _Pragma("unroll")                                                 \
            for (int mt = 0; mt < 2; ++mt)                                    \
                _Pragma("unroll")                                             \
                for (int p = 0; p < 4; ++p) {                                 \
                    mma_bf16(acc[mt][2 * p],     afr[0][mt],                  \
                             bfr[p][0], bfr[p][1]);                           \
                    mma_bf16(acc[mt][2 * p + 1], afr[0][mt],                  \
                             bfr[p][2], bfr[p][3]);                           \
                }                                                             \
        }                                                                     \
    }

// ---- G1: plain or row/col-BN affine on A; bias+ReLU; store C ---------------
template <bool ROWBN>
__global__ void __launch_bounds__(256)
gemm_g1(const float* __restrict__ A,
        const __nv_bfloat16* __restrict__ Wth,
        const __nv_bfloat16* __restrict__ Wtl,
        const float* __restrict__ bias, float* __restrict__ C, int K,
        const int* __restrict__ deg,
        const float* __restrict__ st,
        const float* __restrict__ gamma,
        const float* __restrict__ beta) {
    extern __shared__ __nv_bfloat16 sm[];
    __shared__ float s_asb[2 * HH];
    const int tid = threadIdx.x;
    const int lane = tid & 31;
    const int wid = tid >> 5;
    const int warp_m = wid & 3;
    const int warp_n = wid >> 2;
    const int rowBase = blockIdx.y * 128;
    const int colBase = blockIdx.x * 128;
    const bool ASB = ROWBN;

    float dp1r[4] = {1.f, 1.f, 1.f, 1.f};
    if (ROWBN) {
        float sv, bv;
        bn_sb(st, gamma, beta, tid, sv, bv);
        s_asb[tid] = sv;
        s_asb[HH + tid] = bv;
        #pragma unroll
        for (int i = 0; i < 4; ++i)
            dp1r[i] = 1.f + (float)deg[rowBase + ((tid + i * 256) >> 3)];
        __syncthreads();
    }
    const float* asb = s_asb;

    float acc[2][8][4] = {};
    float4 a_reg[4];

    const int lg = lane >> 3, lj = lane & 7;
    const int a_row_off = (lg & 1) * 8 + lj;
    const int a_col_off = (lg >> 1) * 8;
    const int b_k_off = (lg & 1) * 8 + lj;
    const int b_n_off = (lg >> 1) * 8;

    const int niter = K >> 5;
    GEMM_MAINLOOP();

    const int g = lane >> 2, tq = lane & 3;
    #pragma unroll
    for (int mt = 0; mt < 2; ++mt) {
        #pragma unroll
        for (int nt = 0; nt < 8; ++nt) {
            int row0 = rowBase + warp_m * 32 + mt * 16 + g;
            int col = colBase + warp_n * 64 + nt * 8 + 2 * tq;
            float b0 = bias[col], b1 = bias[col + 1];
            *reinterpret_cast<float2*>(&C[(size_t)row0 * HH + col]) =
                make_float2(fmaxf(acc[mt][nt][0] + b0, 0.f),
                            fmaxf(acc[mt][nt][1] + b1, 0.f));
            *reinterpret_cast<float2*>(&C[(size_t)(row0 + 8) * HH + col]) =
                make_float2(fmaxf(acc[mt][nt][2] + b0, 0.f),
                            fmaxf(acc[mt][nt][3] + b1, 0.f));
        }
    }
}

// ---- G2: bias+ReLU + BN stats; AGG ? (aggregate in smem, write Hout raw-agg)
//                                 : (store z to C) -----------------------------
template <bool AGG>
__global__ void __launch_bounds__(256)
gemm_g2(const float* __restrict__ A,
        const __nv_bfloat16* __restrict__ Wth,
        const __nv_bfloat16* __restrict__ Wtl,
        const float* __restrict__ bias, float* __restrict__ C,
        int K, float* __restrict__ stats) {
    extern __shared__ __nv_bfloat16 sm[];
    __shared__ float s_sum[128], s_sq[128];

    const int tid = threadIdx.x;
    const int lane = tid & 31;
    const int wid = tid >> 5;
    const int warp_m = wid & 3;
    const int warp_n = wid >> 2;
    const int rowBase = blockIdx.y * 128;
    const int colBase = blockIdx.x * 128;
    const bool ASB = false;
    const float* asb = nullptr;
    float dp1r[4] = {1.f, 1.f, 1.f, 1.f};
    (void)asb; (void)dp1r;

    if (tid < 128) { s_sum[tid] = 0.f; s_sq[tid] = 0.f; }

    float acc[2][8][4] = {};
    float4 a_reg[4];

    const int lg = lane >> 3, lj = lane & 7;
    const int a_row_off = (lg & 1) * 8 + lj;
    const int a_col_off = (lg >> 1) * 8;
    const int b_k_off = (lg & 1) * 8 + lj;
    const int b_n_off = (lg >> 1) * 8;

    const int niter = K >> 5;
    GEMM_MAINLOOP();
    __syncthreads();   // drain last-iter smem reads before epilogue reuse

    float* tile = reinterpret_cast<float*>(sm);   // 128 x TILE_LD fp32 (AGG)

    const int g = lane >> 2, tq = lane & 3;
    float cs[16], cq[16];
    #pragma unroll
    for (int i = 0; i < 16; ++i) { cs[i] = 0.f; cq[i] = 0.f; }
    #pragma unroll
    for (int mt = 0; mt < 2; ++mt) {
        #pragma unroll
        for (int nt = 0; nt < 8; ++nt) {
            int lr = warp_m * 32 + mt * 16 + g;
            int lc = warp_n * 64 + nt * 8 + 2 * tq;
            float b0 = bias[colBase + lc], b1 = bias[colBase + lc + 1];
            float v[4] = {fmaxf(acc[mt][nt][0] + b0, 0.f),
                          fmaxf(acc[mt][nt][1] + b1, 0.f),
                          fmaxf(acc[mt][nt][2] + b0, 0.f),
                          fmaxf(acc[mt][nt][3] + b1, 0.f)};
            cs[nt * 2 + 0] += v[0] + v[2];
            cs[nt * 2 + 1] += v[1] + v[3];
            cq[nt * 2 + 0] += v[0] * v[0] + v[2] * v[2];
            cq[nt * 2 + 1] += v[1] * v[1] + v[3] * v[3];
            if (AGG) {
                *reinterpret_cast<float2*>(&tile[lr * TILE_LD + lc]) =
                    make_float2(v[0], v[1]);
                *reinterpret_cast<float2*>(&tile[(lr + 8) * TILE_LD + lc]) =
                    make_float2(v[2], v[3]);
            } else {
                *reinterpret_cast<float2*>(
                    &C[(size_t)(rowBase + lr) * HH + colBase + lc]) =
                    make_float2(v[0], v[1]);
                *reinterpret_cast<float2*>(
                    &C[(size_t)(rowBase + lr + 8) * HH + colBase + lc]) =
                    make_float2(v[2], v[3]);
            }
        }
    }
    #pragma unroll
    for (int i = 0; i < 16; ++i) {
        #pragma unroll
        for (int off = 16; off >= 4; off >>= 1) {
            cs[i] += __shfl_down_sync(0xffffffffu, cs[i], off);
            cq[i] += __shfl_down_sync(0xffffffffu, cq[i], off);
        }
    }
    if (lane < 4) {
        #pragma unroll
        for (int nt = 0; nt < 8; ++nt) {
            #pragma unroll
            for (int c = 0; c < 2; ++c) {
                int lc = warp_n * 64 + nt * 8 + 2 * lane + c;
                atomicAdd(&s_sum[lc], cs[nt * 2 + c]);
                atomicAdd(&s_sq[lc], cq[nt * 2 + c]);
            }
        }
    }
    __syncthreads();   // s_sum/s_sq final; (AGG) tile fully written
    {
        int c = tid & 127;
        if (tid < 128) atomicAdd(&stats[colBase + c], s_sum[c]);
        else           atomicAdd(&stats[HH + colBase + c], s_sq[c]);
    }
    if (AGG) {
        // aggregate within the graph (rows of this CTA) from the smem tile
        const int gph = blockIdx.y;
        const int c0 = lane * 4;
        #pragma unroll
        for (int rr = 0; rr < 16; ++rr) {
            int r = wid * 16 + rr;
            int node = gph * NPG + r;
            int st_ = d_rowstart[node];
            int dgn = d_deg[node];
            float4 a4 = *reinterpret_cast<float4*>(&tile[r * TILE_LD + c0]);
            for (int e = 0; e < dgn; ++e) {
                int sl = __ldg(&d_csr[st_ + e]) - gph * NPG;
                float4 b4 = *reinterpret_cast<float4*>(&tile[sl * TILE_LD + c0]);
                a4.x += b4.x; a4.y += b4.y; a4.z += b4.z; a4.w += b4.w;
            }
            *reinterpret_cast<float4*>(&C[(size_t)node * HH + colBase + c0]) = a4;
        }
    }
}

// ------- c1 GEMM: inline bn2 affine on A, tanh, fused c2 proj -> logits -----
__global__ void __launch_bounds__(256)
gemm_c1(const float* __restrict__ A,
        const __nv_bfloat16* __restrict__ Wth,
        const __nv_bfloat16* __restrict__ Wtl,
        const float* __restrict__ bias,
        int K,
        const float* __restrict__ st2,
        const float* __restrict__ gamma2,
        const float* __restrict__ beta2,
        const float* __restrict__ c2w, float* __restrict__ alog) {
    extern __shared__ __nv_bfloat16 sm[];
    __shared__ float s_asb[2 * HH];
    const int tid = threadIdx.x;
    const int lane = tid & 31;
    const int wid = tid >> 5;
    const int warp_m = wid & 3;
    const int warp_n = wid >> 2;
    const int rowBase = blockIdx.y * 128;
    const int colBase = blockIdx.x * 128;
    const bool ASB = true;
    float dp1r[4] = {1.f, 1.f, 1.f, 1.f};

    {
        float sv, bv;
        bn_sb(st2, gamma2, beta2, tid, sv, bv);
        s_asb[tid] = sv;
        s_asb[HH + tid] = bv;
    }
    __syncthreads();
    const float* asb = s_asb;

    float acc[2][8][4] = {};
    float4 a_reg[4];

    const int lg = lane >> 3, lj = lane & 7;
    const int a_row_off = (lg & 1) * 8 + lj;
    const int a_col_off = (lg >> 1) * 8;
    const int b_k_off = (lg & 1) * 8 + lj;
    const int b_n_off = (lg >> 1) * 8;

    const int niter = K >> 5;
    GEMM_MAINLOOP();

    const int g = lane >> 2, tq = lane & 3;
    float p[2][2][2] = {};
    #pragma unroll
    for (int mt = 0; mt < 2; ++mt) {
        #pragma unroll
        for (int nt = 0; nt < 8; ++nt) {
            int col = colBase + warp_n * 64 + nt * 8 + 2 * tq;
            float b0 = bias[col], b1 = bias[col + 1];
            float v0 = tanhf(acc[mt][nt][0] + b0);
            float v1 = tanhf(acc[mt][nt][1] + b1);
            float v2 = tanhf(acc[mt][nt][2] + b0);
            float v3 = tanhf(acc[mt][nt][3] + b1);
            float w00 = __ldg(&c2w[col * 2 + 0]);
            float w01 = __ldg(&c2w[col * 2 + 1]);
            float w10 = __ldg(&c2w[col * 2 + 2]);
            float w11 = __ldg(&c2w[col * 2 + 3]);
            p[mt][0][0] += v0 * w00 + v1 * w10;
            p[mt][0][1] += v0 * w01 + v1 * w11;
            p[mt][1][0] += v2 * w00 + v3 * w10;
            p[mt][1][1] += v2 * w01 + v3 * w11;
        }
    }
    #pragma unroll
    for (int mt = 0; mt < 2; ++mt)
        #pragma unroll
        for (int hh = 0; hh < 2; ++hh)
            #pragma unroll
            for (int c = 0; c < 2; ++c) {
                float v = p[mt][hh][c];
                v += __shfl_xor_sync(0xffffffffu, v, 1);
                v += __shfl_xor_sync(0xffffffffu, v, 2);
                p[mt][hh][c] = v;
            }
    if (tq == 0) {
        #pragma unroll
        for (int mt = 0; mt < 2; ++mt)
            #pragma unroll
            for (int hh = 0; hh < 2; ++hh) {
                int row = rowBase + warp_m * 32 + mt * 16 + g + hh * 8;
                atomicAdd(&alog[row * 2 + 0], p[mt][hh][0]);
                atomicAdd(&alog[row * 2 + 1], p[mt][hh][1]);
            }
    }
}

// ---------------- softmax over fused logits ---------------------------------
__global__ void softmax2_kernel(const float* __restrict__ alog,
                                const float* __restrict__ c2b,
                                float* __restrict__ Aout) {
    const int r = blockIdx.x * 256 + threadIdx.x;
    float s0 = alog[2 * r + 0] + c2b[0];
    float s1 = alog[2 * r + 1] + c2b[1];
    float m = fmaxf(s0, s1);
    float e0 = expf(s0 - m), e1 = expf(s1 - m);
    float inv = 1.f / (e0 + e1);
    Aout[2 * r + 0] = e0 * inv;
    Aout[2 * r + 1] = e1 * inv;
}

// -------- pooling + classifier head fused (block per graph) -----------------
__global__ void pool_head_kernel(const float* __restrict__ Z,
                                 const float* __restrict__ Aa,
                                 const float* __restrict__ st2,
                                 const float* __restrict__ gamma2,
                                 const float* __restrict__ beta2,
                                 const float* __restrict__ l1w,
                                 const float* __restrict__ l1b,
                                 const float* __restrict__ l2w,
                                 const float* __restrict__ l2b,
                                 float* __restrict__ sub_out,
                                 float* __restrict__ graph_out,
                                 float* __restrict__ logits_out) {
    __shared__ float sa0[NPG];
    __shared__ float ssub[HH];
    __shared__ float red0[HH], red1[HH];
    const int g = blockIdx.x, t = threadIdx.x;
    if (t < NPG) sa0[t] = Aa[(g * NPG + t) * 2];
    float sf, bf;
    bn_sb(st2, gamma2, beta2, t, sf, bf);
    __syncthreads();
    float sh = 0.f, ss = 0.f;
    const size_t base = (size_t)g * NPG * HH;
    for (int r = 0; r < NPG; ++r) {
        float hv = sf * Z[base + r * HH + t] + bf;
        sh += hv;
        ss += sa0[r] * hv;
    }
    sub_out[g * HH + t] = ss;
    graph_out[g * HH + t] = sh * (1.f / NPG);
    ssub[t] = ss;
    __syncthreads();
    float acc = l1b[t];
    #pragma unroll 8
    for (int k = 0; k < HH; ++k) acc += ssub[k] * l1w[k * HH + t];
    float zc = fmaxf(acc, 0.f);
    red0[t] = zc * l2w[t * 2 + 0];
    red1[t] = zc * l2w[t * 2 + 1];
    __syncthreads();
    for (int s = 128; s > 0; s >>= 1) {
        if (t < s) { red0[t] += red0[t + s]; red1[t] += red1[t + s]; }
        __syncthreads();
    }
    if (t == 0) {
        float s0 = red0[0] + l2b[0], s1 = red1[0] + l2b[1];
        float m = fmaxf(s0, s1);
        float lse = m + logf(expf(s0 - m) + expf(s1 - m));
        logits_out[g * 2 + 0] = s0 - lse;
        logits_out[g * 2 + 1] = s1 - lse;
    }
}

// -------- pooled adjacency diag penalty + mean (block per graph) ------------
__global__ void adj_pen_kernel(const float* __restrict__ Aa,
                               const int* __restrict__ src,
                               const int* __restrict__ dst,
                               float* __restrict__ out_pen) {
    const int g = blockIdx.x, t = threadIdx.x;
    float m00 = 0.f, m01 = 0.f, m10 = 0.f, m11 = 0.f;
    for (int e = t; e < EPG; e += 128) {
        int se = src[g * EPG + e], de = dst[g * EPG + e];
        float a0 = Aa[se * 2], a1 = Aa[se * 2 + 1];
        float b0 = Aa[de * 2], b1 = Aa[de * 2 + 1];
        m00 += a0 * b0; m01 += a0 * b1;
        m10 += a1 * b0; m11 += a1 * b1;
    }
    __shared__ float red[4][128];
    red[0][t] = m00; red[1][t] = m01; red[2][t] = m10; red[3][t] = m11;
    __syncthreads();
    for (int s = 64; s > 0; s >>= 1) {
        if (t < s) {
            red[0][t] += red[0][t + s]; red[1][t] += red[1][t + s];
            red[2][t] += red[2][t + s]; red[3][t] += red[3][t + s];
        }
        __syncthreads();
    }
    if (t == 0) {
        float r0 = fmaxf(fabsf(red[0][0]) + fabsf(red[1][0]), 1e-12f);
        float r1 = fmaxf(fabsf(red[2][0]) + fabsf(red[3][0]), 1e-12f);
        float e0 = red[0][0] / r0 - 1.f;
        float e1 = red[3][0] / r1 - 1.f;
        atomicAdd(out_pen, 0.5f * (e0 * e0 + e1 * e1) * (1.f / BB));
    }
}

// ---------------- launch ------------------------------------------------------
extern "C" void kernel_launch(void* const* d_in, const int* in_sizes, int n_in,
                              void* d_out, int out_size) {
    const float* x    = (const float*)d_in[0];
    const int*   ei   = (const int*)d_in[1];
    const int*   src  = ei;
    const int*   dst  = ei + EE;
    const float* w0_1 = (const float*)d_in[3];
    const float* b0_1 = (const float*)d_in[4];
    const float* w0_2 = (const float*)d_in[5];
    const float* b0_2 = (const float*)d_in[6];
    const float* g0   = (const float*)d_in[7];
    const float* be0  = (const float*)d_in[8];
    const float* wl1  = (const float*)d_in[9];
    const float* bl1  = (const float*)d_in[10];
    const float* wl2  = (const float*)d_in[11];
    const float* bl2  = (const float*)d_in[12];
    const float* gl   = (const float*)d_in[13];
    const float* bel  = (const float*)d_in[14];
    const float* c1w  = (const float*)d_in[15];
    const float* c1b  = (const float*)d_in[16];
    const float* c2w  = (const float*)d_in[17];
    const float* c2b  = (const float*)d_in[18];
    const float* l1w  = (const float*)d_in[19];
    const float* l1b  = (const float*)d_in[20];
    const float* l2w  = (const float*)d_in[21];
    const float* l2b  = (const float*)d_in[22];

    float* out        = (float*)d_out;
    float* out_logits = out;
    float* out_sub    = out + BB * 2;
    float* out_graph  = out + BB * 2 + BB * HH;
    float* out_pen    = out + BB * 2 + 2 * BB * HH;

    float *zb, *tb, *hb, *ab, *alog, *stats;
    cudaGetSymbolAddress((void**)&zb, d_z);
    cudaGetSymbolAddress((void**)&tb, d_t);
    cudaGetSymbolAddress((void**)&hb, d_h);
    cudaGetSymbolAddress((void**)&ab, d_a);
    cudaGetSymbolAddress((void**)&alog, d_alog);
    cudaGetSymbolAddress((void**)&stats, d_stats);
    int* degp;
    cudaGetSymbolAddress((void**)&degp, d_deg);
    __nv_bfloat16 *wth, *wtl;
    cudaGetSymbolAddress((void**)&wth, d_wth);
    cudaGetSymbolAddress((void**)&wtl, d_wtl);

    cudaFuncSetAttribute(gemm_g1<false>,
                         cudaFuncAttributeMaxDynamicSharedMemorySize, GEMM_SMEM_BYTES);
    cudaFuncSetAttribute(gemm_g1<true>,
                         cudaFuncAttributeMaxDynamicSharedMemorySize, GEMM_SMEM_BYTES);
    cudaFuncSetAttribute(gemm_g2<false>,
                         cudaFuncAttributeMaxDynamicSharedMemorySize, GEMM_SMEM_BYTES);
    cudaFuncSetAttribute(gemm_g2<true>,
                         cudaFuncAttributeMaxDynamicSharedMemorySize, GEMM_SMEM_BYTES);
    cudaFuncSetAttribute(gemm_c1,
                         cudaFuncAttributeMaxDynamicSharedMemorySize, GEMM_SMEM_BYTES);

    const int O_W01 = 0;
    const int O_W02 = 32768;
    const int O_L1A = 98304;
    const int O_L2A = 163840;
    const int O_L1B = 229376;
    const int O_L2B = 294912;
    const int O_C1  = 360448;

    const dim3 gemm_grid(HH / 128, NN / 128);

    wsplit_all_kernel<<<(WSPLIT_TOTAL + 255) / 256, 256>>>(
        w0_1, w0_2, wl1, wl2, c1w, wth, wtl, out_pen);                    // 0
    csr_kernel<<<BB, NPG>>>(src, dst);                                    // 1
    agg_gather_x<<<NN / 8, 256>>>(x, hb);                                 // 2
    // ---- layer 0 ----
    gemm_g1<false><<<gemm_grid, 256, GEMM_SMEM_BYTES>>>(                  // 3 (profiled)
        hb, wth + O_W01, wtl + O_W01, b0_1, tb, FIN,
        nullptr, nullptr, nullptr, nullptr);
    gemm_g2<true><<<gemm_grid, 256, GEMM_SMEM_BYTES>>>(                   // 4
        tb, wth + O_W02, wtl + O_W02, b0_2, hb, HH, stats);
    // ---- layer 1 ----
    gemm_g1<true><<<gemm_grid, 256, GEMM_SMEM_BYTES>>>(
        hb, wth + O_L1A, wtl + O_L1A, bl1, tb, HH, degp, stats, g0, be0);
    gemm_g2<true><<<gemm_grid, 256, GEMM_SMEM_BYTES>>>(
        tb, wth + O_L2A, wtl + O_L2A, bl2, hb, HH, stats + 2 * HH);
    // ---- layer 2 ----
    gemm_g1<true><<<gemm_grid, 256, GEMM_SMEM_BYTES>>>(
        hb, wth + O_L1B, wtl + O_L1B, bl1 + HH, tb, HH, degp,
        stats + 2 * HH, gl, bel);
    gemm_g2<false><<<gemm_grid, 256, GEMM_SMEM_BYTES>>>(
        tb, wth + O_L2B, wtl + O_L2B, bl2 + HH, zb, HH, stats + 4 * HH);

    // ---- assignment: c1 GEMM (inline BN2 affine) + fused c2 proj ----
    gemm_c1<<<gemm_grid, 256, GEMM_SMEM_BYTES>>>(
        zb, wth + O_C1, wtl + O_C1, c1b, HH,
        stats + 4 * HH, gl + HH, bel + HH, c2w, alog);
    softmax2_kernel<<<NN / 256, 256>>>(alog, c2b, ab);

    // ---- pooling+head / adjacency penalty ----
    pool_head_kernel<<<BB, 256>>>(zb, ab, stats + 4 * HH, gl + HH, bel + HH,
                                  l1w, l1b, l2w, l2b,
                                  out_sub, out_graph, out_logits);
    adj_pen_kernel<<<BB, 128>>>(ab, src, dst, out_pen);
}

// round 16
// speedup vs baseline: 1.4064x; 1.1544x over previous
#include <cuda_runtime.h>
#include <cuda_fp16.h>
#include <math.h>

// Problem constants (fixed by setup_inputs)
#define NN      65536
#define BB      512
#define NPG     128
#define EE      262144
#define EPG     512
#define HH      256
#define FIN     128
#define BN_EPS  1e-5f

// ---------------- scratch (device globals; no cudaMalloc allowed) ----------
__device__ float d_z[NN * HH];
__device__ float d_t[NN * HH];
__device__ float d_h[NN * HH];
__device__ float d_a[NN * 2];
__device__ float d_alog[NN * 2];
__device__ float d_stats[3 * 2 * HH];   // per layer: [sum(256) | sumsq(256)]
__device__ int   d_csr[EE];
__device__ int   d_rowstart[NN];
__device__ int   d_deg[NN];
#define WSPLIT_TOTAL (256 * (128 + 6 * 256))
__device__ __half d_wfh[WSPLIT_TOTAL];   // single fp16 weight plane

// ---------------- helpers ----------------------------------------------------
__device__ __forceinline__ unsigned smem_u32(const void* p) {
    return (unsigned)__cvta_generic_to_shared(p);
}
__device__ __forceinline__ void ldsm_x4(unsigned addr, unsigned& r0, unsigned& r1,
                                        unsigned& r2, unsigned& r3) {
    asm volatile("ldmatrix.sync.aligned.m8n8.x4.shared.b16 {%0,%1,%2,%3}, [%4];"
                 : "=r"(r0), "=r"(r1), "=r"(r2), "=r"(r3) : "r"(addr));
}
__device__ __forceinline__ void ldsm_x4t(unsigned addr, unsigned& r0, unsigned& r1,
                                         unsigned& r2, unsigned& r3) {
    asm volatile("ldmatrix.sync.aligned.m8n8.x4.trans.shared.b16 {%0,%1,%2,%3}, [%4];"
                 : "=r"(r0), "=r"(r1), "=r"(r2), "=r"(r3) : "r"(addr));
}
__device__ __forceinline__ void mma_f16(float* d, const unsigned* a,
                                        unsigned b0, unsigned b1) {
    asm volatile("mma.sync.aligned.m16n8k16.row.col.f32.f16.f16.f32 "
                 "{%0,%1,%2,%3}, {%4,%5,%6,%7}, {%8,%9}, {%0,%1,%2,%3};"
                 : "+f"(d[0]), "+f"(d[1]), "+f"(d[2]), "+f"(d[3])
                 : "r"(a[0]), "r"(a[1]), "r"(a[2]), "r"(a[3]), "r"(b0), "r"(b1));
}
__device__ __forceinline__ void split_f16(float v, __half& h, __half& l) {
    h = __float2half(v);
    l = __float2half(v - __half2float(h));
}
__device__ __forceinline__ void bn_sb(const float* __restrict__ st,
                                      const float* __restrict__ gamma,
                                      const float* __restrict__ beta,
                                      int f, float& s, float& b) {
    const float inv_n = 1.f / NN;
    float mu  = st[f] * inv_n;
    float var = st[HH + f] * inv_n - mu * mu;
    s = rsqrtf(var + BN_EPS) * gamma[f];
    b = beta[f] - mu * s;
}
#define CP_ASYNC16(dst, src) \
    asm volatile("cp.async.cg.shared.global [%0], [%1], 16;" \
                 :: "r"(dst), "l"(src))
#define CP_COMMIT() asm volatile("cp.async.commit_group;")
#define CP_WAIT0()  asm volatile("cp.async.wait_group 0;")

// ---------------- weight prep + scratch zeroing ------------------------------
__global__ void wsplit_all_kernel(const float* __restrict__ w01,
                                  const float* __restrict__ w02,
                                  const float* __restrict__ wl1,
                                  const float* __restrict__ wl2,
                                  const float* __restrict__ c1w,
                                  __half* __restrict__ oh,
                                  float* __restrict__ out_pen) {
    int id = blockIdx.x * 256 + threadIdx.x;
    if (id == 0) out_pen[0] = 0.f;
    if (id < 3 * 2 * HH) d_stats[id] = 0.f;
    if (id < NN * 2) d_alog[id] = 0.f;
    if (id >= WSPLIT_TOTAL) return;
    const float* src;
    if (id < 32768) {
        src = w01 + id;
    } else {
        int r = id - 32768;
        int m = r >> 16, off = r & 65535;
        const float* bases[6] = {w02, wl1, wl2, wl1 + 65536, wl2 + 65536, c1w};
        src = bases[m] + off;
    }
    oh[id] = __float2half(*src);
}

// ---------------- CSR build (atomic, one block/graph) -----------------------
__global__ void csr_kernel(const int* __restrict__ src,
                           const int* __restrict__ dst) {
    __shared__ int cnt[NPG];
    __shared__ int sscan[NPG];
    __shared__ int pos[NPG];
    const int g = blockIdx.x, t = threadIdx.x;
    const int ebase = g * EPG;
    cnt[t] = 0;
    __syncthreads();
    int mys[4], myd[4];
    #pragma unroll
    for (int i = 0; i < 4; ++i) {
        int e = ebase + t * 4 + i;
        mys[i] = src[e];
        myd[i] = dst[e] - g * NPG;
        atomicAdd(&cnt[myd[i]], 1);
    }
    __syncthreads();
    int c = cnt[t];
    sscan[t] = c;
    __syncthreads();
    for (int off = 1; off < NPG; off <<= 1) {
        int v = (t >= off) ? sscan[t - off] : 0;
        __syncthreads();
        sscan[t] += v;
        __syncthreads();
    }
    int excl = sscan[t] - c;
    d_rowstart[g * NPG + t] = ebase + excl;
    d_deg[g * NPG + t] = c;
    pos[t] = ebase + excl;
    __syncthreads();
    #pragma unroll
    for (int i = 0; i < 4; ++i) {
        int p = atomicAdd(&pos[myd[i]], 1);
        d_csr[p] = mys[i];
    }
}

// -------- gather aggregation (first layer only, on x) -----------------------
__global__ void agg_gather_x(const float* __restrict__ h,
                             float* __restrict__ z) {
    const int node = blockIdx.x * 8 + (threadIdx.x >> 5);
    const int lane = threadIdx.x & 31;
    const int s = d_rowstart[node];
    const int dg = d_deg[node];
    const int c0 = lane * 4;
    const size_t rb = (size_t)node * FIN;
    float4 a0 = *reinterpret_cast<const float4*>(&h[rb + c0]);
    for (int e = 0; e < dg; ++e) {
        const size_t sb = (size_t)__ldg(&d_csr[s + e]) * FIN;
        float4 b0 = *reinterpret_cast<const float4*>(&h[sb + c0]);
        a0.x += b0.x; a0.y += b0.y; a0.z += b0.z; a0.w += b0.w;
    }
    *reinterpret_cast<float4*>(&z[rb + c0]) = a0;
}

// ------- fp16x2 HMMA GEMM (single mid-loop barrier schedule) ----------------
// A split fp16 hi/lo; W single fp16. 2 MMA passes per k16: AhW + AlW.
#define LDA 40
#define LDW 136
#define SM_AH  0
#define SM_AL  10240
#define SM_WH  20480
#define GEMM_SMEM_BYTES 67584   // covers GEMM (58368B) and fp32 agg tile

#define TILE_LD 132   // fp32 agg tile row stride (16B-aligned)

#define GEMM_LOAD_A(it) do {                                                  \
    const int k0 = (it) * 32;                                                 \
    _Pragma("unroll")                                                         \
    for (int i = 0; i < 4; ++i) {                                             \
        int idx = tid + i * 256;                                              \
        int row = idx >> 3;                                                   \
        int c = (idx & 7) * 4;                                                \
        a_reg[i] = *reinterpret_cast<const float4*>(                          \
            &A[(size_t)(rowBase + row) * K + k0 + c]);                        \
        if (ASB) {                                                            \
            float4 sv = *reinterpret_cast<const float4*>(&asb[k0 + c]);       \
            float4 bv = *reinterpret_cast<const float4*>(&asb[HH + k0 + c]);  \
            a_reg[i].x = sv.x * a_reg[i].x + dp1r[i] * bv.x;                  \
            a_reg[i].y = sv.y * a_reg[i].y + dp1r[i] * bv.y;                  \
            a_reg[i].z = sv.z * a_reg[i].z + dp1r[i] * bv.z;                  \
            a_reg[i].w = sv.w * a_reg[i].w + dp1r[i] * bv.w;                  \
        }                                                                     \
    }                                                                         \
} while (0)

#define GEMM_STORE_A(buf) do {                                                \
    __half* ah = sm + SM_AH + (buf) * 5120;                                   \
    __half* al = sm + SM_AL + (buf) * 5120;                                   \
    _Pragma("unroll")                                                         \
    for (int i = 0; i < 4; ++i) {                                             \
        int idx = tid + i * 256;                                              \
        int row = idx >> 3;                                                   \
        int c = (idx & 7) * 4;                                                \
        float vv[4] = {a_reg[i].x, a_reg[i].y, a_reg[i].z, a_reg[i].w};       \
        unsigned hp[2], lp[2];                                                \
        _Pragma("unroll")                                                     \
        for (int q = 0; q < 2; ++q) {                                         \
            __half h0, l0, h1, l1;                                            \
            split_f16(vv[2 * q], h0, l0);                                     \
            split_f16(vv[2 * q + 1], h1, l1);                                 \
            hp[q] = ((unsigned)__half_as_ushort(h1) << 16) |                  \
                    __half_as_ushort(h0);                                     \
            lp[q] = ((unsigned)__half_as_ushort(l1) << 16) |                  \
                    __half_as_ushort(l0);                                     \
        }                                                                     \
        *reinterpret_cast<uint2*>(&ah[row * LDA + c]) =                       \
            make_uint2(hp[0], hp[1]);                                         \
        *reinterpret_cast<uint2*>(&al[row * LDA + c]) =                       \
            make_uint2(lp[0], lp[1]);                                         \
    }                                                                         \
} while (0)

#define GEMM_CP_W(it, buf) do {                                               \
    const int k0 = (it) * 32;                                                 \
    __half* wh = sm + SM_WH + (buf) * 4352;                                   \
    _Pragma("unroll")                                                         \
    for (int i = 0; i < 2; ++i) {                                             \
        int idx = tid + i * 256;                                              \
        int row = idx >> 4;                                                   \
        int c8 = (idx & 15) * 8;                                              \
        size_t go = (size_t)(k0 + row) * HH + colBase + c8;                   \
        CP_ASYNC16(smem_u32(&wh[row * LDW + c8]), &Wh[go]);                   \
    }                                                                         \
    CP_COMMIT();                                                              \
} while (0)

#define GEMM_MAINLOOP()                                                       \
    GEMM_LOAD_A(0);                                                           \
    GEMM_CP_W(0, 0);                                                          \
    for (int it = 0; it < niter; ++it) {                                      \
        const int buf = it & 1;                                               \
        GEMM_STORE_A(buf);                                                    \
        if (it + 1 < niter) GEMM_LOAD_A(it + 1);                              \
        CP_WAIT0();                                                           \
        __syncthreads();                                                      \
        if (it + 1 < niter) GEMM_CP_W(it + 1, buf ^ 1);                       \
        const __half* ah = sm + SM_AH + buf * 5120;                           \
        const __half* al = sm + SM_AL + buf * 5120;                           \
        const __half* wh = sm + SM_WH + buf * 4352;                           \
        _Pragma("unroll")                                                     \
        for (int ks = 0; ks < 2; ++ks) {                                      \
            const int kb = ks * 16;                                           \
            unsigned afr[2][2][4];                                            \
            _Pragma("unroll")                                                 \
            for (int mt = 0; mt < 2; ++mt) {                                  \
                int row = warp_m * 32 + mt * 16 + a_row_off;                  \
                int col = kb + a_col_off;                                     \
                ldsm_x4(smem_u32(&ah[row * LDA + col]),                       \
                        afr[0][mt][0], afr[0][mt][1], afr[0][mt][2],          \
                        afr[0][mt][3]);                                       \
                ldsm_x4(smem_u32(&al[row * LDA + col]),                       \
                        afr[1][mt][0], afr[1][mt][1], afr[1][mt][2],          \
                        afr[1][mt][3]);                                       \
            }                                                                 \
            unsigned bfr[4][4];                                               \
            _Pragma("unroll")                                                 \
            for (int p = 0; p < 4; ++p) {                                     \
                int kk = kb + b_k_off;                                        \
                int nn = warp_n * 64 + p * 16 + b_n_off;                      \
                ldsm_x4t(smem_u32(&wh[kk * LDW + nn]),                        \
                         bfr[p][0], bfr[p][1], bfr[p][2], bfr[p][3]);         \
            }                                                                 \
            _Pragma("unroll")                                                 \
            for (int s = 0; s < 2; ++s)                                       \
                _Pragma("unroll")                                             \
                for (int mt = 0; mt < 2; ++mt)                                \
                    _Pragma("unroll")                                         \
                    for (int p = 0; p < 4; ++p) {                             \
                        mma_f16(acc[mt][2 * p],     afr[s][mt],               \
                                bfr[p][0], bfr[p][1]);                        \
                        mma_f16(acc[mt][2 * p + 1], afr[s][mt],               \
                                bfr[p][2], bfr[p][3]);                        \
                    }                                                         \
        }                                                                     \
    }

// ---- G1: plain or row/col-BN affine on A; bias+ReLU; store C ---------------
template <bool ROWBN>
__global__ void __launch_bounds__(256)
gemm_g1(const float* __restrict__ A,
        const __half* __restrict__ Wh,
        const float* __restrict__ bias, float* __restrict__ C, int K,
        const int* __restrict__ deg,
        const float* __restrict__ st,
        const float* __restrict__ gamma,
        const float* __restrict__ beta) {
    extern __shared__ __half sm[];
    __shared__ float s_asb[2 * HH];
    const int tid = threadIdx.x;
    const int lane = tid & 31;
    const int wid = tid >> 5;
    const int warp_m = wid & 3;
    const int warp_n = wid >> 2;
    const int rowBase = blockIdx.y * 128;
    const int colBase = blockIdx.x * 128;
    const bool ASB = ROWBN;

    float dp1r[4] = {1.f, 1.f, 1.f, 1.f};
    if (ROWBN) {
        float sv, bv;
        bn_sb(st, gamma, beta, tid, sv, bv);
        s_asb[tid] = sv;
        s_asb[HH + tid] = bv;
        #pragma unroll
        for (int i = 0; i < 4; ++i)
            dp1r[i] = 1.f + (float)deg[rowBase + ((tid + i * 256) >> 3)];
        __syncthreads();
    }
    const float* asb = s_asb;

    float acc[2][8][4] = {};
    float4 a_reg[4];

    const int lg = lane >> 3, lj = lane & 7;
    const int a_row_off = (lg & 1) * 8 + lj;
    const int a_col_off = (lg >> 1) * 8;
    const int b_k_off = (lg & 1) * 8 + lj;
    const int b_n_off = (lg >> 1) * 8;

    const int niter = K >> 5;
    GEMM_MAINLOOP();

    const int g = lane >> 2, tq = lane & 3;
    #pragma unroll
    for (int mt = 0; mt < 2; ++mt) {
        #pragma unroll
        for (int nt = 0; nt < 8; ++nt) {
            int row0 = rowBase + warp_m * 32 + mt * 16 + g;
            int col = colBase + warp_n * 64 + nt * 8 + 2 * tq;
            float b0 = bias[col], b1 = bias[col + 1];
            *reinterpret_cast<float2*>(&C[(size_t)row0 * HH + col]) =
                make_float2(fmaxf(acc[mt][nt][0] + b0, 0.f),
                            fmaxf(acc[mt][nt][1] + b1, 0.f));
            *reinterpret_cast<float2*>(&C[(size_t)(row0 + 8) * HH + col]) =
                make_float2(fmaxf(acc[mt][nt][2] + b0, 0.f),
                            fmaxf(acc[mt][nt][3] + b1, 0.f));
        }
    }
}

// ---- G2: bias+ReLU + BN stats; AGG ? (aggregate in smem, write raw-agg)
//                                 : (store z to C) ---------------------------
template <bool AGG>
__global__ void __launch_bounds__(256)
gemm_g2(const float* __restrict__ A,
        const __half* __restrict__ Wh,
        const float* __restrict__ bias, float* __restrict__ C,
        int K, float* __restrict__ stats) {
    extern __shared__ __half sm[];
    __shared__ float s_sum[128], s_sq[128];

    const int tid = threadIdx.x;
    const int lane = tid & 31;
    const int wid = tid >> 5;
    const int warp_m = wid & 3;
    const int warp_n = wid >> 2;
    const int rowBase = blockIdx.y * 128;
    const int colBase = blockIdx.x * 128;
    const bool ASB = false;
    const float* asb = nullptr;
    float dp1r[4] = {1.f, 1.f, 1.f, 1.f};
    (void)asb; (void)dp1r;

    if (tid < 128) { s_sum[tid] = 0.f; s_sq[tid] = 0.f; }

    float acc[2][8][4] = {};
    float4 a_reg[4];

    const int lg = lane >> 3, lj = lane & 7;
    const int a_row_off = (lg & 1) * 8 + lj;
    const int a_col_off = (lg >> 1) * 8;
    const int b_k_off = (lg & 1) * 8 + lj;
    const int b_n_off = (lg >> 1) * 8;

    const int niter = K >> 5;
    GEMM_MAINLOOP();
    __syncthreads();   // drain last-iter smem reads before epilogue reuse

    float* tile = reinterpret_cast<float*>(sm);   // 128 x TILE_LD fp32 (AGG)

    const int g = lane >> 2, tq = lane & 3;
    float cs[16], cq[16];
    #pragma unroll
    for (int i = 0; i < 16; ++i) { cs[i] = 0.f; cq[i] = 0.f; }
    #pragma unroll
    for (int mt = 0; mt < 2; ++mt) {
        #pragma unroll
        for (int nt = 0; nt < 8; ++nt) {
            int lr = warp_m * 32 + mt * 16 + g;
            int lc = warp_n * 64 + nt * 8 + 2 * tq;
            float b0 = bias[colBase + lc], b1 = bias[colBase + lc + 1];
            float v[4] = {fmaxf(acc[mt][nt][0] + b0, 0.f),
                          fmaxf(acc[mt][nt][1] + b1, 0.f),
                          fmaxf(acc[mt][nt][2] + b0, 0.f),
                          fmaxf(acc[mt][nt][3] + b1, 0.f)};
            cs[nt * 2 + 0] += v[0] + v[2];
            cs[nt * 2 + 1] += v[1] + v[3];
            cq[nt * 2 + 0] += v[0] * v[0] + v[2] * v[2];
            cq[nt * 2 + 1] += v[1] * v[1] + v[3] * v[3];
            if (AGG) {
                *reinterpret_cast<float2*>(&tile[lr * TILE_LD + lc]) =
                    make_float2(v[0], v[1]);
                *reinterpret_cast<float2*>(&tile[(lr + 8) * TILE_LD + lc]) =
                    make_float2(v[2], v[3]);
            } else {
                *reinterpret_cast<float2*>(
                    &C[(size_t)(rowBase + lr) * HH + colBase + lc]) =
                    make_float2(v[0], v[1]);
                *reinterpret_cast<float2*>(
                    &C[(size_t)(rowBase + lr + 8) * HH + colBase + lc]) =
                    make_float2(v[2], v[3]);
            }
        }
    }
    #pragma unroll
    for (int i = 0; i < 16; ++i) {
        #pragma unroll
        for (int off = 16; off >= 4; off >>= 1) {
            cs[i] += __shfl_down_sync(0xffffffffu, cs[i], off);
            cq[i] += __shfl_down_sync(0xffffffffu, cq[i], off);
        }
    }
    if (lane < 4) {
        #pragma unroll
        for (int nt = 0; nt < 8; ++nt) {
            #pragma unroll
            for (int c = 0; c < 2; ++c) {
                int lc = warp_n * 64 + nt * 8 + 2 * lane + c;
                atomicAdd(&s_sum[lc], cs[nt * 2 + c]);
                atomicAdd(&s_sq[lc], cq[nt * 2 + c]);
            }
        }
    }
    __syncthreads();   // s_sum/s_sq final; (AGG) tile fully written
    {
        int c = tid & 127;
        if (tid < 128) atomicAdd(&stats[colBase + c], s_sum[c]);
        else           atomicAdd(&stats[HH + colBase + c], s_sq[c]);
    }
    if (AGG) {
        const int gph = blockIdx.y;
        const int c0 = lane * 4;
        #pragma unroll
        for (int rr = 0; rr < 16; ++rr) {
            int r = wid * 16 + rr;
            int node = gph * NPG + r;
            int st_ = d_rowstart[node];
            int dgn = d_deg[node];
            float4 a4 = *reinterpret_cast<float4*>(&tile[r * TILE_LD + c0]);
            for (int e = 0; e < dgn; ++e) {
                int sl = __ldg(&d_csr[st_ + e]) - gph * NPG;
                float4 b4 = *reinterpret_cast<float4*>(&tile[sl * TILE_LD + c0]);
                a4.x += b4.x; a4.y += b4.y; a4.z += b4.z; a4.w += b4.w;
            }
            *reinterpret_cast<float4*>(&C[(size_t)node * HH + colBase + c0]) = a4;
        }
    }
}

// ------- c1 GEMM: inline bn2 affine on A, tanh, fused c2 proj -> logits -----
__global__ void __launch_bounds__(256)
gemm_c1(const float* __restrict__ A,
        const __half* __restrict__ Wh,
        const float* __restrict__ bias,
        int K,
        const float* __restrict__ st2,
        const float* __restrict__ gamma2,
        const float* __restrict__ beta2,
        const float* __restrict__ c2w, float* __restrict__ alog) {
    extern __shared__ __half sm[];
    __shared__ float s_asb[2 * HH];
    const int tid = threadIdx.x;
    const int lane = tid & 31;
    const int wid = tid >> 5;
    const int warp_m = wid & 3;
    const int warp_n = wid >> 2;
    const int rowBase = blockIdx.y * 128;
    const int colBase = blockIdx.x * 128;
    const bool ASB = true;
    float dp1r[4] = {1.f, 1.f, 1.f, 1.f};

    {
        float sv, bv;
        bn_sb(st2, gamma2, beta2, tid, sv, bv);
        s_asb[tid] = sv;
        s_asb[HH + tid] = bv;
    }
    __syncthreads();
    const float* asb = s_asb;

    float acc[2][8][4] = {};
    float4 a_reg[4];

    const int lg = lane >> 3, lj = lane & 7;
    const int a_row_off = (lg & 1) * 8 + lj;
    const int a_col_off = (lg >> 1) * 8;
    const int b_k_off = (lg & 1) * 8 + lj;
    const int b_n_off = (lg >> 1) * 8;

    const int niter = K >> 5;
    GEMM_MAINLOOP();

    const int g = lane >> 2, tq = lane & 3;
    float p[2][2][2] = {};
    #pragma unroll
    for (int mt = 0; mt < 2; ++mt) {
        #pragma unroll
        for (int nt = 0; nt < 8; ++nt) {
            int col = colBase + warp_n * 64 + nt * 8 + 2 * tq;
            float b0 = bias[col], b1 = bias[col + 1];
            float v0 = tanhf(acc[mt][nt][0] + b0);
            float v1 = tanhf(acc[mt][nt][1] + b1);
            float v2 = tanhf(acc[mt][nt][2] + b0);
            float v3 = tanhf(acc[mt][nt][3] + b1);
            float w00 = __ldg(&c2w[col * 2 + 0]);
            float w01 = __ldg(&c2w[col * 2 + 1]);
            float w10 = __ldg(&c2w[col * 2 + 2]);
            float w11 = __ldg(&c2w[col * 2 + 3]);
            p[mt][0][0] += v0 * w00 + v1 * w10;
            p[mt][0][1] += v0 * w01 + v1 * w11;
            p[mt][1][0] += v2 * w00 + v3 * w10;
            p[mt][1][1] += v2 * w01 + v3 * w11;
        }
    }
    #pragma unroll
    for (int mt = 0; mt < 2; ++mt)
        #pragma unroll
        for (int hh = 0; hh < 2; ++hh)
            #pragma unroll
            for (int c = 0; c < 2; ++c) {
                float v = p[mt][hh][c];
                v += __shfl_xor_sync(0xffffffffu, v, 1);
                v += __shfl_xor_sync(0xffffffffu, v, 2);
                p[mt][hh][c] = v;
            }
    if (tq == 0) {
        #pragma unroll
        for (int mt = 0; mt < 2; ++mt)
            #pragma unroll
            for (int hh = 0; hh < 2; ++hh) {
                int row = rowBase + warp_m * 32 + mt * 16 + g + hh * 8;
                atomicAdd(&alog[row * 2 + 0], p[mt][hh][0]);
                atomicAdd(&alog[row * 2 + 1], p[mt][hh][1]);
            }
    }
}

// ---------------- softmax over fused logits ---------------------------------
__global__ void softmax2_kernel(const float* __restrict__ alog,
                                const float* __restrict__ c2b,
                                float* __restrict__ Aout) {
    const int r = blockIdx.x * 256 + threadIdx.x;
    float s0 = alog[2 * r + 0] + c2b[0];
    float s1 = alog[2 * r + 1] + c2b[1];
    float m = fmaxf(s0, s1);
    float e0 = expf(s0 - m), e1 = expf(s1 - m);
    float inv = 1.f / (e0 + e1);
    Aout[2 * r + 0] = e0 * inv;
    Aout[2 * r + 1] = e1 * inv;
}

// -------- pooling + classifier head fused (block per graph) -----------------
__global__ void pool_head_kernel(const float* __restrict__ Z,
                                 const float* __restrict__ Aa,
                                 const float* __restrict__ st2,
                                 const float* __restrict__ gamma2,
                                 const float* __restrict__ beta2,
                                 const float* __restrict__ l1w,
                                 const float* __restrict__ l1b,
                                 const float* __restrict__ l2w,
                                 const float* __restrict__ l2b,
                                 float* __restrict__ sub_out,
                                 float* __restrict__ graph_out,
                                 float* __restrict__ logits_out) {
    __shared__ float sa0[NPG];
    __shared__ float ssub[HH];
    __shared__ float red0[HH], red1[HH];
    const int g = blockIdx.x, t = threadIdx.x;
    if (t < NPG) sa0[t] = Aa[(g * NPG + t) * 2];
    float sf, bf;
    bn_sb(st2, gamma2, beta2, t, sf, bf);
    __syncthreads();
    float sh = 0.f, ss = 0.f;
    const size_t base = (size_t)g * NPG * HH;
    for (int r = 0; r < NPG; ++r) {
        float hv = sf * Z[base + r * HH + t] + bf;
        sh += hv;
        ss += sa0[r] * hv;
    }
    sub_out[g * HH + t] = ss;
    graph_out[g * HH + t] = sh * (1.f / NPG);
    ssub[t] = ss;
    __syncthreads();
    float acc = l1b[t];
    #pragma unroll 8
    for (int k = 0; k < HH; ++k) acc += ssub[k] * l1w[k * HH + t];
    float zc = fmaxf(acc, 0.f);
    red0[t] = zc * l2w[t * 2 + 0];
    red1[t] = zc * l2w[t * 2 + 1];
    __syncthreads();
    for (int s = 128; s > 0; s >>= 1) {
        if (t < s) { red0[t] += red0[t + s]; red1[t] += red1[t + s]; }
        __syncthreads();
    }
    if (t == 0) {
        float s0 = red0[0] + l2b[0], s1 = red1[0] + l2b[1];
        float m = fmaxf(s0, s1);
        float lse = m + logf(expf(s0 - m) + expf(s1 - m));
        logits_out[g * 2 + 0] = s0 - lse;
        logits_out[g * 2 + 1] = s1 - lse;
    }
}

// -------- pooled adjacency diag penalty + mean (block per graph) ------------
__global__ void adj_pen_kernel(const float* __restrict__ Aa,
                               const int* __restrict__ src,
                               const int* __restrict__ dst,
                               float* __restrict__ out_pen) {
    const int g = blockIdx.x, t = threadIdx.x;
    float m00 = 0.f, m01 = 0.f, m10 = 0.f, m11 = 0.f;
    for (int e = t; e < EPG; e += 128) {
        int se = src[g * EPG + e], de = dst[g * EPG + e];
        float a0 = Aa[se * 2], a1 = Aa[se * 2 + 1];
        float b0 = Aa[de * 2], b1 = Aa[de * 2 + 1];
        m00 += a0 * b0; m01 += a0 * b1;
        m10 += a1 * b0; m11 += a1 * b1;
    }
    __shared__ float red[4][128];
    red[0][t] = m00; red[1][t] = m01; red[2][t] = m10; red[3][t] = m11;
    __syncthreads();
    for (int s = 64; s > 0; s >>= 1) {
        if (t < s) {
            red[0][t] += red[0][t + s]; red[1][t] += red[1][t + s];
            red[2][t] += red[2][t + s]; red[3][t] += red[3][t + s];
        }
        __syncthreads();
    }
    if (t == 0) {
        float r0 = fmaxf(fabsf(red[0][0]) + fabsf(red[1][0]), 1e-12f);
        float r1 = fmaxf(fabsf(red[2][0]) + fabsf(red[3][0]), 1e-12f);
        float e0 = red[0][0] / r0 - 1.f;
        float e1 = red[3][0] / r1 - 1.f;
        atomicAdd(out_pen, 0.5f * (e0 * e0 + e1 * e1) * (1.f / BB));
    }
}

// ---------------- launch ------------------------------------------------------
extern "C" void kernel_launch(void* const* d_in, const int* in_sizes, int n_in,
                              void* d_out, int out_size) {
    const float* x    = (const float*)d_in[0];
    const int*   ei   = (const int*)d_in[1];
    const int*   src  = ei;
    const int*   dst  = ei + EE;
    const float* w0_1 = (const float*)d_in[3];
    const float* b0_1 = (const float*)d_in[4];
    const float* w0_2 = (const float*)d_in[5];
    const float* b0_2 = (const float*)d_in[6];
    const float* g0   = (const float*)d_in[7];
    const float* be0  = (const float*)d_in[8];
    const float* wl1  = (const float*)d_in[9];
    const float* bl1  = (const float*)d_in[10];
    const float* wl2  = (const float*)d_in[11];
    const float* bl2  = (const float*)d_in[12];
    const float* gl   = (const float*)d_in[13];
    const float* bel  = (const float*)d_in[14];
    const float* c1w  = (const float*)d_in[15];
    const float* c1b  = (const float*)d_in[16];
    const float* c2w  = (const float*)d_in[17];
    const float* c2b  = (const float*)d_in[18];
    const float* l1w  = (const float*)d_in[19];
    const float* l1b  = (const float*)d_in[20];
    const float* l2w  = (const float*)d_in[21];
    const float* l2b  = (const float*)d_in[22];

    float* out        = (float*)d_out;
    float* out_logits = out;
    float* out_sub    = out + BB * 2;
    float* out_graph  = out + BB * 2 + BB * HH;
    float* out_pen    = out + BB * 2 + 2 * BB * HH;

    float *zb, *tb, *hb, *ab, *alog, *stats;
    cudaGetSymbolAddress((void**)&zb, d_z);
    cudaGetSymbolAddress((void**)&tb, d_t);
    cudaGetSymbolAddress((void**)&hb, d_h);
    cudaGetSymbolAddress((void**)&ab, d_a);
    cudaGetSymbolAddress((void**)&alog, d_alog);
    cudaGetSymbolAddress((void**)&stats, d_stats);
    int* degp;
    cudaGetSymbolAddress((void**)&degp, d_deg);
    __half* wfh;
    cudaGetSymbolAddress((void**)&wfh, d_wfh);

    cudaFuncSetAttribute(gemm_g1<false>,
                         cudaFuncAttributeMaxDynamicSharedMemorySize, GEMM_SMEM_BYTES);
    cudaFuncSetAttribute(gemm_g1<true>,
                         cudaFuncAttributeMaxDynamicSharedMemorySize, GEMM_SMEM_BYTES);
    cudaFuncSetAttribute(gemm_g2<false>,
                         cudaFuncAttributeMaxDynamicSharedMemorySize, GEMM_SMEM_BYTES);
    cudaFuncSetAttribute(gemm_g2<true>,
                         cudaFuncAttributeMaxDynamicSharedMemorySize, GEMM_SMEM_BYTES);
    cudaFuncSetAttribute(gemm_c1,
                         cudaFuncAttributeMaxDynamicSharedMemorySize, GEMM_SMEM_BYTES);

    const int O_W01 = 0;
    const int O_W02 = 32768;
    const int O_L1A = 98304;
    const int O_L2A = 163840;
    const int O_L1B = 229376;
    const int O_L2B = 294912;
    const int O_C1  = 360448;

    const dim3 gemm_grid(HH / 128, NN / 128);

    wsplit_all_kernel<<<(WSPLIT_TOTAL + 255) / 256, 256>>>(
        w0_1, w0_2, wl1, wl2, c1w, wfh, out_pen);                         // 0
    csr_kernel<<<BB, NPG>>>(src, dst);                                    // 1
    agg_gather_x<<<NN / 8, 256>>>(x, hb);                                 // 2
    // ---- layer 0 ----
    gemm_g1<false><<<gemm_grid, 256, GEMM_SMEM_BYTES>>>(                  // 3 (profiled)
        hb, wfh + O_W01, b0_1, tb, FIN, nullptr, nullptr, nullptr, nullptr);
    gemm_g2<true><<<gemm_grid, 256, GEMM_SMEM_BYTES>>>(                   // 4
        tb, wfh + O_W02, b0_2, hb, HH, stats);
    // ---- layer 1 ----
    gemm_g1<true><<<gemm_grid, 256, GEMM_SMEM_BYTES>>>(
        hb, wfh + O_L1A, bl1, tb, HH, degp, stats, g0, be0);
    gemm_g2<true><<<gemm_grid, 256, GEMM_SMEM_BYTES>>>(
        tb, wfh + O_L2A, bl2, hb, HH, stats + 2 * HH);
    // ---- layer 2 ----
    gemm_g1<true><<<gemm_grid, 256, GEMM_SMEM_BYTES>>>(
        hb, wfh + O_L1B, bl1 + HH, tb, HH, degp, stats + 2 * HH, gl, bel);
    gemm_g2<false><<<gemm_grid, 256, GEMM_SMEM_BYTES>>>(
        tb, wfh + O_L2B, bl2 + HH, zb, HH, stats + 4 * HH);

    // ---- assignment: c1 GEMM (inline BN2 affine) + fused c2 proj ----
    gemm_c1<<<gemm_grid, 256, GEMM_SMEM_BYTES>>>(
        zb, wfh + O_C1, c1b, HH, stats + 4 * HH, gl + HH, bel + HH, c2w, alog);
    softmax2_kernel<<<NN / 256, 256>>>(alog, c2b, ab);

    // ---- pooling+head / adjacency penalty ----
    pool_head_kernel<<<BB, 256>>>(zb, ab, stats + 4 * HH, gl + HH, bel + HH,
                                  l1w, l1b, l2w, l2b,
                                  out_sub, out_graph, out_logits);
    adj_pen_kernel<<<BB, 128>>>(ab, src, dst, out_pen);
}

// round 17
// speedup vs baseline: 1.4329x; 1.0188x over previous
#include <cuda_runtime.h>
#include <cuda_fp16.h>
#include <math.h>

// Problem constants (fixed by setup_inputs)
#define NN      65536
#define BB      512
#define NPG     128
#define EE      262144
#define EPG     512
#define HH      256
#define FIN     128
#define BN_EPS  1e-5f

// ---------------- scratch (device globals; no cudaMalloc allowed) ----------
__device__ float d_z[NN * HH];
__device__ float d_t[NN * HH];
__device__ float d_h[NN * HH];
__device__ float d_alog[NN * 2];
__device__ float d_stats[3 * 2 * HH];   // per layer: [sum(256) | sumsq(256)]
__device__ int   d_csr[EE];
__device__ int   d_rowstart[NN];
__device__ int   d_deg[NN];
#define WSPLIT_TOTAL (256 * (128 + 6 * 256))
__device__ __half d_wfh[WSPLIT_TOTAL];   // single fp16 weight plane

// ---------------- helpers ----------------------------------------------------
__device__ __forceinline__ unsigned smem_u32(const void* p) {
    return (unsigned)__cvta_generic_to_shared(p);
}
__device__ __forceinline__ void ldsm_x4(unsigned addr, unsigned& r0, unsigned& r1,
                                        unsigned& r2, unsigned& r3) {
    asm volatile("ldmatrix.sync.aligned.m8n8.x4.shared.b16 {%0,%1,%2,%3}, [%4];"
                 : "=r"(r0), "=r"(r1), "=r"(r2), "=r"(r3) : "r"(addr));
}
__device__ __forceinline__ void ldsm_x4t(unsigned addr, unsigned& r0, unsigned& r1,
                                         unsigned& r2, unsigned& r3) {
    asm volatile("ldmatrix.sync.aligned.m8n8.x4.trans.shared.b16 {%0,%1,%2,%3}, [%4];"
                 : "=r"(r0), "=r"(r1), "=r"(r2), "=r"(r3) : "r"(addr));
}
__device__ __forceinline__ void mma_f16(float* d, const unsigned* a,
                                        unsigned b0, unsigned b1) {
    asm volatile("mma.sync.aligned.m16n8k16.row.col.f32.f16.f16.f32 "
                 "{%0,%1,%2,%3}, {%4,%5,%6,%7}, {%8,%9}, {%0,%1,%2,%3};"
                 : "+f"(d[0]), "+f"(d[1]), "+f"(d[2]), "+f"(d[3])
                 : "r"(a[0]), "r"(a[1]), "r"(a[2]), "r"(a[3]), "r"(b0), "r"(b1));
}
__device__ __forceinline__ void split_f16(float v, __half& h, __half& l) {
    h = __float2half(v);
    l = __float2half(v - __half2float(h));
}
__device__ __forceinline__ void bn_sb(const float* __restrict__ st,
                                      const float* __restrict__ gamma,
                                      const float* __restrict__ beta,
                                      int f, float& s, float& b) {
    const float inv_n = 1.f / NN;
    float mu  = st[f] * inv_n;
    float var = st[HH + f] * inv_n - mu * mu;
    s = rsqrtf(var + BN_EPS) * gamma[f];
    b = beta[f] - mu * s;
}
#define CP_ASYNC16(dst, src) \
    asm volatile("cp.async.cg.shared.global [%0], [%1], 16;" \
                 :: "r"(dst), "l"(src))
#define CP_COMMIT() asm volatile("cp.async.commit_group;")
#define CP_WAIT0()  asm volatile("cp.async.wait_group 0;")

// ---------------- weight prep + scratch zeroing ------------------------------
__global__ void wsplit_all_kernel(const float* __restrict__ w01,
                                  const float* __restrict__ w02,
                                  const float* __restrict__ wl1,
                                  const float* __restrict__ wl2,
                                  const float* __restrict__ c1w,
                                  __half* __restrict__ oh,
                                  float* __restrict__ out_pen) {
    int id = blockIdx.x * 256 + threadIdx.x;
    if (id == 0) out_pen[0] = 0.f;
    if (id < 3 * 2 * HH) d_stats[id] = 0.f;
    if (id < NN * 2) d_alog[id] = 0.f;
    if (id >= WSPLIT_TOTAL) return;
    const float* src;
    if (id < 32768) {
        src = w01 + id;
    } else {
        int r = id - 32768;
        int m = r >> 16, off = r & 65535;
        const float* bases[6] = {w02, wl1, wl2, wl1 + 65536, wl2 + 65536, c1w};
        src = bases[m] + off;
    }
    oh[id] = __float2half(*src);
}

// ---------------- CSR build (atomic, one block/graph) -----------------------
__global__ void csr_kernel(const int* __restrict__ src,
                           const int* __restrict__ dst) {
    __shared__ int cnt[NPG];
    __shared__ int sscan[NPG];
    __shared__ int pos[NPG];
    const int g = blockIdx.x, t = threadIdx.x;
    const int ebase = g * EPG;
    cnt[t] = 0;
    __syncthreads();
    int mys[4], myd[4];
    #pragma unroll
    for (int i = 0; i < 4; ++i) {
        int e = ebase + t * 4 + i;
        mys[i] = src[e];
        myd[i] = dst[e] - g * NPG;
        atomicAdd(&cnt[myd[i]], 1);
    }
    __syncthreads();
    int c = cnt[t];
    sscan[t] = c;
    __syncthreads();
    for (int off = 1; off < NPG; off <<= 1) {
        int v = (t >= off) ? sscan[t - off] : 0;
        __syncthreads();
        sscan[t] += v;
        __syncthreads();
    }
    int excl = sscan[t] - c;
    d_rowstart[g * NPG + t] = ebase + excl;
    d_deg[g * NPG + t] = c;
    pos[t] = ebase + excl;
    __syncthreads();
    #pragma unroll
    for (int i = 0; i < 4; ++i) {
        int p = atomicAdd(&pos[myd[i]], 1);
        d_csr[p] = mys[i];
    }
}

// -------- gather aggregation (first layer only, on x) -----------------------
__global__ void agg_gather_x(const float* __restrict__ h,
                             float* __restrict__ z) {
    const int node = blockIdx.x * 8 + (threadIdx.x >> 5);
    const int lane = threadIdx.x & 31;
    const int s = d_rowstart[node];
    const int dg = d_deg[node];
    const int c0 = lane * 4;
    const size_t rb = (size_t)node * FIN;
    float4 a0 = *reinterpret_cast<const float4*>(&h[rb + c0]);
    for (int e = 0; e < dg; ++e) {
        const size_t sb = (size_t)__ldg(&d_csr[s + e]) * FIN;
        float4 b0 = *reinterpret_cast<const float4*>(&h[sb + c0]);
        a0.x += b0.x; a0.y += b0.y; a0.z += b0.z; a0.w += b0.w;
    }
    *reinterpret_cast<float4*>(&z[rb + c0]) = a0;
}

// ------- fp16x2 HMMA GEMM (single mid-loop barrier schedule) ----------------
#define LDA 40
#define LDW 136
#define SM_AH  0
#define SM_AL  10240
#define SM_WH  20480
#define GEMM_SMEM_BYTES 67584   // covers GEMM (58368B) and fp32 agg tile
#define TILE_LD 132

#define GEMM_LOAD_A(it) do {                                                  \
    const int k0 = (it) * 32;                                                 \
    _Pragma("unroll")                                                         \
    for (int i = 0; i < 4; ++i) {                                             \
        int idx = tid + i * 256;                                              \
        int row = idx >> 3;                                                   \
        int c = (idx & 7) * 4;                                                \
        a_reg[i] = *reinterpret_cast<const float4*>(                          \
            &A[(size_t)(rowBase + row) * K + k0 + c]);                        \
        if (ASB) {                                                            \
            float4 sv = *reinterpret_cast<const float4*>(&asb[k0 + c]);       \
            float4 bv = *reinterpret_cast<const float4*>(&asb[HH + k0 + c]);  \
            a_reg[i].x = sv.x * a_reg[i].x + dp1r[i] * bv.x;                  \
            a_reg[i].y = sv.y * a_reg[i].y + dp1r[i] * bv.y;                  \
            a_reg[i].z = sv.z * a_reg[i].z + dp1r[i] * bv.z;                  \
            a_reg[i].w = sv.w * a_reg[i].w + dp1r[i] * bv.w;                  \
        }                                                                     \
    }                                                                         \
} while (0)

#define GEMM_STORE_A(buf) do {                                                \
    __half* ah = sm + SM_AH + (buf) * 5120;                                   \
    __half* al = sm + SM_AL + (buf) * 5120;                                   \
    _Pragma("unroll")                                                         \
    for (int i = 0; i < 4; ++i) {                                             \
        int idx = tid + i * 256;                                              \
        int row = idx >> 3;                                                   \
        int c = (idx & 7) * 4;                                                \
        float vv[4] = {a_reg[i].x, a_reg[i].y, a_reg[i].z, a_reg[i].w};       \
        unsigned hp[2], lp[2];                                                \
        _Pragma("unroll")                                                     \
        for (int q = 0; q < 2; ++q) {                                         \
            __half h0, l0, h1, l1;                                            \
            split_f16(vv[2 * q], h0, l0);                                     \
            split_f16(vv[2 * q + 1], h1, l1);                                 \
            hp[q] = ((unsigned)__half_as_ushort(h1) << 16) |                  \
                    __half_as_ushort(h0);                                     \
            lp[q] = ((unsigned)__half_as_ushort(l1) << 16) |                  \
                    __half_as_ushort(l0);                                     \
        }                                                                     \
        *reinterpret_cast<uint2*>(&ah[row * LDA + c]) =                       \
            make_uint2(hp[0], hp[1]);                                         \
        *reinterpret_cast<uint2*>(&al[row * LDA + c]) =                       \
            make_uint2(lp[0], lp[1]);                                         \
    }                                                                         \
} while (0)

#define GEMM_CP_W(it, buf) do {                                               \
    const int k0 = (it) * 32;                                                 \
    __half* wh = sm + SM_WH + (buf) * 4352;                                   \
    _Pragma("unroll")                                                         \
    for (int i = 0; i < 2; ++i) {                                             \
        int idx = tid + i * 256;                                              \
        int row = idx >> 4;                                                   \
        int c8 = (idx & 15) * 8;                                              \
        size_t go = (size_t)(k0 + row) * HH + colBase + c8;                   \
        CP_ASYNC16(smem_u32(&wh[row * LDW + c8]), &Wh[go]);                   \
    }                                                                         \
    CP_COMMIT();                                                              \
} while (0)

#define GEMM_MAINLOOP()                                                       \
    GEMM_LOAD_A(0);                                                           \
    GEMM_CP_W(0, 0);                                                          \
    for (int it = 0; it < niter; ++it) {                                      \
        const int buf = it & 1;                                               \
        GEMM_STORE_A(buf);                                                    \
        if (it + 1 < niter) GEMM_LOAD_A(it + 1);                              \
        CP_WAIT0();                                                           \
        __syncthreads();                                                      \
        if (it + 1 < niter) GEMM_CP_W(it + 1, buf ^ 1);                       \
        const __half* ah = sm + SM_AH + buf * 5120;                           \
        const __half* al = sm + SM_AL + buf * 5120;                           \
        const __half* wh = sm + SM_WH + buf * 4352;                           \
        _Pragma("unroll")                                                     \
        for (int ks = 0; ks < 2; ++ks) {                                      \
            const int kb = ks * 16;                                           \
            unsigned afr[2][2][4];                                            \
            _Pragma("unroll")                                                 \
            for (int mt = 0; mt < 2; ++mt) {                                  \
                int row = warp_m * 32 + mt * 16 + a_row_off;                  \
                int col = kb + a_col_off;                                     \
                ldsm_x4(smem_u32(&ah[row * LDA + col]),                       \
                        afr[0][mt][0], afr[0][mt][1], afr[0][mt][2],          \
                        afr[0][mt][3]);                                       \
                ldsm_x4(smem_u32(&al[row * LDA + col]),                       \
                        afr[1][mt][0], afr[1][mt][1], afr[1][mt][2],          \
                        afr[1][mt][3]);                                       \
            }                                                                 \
            unsigned bfr[4][4];                                               \
            _Pragma("unroll")                                                 \
            for (int p = 0; p < 4; ++p) {                                     \
                int kk = kb + b_k_off;                                        \
                int nn = warp_n * 64 + p * 16 + b_n_off;                      \
                ldsm_x4t(smem_u32(&wh[kk * LDW + nn]),                        \
                         bfr[p][0], bfr[p][1], bfr[p][2], bfr[p][3]);         \
            }                                                                 \
            _Pragma("unroll")                                                 \
            for (int s = 0; s < 2; ++s)                                       \
                _Pragma("unroll")                                             \
                for (int mt = 0; mt < 2; ++mt)                                \
                    _Pragma("unroll")                                         \
                    for (int p = 0; p < 4; ++p) {                             \
                        mma_f16(acc[mt][2 * p],     afr[s][mt],               \
                                bfr[p][0], bfr[p][1]);                        \
                        mma_f16(acc[mt][2 * p + 1], afr[s][mt],               \
                                bfr[p][2], bfr[p][3]);                        \
                    }                                                         \
        }                                                                     \
    }

// ---- G1: plain or row/col-BN affine on A; bias+ReLU; store C ---------------
template <bool ROWBN>
__global__ void __launch_bounds__(256)
gemm_g1(const float* __restrict__ A,
        const __half* __restrict__ Wh,
        const float* __restrict__ bias, float* __restrict__ C, int K,
        const int* __restrict__ deg,
        const float* __restrict__ st,
        const float* __restrict__ gamma,
        const float* __restrict__ beta) {
    extern __shared__ __half sm[];
    __shared__ float s_asb[2 * HH];
    const int tid = threadIdx.x;
    const int lane = tid & 31;
    const int wid = tid >> 5;
    const int warp_m = wid & 3;
    const int warp_n = wid >> 2;
    const int rowBase = blockIdx.y * 128;
    const int colBase = blockIdx.x * 128;
    const bool ASB = ROWBN;

    float dp1r[4] = {1.f, 1.f, 1.f, 1.f};
    if (ROWBN) {
        float sv, bv;
        bn_sb(st, gamma, beta, tid, sv, bv);
        s_asb[tid] = sv;
        s_asb[HH + tid] = bv;
        #pragma unroll
        for (int i = 0; i < 4; ++i)
            dp1r[i] = 1.f + (float)deg[rowBase + ((tid + i * 256) >> 3)];
        __syncthreads();
    }
    const float* asb = s_asb;

    float acc[2][8][4] = {};
    float4 a_reg[4];

    const int lg = lane >> 3, lj = lane & 7;
    const int a_row_off = (lg & 1) * 8 + lj;
    const int a_col_off = (lg >> 1) * 8;
    const int b_k_off = (lg & 1) * 8 + lj;
    const int b_n_off = (lg >> 1) * 8;

    const int niter = K >> 5;
    GEMM_MAINLOOP();

    const int g = lane >> 2, tq = lane & 3;
    #pragma unroll
    for (int mt = 0; mt < 2; ++mt) {
        #pragma unroll
        for (int nt = 0; nt < 8; ++nt) {
            int row0 = rowBase + warp_m * 32 + mt * 16 + g;
            int col = colBase + warp_n * 64 + nt * 8 + 2 * tq;
            float b0 = bias[col], b1 = bias[col + 1];
            *reinterpret_cast<float2*>(&C[(size_t)row0 * HH + col]) =
                make_float2(fmaxf(acc[mt][nt][0] + b0, 0.f),
                            fmaxf(acc[mt][nt][1] + b1, 0.f));
            *reinterpret_cast<float2*>(&C[(size_t)(row0 + 8) * HH + col]) =
                make_float2(fmaxf(acc[mt][nt][2] + b0, 0.f),
                            fmaxf(acc[mt][nt][3] + b1, 0.f));
        }
    }
}

// ---- G2: bias+ReLU + BN stats; AGG ? (aggregate in smem, write raw-agg)
//                                 : (store z to C) ---------------------------
template <bool AGG>
__global__ void __launch_bounds__(256)
gemm_g2(const float* __restrict__ A,
        const __half* __restrict__ Wh,
        const float* __restrict__ bias, float* __restrict__ C,
        int K, float* __restrict__ stats) {
    extern __shared__ __half sm[];
    __shared__ float s_sum[128], s_sq[128];

    const int tid = threadIdx.x;
    const int lane = tid & 31;
    const int wid = tid >> 5;
    const int warp_m = wid & 3;
    const int warp_n = wid >> 2;
    const int rowBase = blockIdx.y * 128;
    const int colBase = blockIdx.x * 128;
    const bool ASB = false;
    const float* asb = nullptr;
    float dp1r[4] = {1.f, 1.f, 1.f, 1.f};
    (void)asb; (void)dp1r;

    if (tid < 128) { s_sum[tid] = 0.f; s_sq[tid] = 0.f; }

    float acc[2][8][4] = {};
    float4 a_reg[4];

    const int lg = lane >> 3, lj = lane & 7;
    const int a_row_off = (lg & 1) * 8 + lj;
    const int a_col_off = (lg >> 1) * 8;
    const int b_k_off = (lg & 1) * 8 + lj;
    const int b_n_off = (lg >> 1) * 8;

    const int niter = K >> 5;
    GEMM_MAINLOOP();
    __syncthreads();   // drain last-iter smem reads before epilogue reuse

    float* tile = reinterpret_cast<float*>(sm);

    const int g = lane >> 2, tq = lane & 3;
    float cs[16], cq[16];
    #pragma unroll
    for (int i = 0; i < 16; ++i) { cs[i] = 0.f; cq[i] = 0.f; }
    #pragma unroll
    for (int mt = 0; mt < 2; ++mt) {
        #pragma unroll
        for (int nt = 0; nt < 8; ++nt) {
            int lr = warp_m * 32 + mt * 16 + g;
            int lc = warp_n * 64 + nt * 8 + 2 * tq;
            float b0 = bias[colBase + lc], b1 = bias[colBase + lc + 1];
            float v[4] = {fmaxf(acc[mt][nt][0] + b0, 0.f),
                          fmaxf(acc[mt][nt][1] + b1, 0.f),
                          fmaxf(acc[mt][nt][2] + b0, 0.f),
                          fmaxf(acc[mt][nt][3] + b1, 0.f)};
            cs[nt * 2 + 0] += v[0] + v[2];
            cs[nt * 2 + 1] += v[1] + v[3];
            cq[nt * 2 + 0] += v[0] * v[0] + v[2] * v[2];
            cq[nt * 2 + 1] += v[1] * v[1] + v[3] * v[3];
            if (AGG) {
                *reinterpret_cast<float2*>(&tile[lr * TILE_LD + lc]) =
                    make_float2(v[0], v[1]);
                *reinterpret_cast<float2*>(&tile[(lr + 8) * TILE_LD + lc]) =
                    make_float2(v[2], v[3]);
            } else {
                *reinterpret_cast<float2*>(
                    &C[(size_t)(rowBase + lr) * HH + colBase + lc]) =
                    make_float2(v[0], v[1]);
                *reinterpret_cast<float2*>(
                    &C[(size_t)(rowBase + lr + 8) * HH + colBase + lc]) =
                    make_float2(v[2], v[3]);
            }
        }
    }
    #pragma unroll
    for (int i = 0; i < 16; ++i) {
        #pragma unroll
        for (int off = 16; off >= 4; off >>= 1) {
            cs[i] += __shfl_down_sync(0xffffffffu, cs[i], off);
            cq[i] += __shfl_down_sync(0xffffffffu, cq[i], off);
        }
    }
    if (lane < 4) {
        #pragma unroll
        for (int nt = 0; nt < 8; ++nt) {
            #pragma unroll
            for (int c = 0; c < 2; ++c) {
                int lc = warp_n * 64 + nt * 8 + 2 * lane + c;
                atomicAdd(&s_sum[lc], cs[nt * 2 + c]);
                atomicAdd(&s_sq[lc], cq[nt * 2 + c]);
            }
        }
    }
    __syncthreads();
    {
        int c = tid & 127;
        if (tid < 128) atomicAdd(&stats[colBase + c], s_sum[c]);
        else           atomicAdd(&stats[HH + colBase + c], s_sq[c]);
    }
    if (AGG) {
        const int gph = blockIdx.y;
        const int c0 = lane * 4;
        #pragma unroll
        for (int rr = 0; rr < 16; ++rr) {
            int r = wid * 16 + rr;
            int node = gph * NPG + r;
            int st_ = d_rowstart[node];
            int dgn = d_deg[node];
            float4 a4 = *reinterpret_cast<float4*>(&tile[r * TILE_LD + c0]);
            for (int e = 0; e < dgn; ++e) {
                int sl = __ldg(&d_csr[st_ + e]) - gph * NPG;
                float4 b4 = *reinterpret_cast<float4*>(&tile[sl * TILE_LD + c0]);
                a4.x += b4.x; a4.y += b4.y; a4.z += b4.z; a4.w += b4.w;
            }
            *reinterpret_cast<float4*>(&C[(size_t)node * HH + colBase + c0]) = a4;
        }
    }
}

// ------- c1 GEMM: inline bn2 affine on A, tanh, fused c2 proj -> logits -----
__global__ void __launch_bounds__(256)
gemm_c1(const float* __restrict__ A,
        const __half* __restrict__ Wh,
        const float* __restrict__ bias,
        int K,
        const float* __restrict__ st2,
        const float* __restrict__ gamma2,
        const float* __restrict__ beta2,
        const float* __restrict__ c2w, float* __restrict__ alog) {
    extern __shared__ __half sm[];
    __shared__ float s_asb[2 * HH];
    const int tid = threadIdx.x;
    const int lane = tid & 31;
    const int wid = tid >> 5;
    const int warp_m = wid & 3;
    const int warp_n = wid >> 2;
    const int rowBase = blockIdx.y * 128;
    const int colBase = blockIdx.x * 128;
    const bool ASB = true;
    float dp1r[4] = {1.f, 1.f, 1.f, 1.f};

    {
        float sv, bv;
        bn_sb(st2, gamma2, beta2, tid, sv, bv);
        s_asb[tid] = sv;
        s_asb[HH + tid] = bv;
    }
    __syncthreads();
    const float* asb = s_asb;

    float acc[2][8][4] = {};
    float4 a_reg[4];

    const int lg = lane >> 3, lj = lane & 7;
    const int a_row_off = (lg & 1) * 8 + lj;
    const int a_col_off = (lg >> 1) * 8;
    const int b_k_off = (lg & 1) * 8 + lj;
    const int b_n_off = (lg >> 1) * 8;

    const int niter = K >> 5;
    GEMM_MAINLOOP();

    const int g = lane >> 2, tq = lane & 3;
    float p[2][2][2] = {};
    #pragma unroll
    for (int mt = 0; mt < 2; ++mt) {
        #pragma unroll
        for (int nt = 0; nt < 8; ++nt) {
            int col = colBase + warp_n * 64 + nt * 8 + 2 * tq;
            float b0 = bias[col], b1 = bias[col + 1];
            float v0 = tanhf(acc[mt][nt][0] + b0);
            float v1 = tanhf(acc[mt][nt][1] + b1);
            float v2 = tanhf(acc[mt][nt][2] + b0);
            float v3 = tanhf(acc[mt][nt][3] + b1);
            float w00 = __ldg(&c2w[col * 2 + 0]);
            float w01 = __ldg(&c2w[col * 2 + 1]);
            float w10 = __ldg(&c2w[col * 2 + 2]);
            float w11 = __ldg(&c2w[col * 2 + 3]);
            p[mt][0][0] += v0 * w00 + v1 * w10;
            p[mt][0][1] += v0 * w01 + v1 * w11;
            p[mt][1][0] += v2 * w00 + v3 * w10;
            p[mt][1][1] += v2 * w01 + v3 * w11;
        }
    }
    #pragma unroll
    for (int mt = 0; mt < 2; ++mt)
        #pragma unroll
        for (int hh = 0; hh < 2; ++hh)
            #pragma unroll
            for (int c = 0; c < 2; ++c) {
                float v = p[mt][hh][c];
                v += __shfl_xor_sync(0xffffffffu, v, 1);
                v += __shfl_xor_sync(0xffffffffu, v, 2);
                p[mt][hh][c] = v;
            }
    if (tq == 0) {
        #pragma unroll
        for (int mt = 0; mt < 2; ++mt)
            #pragma unroll
            for (int hh = 0; hh < 2; ++hh) {
                int row = rowBase + warp_m * 32 + mt * 16 + g + hh * 8;
                atomicAdd(&alog[row * 2 + 0], p[mt][hh][0]);
                atomicAdd(&alog[row * 2 + 1], p[mt][hh][1]);
            }
    }
}

// -------- fused softmax + pooling + head + adjacency penalty (per graph) ----
__global__ void pool_head_adj_kernel(const float* __restrict__ Z,
                                     const float* __restrict__ alog,
                                     const float* __restrict__ c2b,
                                     const float* __restrict__ st2,
                                     const float* __restrict__ gamma2,
                                     const float* __restrict__ beta2,
                                     const float* __restrict__ l1w,
                                     const float* __restrict__ l1b,
                                     const float* __restrict__ l2w,
                                     const float* __restrict__ l2b,
                                     const int* __restrict__ src,
                                     const int* __restrict__ dst,
                                     float* __restrict__ sub_out,
                                     float* __restrict__ graph_out,
                                     float* __restrict__ logits_out,
                                     float* __restrict__ out_pen) {
    __shared__ float sa0[NPG], sa1[NPG];
    __shared__ float ssub[HH];
    __shared__ float red0[HH], red1[HH];
    __shared__ float adjred[4][HH];
    const int g = blockIdx.x, t = threadIdx.x;   // 256 threads
    // softmax for this graph's 128 nodes (from fused logits)
    if (t < NPG) {
        int node = g * NPG + t;
        float s0 = alog[2 * node + 0] + c2b[0];
        float s1 = alog[2 * node + 1] + c2b[1];
        float m = fmaxf(s0, s1);
        float e0 = expf(s0 - m), e1 = expf(s1 - m);
        float inv = 1.f / (e0 + e1);
        sa0[t] = e0 * inv;
        sa1[t] = e1 * inv;
    }
    float sf, bf;
    bn_sb(st2, gamma2, beta2, t, sf, bf);
    __syncthreads();
    // pooling (applies layer-2 BN affine on the fly)
    float sh = 0.f, ss = 0.f;
    const size_t base = (size_t)g * NPG * HH;
    for (int r = 0; r < NPG; ++r) {
        float hv = sf * Z[base + r * HH + t] + bf;
        sh += hv;
        ss += sa0[r] * hv;
    }
    sub_out[g * HH + t] = ss;
    graph_out[g * HH + t] = sh * (1.f / NPG);
    ssub[t] = ss;
    // adjacency partial sums (2 edges per thread)
    float m00 = 0.f, m01 = 0.f, m10 = 0.f, m11 = 0.f;
    #pragma unroll
    for (int i = 0; i < 2; ++i) {
        int e = g * EPG + t + i * 256;
        int sl = src[e] - g * NPG;
        int dl = dst[e] - g * NPG;
        float a0 = sa0[sl], a1 = sa1[sl];
        float b0 = sa0[dl], b1 = sa1[dl];
        m00 += a0 * b0; m01 += a0 * b1;
        m10 += a1 * b0; m11 += a1 * b1;
    }
    adjred[0][t] = m00; adjred[1][t] = m01;
    adjred[2][t] = m10; adjred[3][t] = m11;
    __syncthreads();
    // head matvec
    float acc = l1b[t];
    #pragma unroll 8
    for (int k = 0; k < HH; ++k) acc += ssub[k] * l1w[k * HH + t];
    float zc = fmaxf(acc, 0.f);
    red0[t] = zc * l2w[t * 2 + 0];
    red1[t] = zc * l2w[t * 2 + 1];
    __syncthreads();
    // joint tree reduction (head logits + adjacency 2x2)
    for (int s = 128; s > 0; s >>= 1) {
        if (t < s) {
            red0[t] += red0[t + s]; red1[t] += red1[t + s];
            adjred[0][t] += adjred[0][t + s];
            adjred[1][t] += adjred[1][t + s];
            adjred[2][t] += adjred[2][t + s];
            adjred[3][t] += adjred[3][t + s];
        }
        __syncthreads();
    }
    if (t == 0) {
        float s0 = red0[0] + l2b[0], s1 = red1[0] + l2b[1];
        float m = fmaxf(s0, s1);
        float lse = m + logf(expf(s0 - m) + expf(s1 - m));
        logits_out[g * 2 + 0] = s0 - lse;
        logits_out[g * 2 + 1] = s1 - lse;
        float r0 = fmaxf(fabsf(adjred[0][0]) + fabsf(adjred[1][0]), 1e-12f);
        float r1 = fmaxf(fabsf(adjred[2][0]) + fabsf(adjred[3][0]), 1e-12f);
        float e0 = adjred[0][0] / r0 - 1.f;
        float e1 = adjred[3][0] / r1 - 1.f;
        atomicAdd(out_pen, 0.5f * (e0 * e0 + e1 * e1) * (1.f / BB));
    }
}

// ---------------- launch ------------------------------------------------------
extern "C" void kernel_launch(void* const* d_in, const int* in_sizes, int n_in,
                              void* d_out, int out_size) {
    const float* x    = (const float*)d_in[0];
    const int*   ei   = (const int*)d_in[1];
    const int*   src  = ei;
    const int*   dst  = ei + EE;
    const float* w0_1 = (const float*)d_in[3];
    const float* b0_1 = (const float*)d_in[4];
    const float* w0_2 = (const float*)d_in[5];
    const float* b0_2 = (const float*)d_in[6];
    const float* g0   = (const float*)d_in[7];
    const float* be0  = (const float*)d_in[8];
    const float* wl1  = (const float*)d_in[9];
    const float* bl1  = (const float*)d_in[10];
    const float* wl2  = (const float*)d_in[11];
    const float* bl2  = (const float*)d_in[12];
    const float* gl   = (const float*)d_in[13];
    const float* bel  = (const float*)d_in[14];
    const float* c1w  = (const float*)d_in[15];
    const float* c1b  = (const float*)d_in[16];
    const float* c2w  = (const float*)d_in[17];
    const float* c2b  = (const float*)d_in[18];
    const float* l1w  = (const float*)d_in[19];
    const float* l1b  = (const float*)d_in[20];
    const float* l2w  = (const float*)d_in[21];
    const float* l2b  = (const float*)d_in[22];

    float* out        = (float*)d_out;
    float* out_logits = out;
    float* out_sub    = out + BB * 2;
    float* out_graph  = out + BB * 2 + BB * HH;
    float* out_pen    = out + BB * 2 + 2 * BB * HH;

    float *zb, *tb, *hb, *alog, *stats;
    cudaGetSymbolAddress((void**)&zb, d_z);
    cudaGetSymbolAddress((void**)&tb, d_t);
    cudaGetSymbolAddress((void**)&hb, d_h);
    cudaGetSymbolAddress((void**)&alog, d_alog);
    cudaGetSymbolAddress((void**)&stats, d_stats);
    int* degp;
    cudaGetSymbolAddress((void**)&degp, d_deg);
    __half* wfh;
    cudaGetSymbolAddress((void**)&wfh, d_wfh);

    cudaFuncSetAttribute(gemm_g1<false>,
                         cudaFuncAttributeMaxDynamicSharedMemorySize, GEMM_SMEM_BYTES);
    cudaFuncSetAttribute(gemm_g1<true>,
                         cudaFuncAttributeMaxDynamicSharedMemorySize, GEMM_SMEM_BYTES);
    cudaFuncSetAttribute(gemm_g2<false>,
                         cudaFuncAttributeMaxDynamicSharedMemorySize, GEMM_SMEM_BYTES);
    cudaFuncSetAttribute(gemm_g2<true>,
                         cudaFuncAttributeMaxDynamicSharedMemorySize, GEMM_SMEM_BYTES);
    cudaFuncSetAttribute(gemm_c1,
                         cudaFuncAttributeMaxDynamicSharedMemorySize, GEMM_SMEM_BYTES);

    const int O_W01 = 0;
    const int O_W02 = 32768;
    const int O_L1A = 98304;
    const int O_L2A = 163840;
    const int O_L1B = 229376;
    const int O_L2B = 294912;
    const int O_C1  = 360448;

    const dim3 gemm_grid(HH / 128, NN / 128);

    wsplit_all_kernel<<<(WSPLIT_TOTAL + 255) / 256, 256>>>(
        w0_1, w0_2, wl1, wl2, c1w, wfh, out_pen);                         // 0
    csr_kernel<<<BB, NPG>>>(src, dst);                                    // 1
    agg_gather_x<<<NN / 8, 256>>>(x, hb);                                 // 2
    // ---- layer 0 ----
    gemm_g1<false><<<gemm_grid, 256, GEMM_SMEM_BYTES>>>(                  // 3 (profiled)
        hb, wfh + O_W01, b0_1, tb, FIN, nullptr, nullptr, nullptr, nullptr);
    gemm_g2<true><<<gemm_grid, 256, GEMM_SMEM_BYTES>>>(                   // 4
        tb, wfh + O_W02, b0_2, hb, HH, stats);
    // ---- layer 1 ----
    gemm_g1<true><<<gemm_grid, 256, GEMM_SMEM_BYTES>>>(
        hb, wfh + O_L1A, bl1, tb, HH, degp, stats, g0, be0);
    gemm_g2<true><<<gemm_grid, 256, GEMM_SMEM_BYTES>>>(
        tb, wfh + O_L2A, bl2, hb, HH, stats + 2 * HH);
    // ---- layer 2 ----
    gemm_g1<true><<<gemm_grid, 256, GEMM_SMEM_BYTES>>>(
        hb, wfh + O_L1B, bl1 + HH, tb, HH, degp, stats + 2 * HH, gl, bel);
    gemm_g2<false><<<gemm_grid, 256, GEMM_SMEM_BYTES>>>(
        tb, wfh + O_L2B, bl2 + HH, zb, HH, stats + 4 * HH);

    // ---- assignment: c1 GEMM (inline BN2 affine) + fused c2 proj ----
    gemm_c1<<<gemm_grid, 256, GEMM_SMEM_BYTES>>>(
        zb, wfh + O_C1, c1b, HH, stats + 4 * HH, gl + HH, bel + HH, c2w, alog);

    // ---- fused softmax + pooling + head + adjacency penalty ----
    pool_head_adj_kernel<<<BB, 256>>>(zb, alog, c2b,
                                      stats + 4 * HH, gl + HH, bel + HH,
                                      l1w, l1b, l2w, l2b, src, dst,
                                      out_sub, out_graph, out_logits, out_pen);
}